// round 4
// baseline (speedup 1.0000x reference)
#include <cuda_runtime.h>
#include <cstdint>

#define BB 2
#define NN 384
#define DD 768
#define EE 64
#define HH 512

// -------- scratch (no allocations allowed) --------
__device__ float g_agg[BB * NN * EE];     //  192 KB
__device__ float g_NI [BB * NN * HH];     // 1.5 MB  (nodes@Wi + eb1)
__device__ float g_NJ [BB * NN * HH];     // 1.5 MB  (nodes@Wj)

__device__ __forceinline__ uint32_t f32_to_tf32(float f) {
    uint32_t r;
    asm("cvt.rna.tf32.f32 %0, %1;" : "=r"(r) : "f"(f));
    return r;
}
__device__ __forceinline__ void mma_tf32(float c[4],
                                         uint32_t a0, uint32_t a1, uint32_t a2, uint32_t a3,
                                         uint32_t b0, uint32_t b1) {
    asm volatile("mma.sync.aligned.m16n8k8.row.col.f32.tf32.tf32.f32 "
        "{%0,%1,%2,%3}, {%4,%5,%6,%7}, {%8,%9}, {%0,%1,%2,%3};"
        : "+f"(c[0]), "+f"(c[1]), "+f"(c[2]), "+f"(c[3])
        : "r"(a0), "r"(a1), "r"(a2), "r"(a3), "r"(b0), "r"(b1));
}

// ============================================================
// Kernel 1: agg[b,i,e] = sum_j edges[b,i,j,e] * adj[b,i,j]
// ============================================================
__global__ __launch_bounds__(256) void k_agg(const float* __restrict__ edges,
                                             const float* __restrict__ adj)
{
    int bi = blockIdx.x;
    int e  = threadIdx.x & 63;
    int jg = threadIdx.x >> 6;
    const float* erow = edges + (size_t)bi * NN * EE;
    const float* arow = adj   + (size_t)bi * NN;
    float acc = 0.f;
    for (int j = jg; j < NN; j += 4) {
        float a = arow[j];
        if (a != 0.f) acc += erow[(size_t)j * EE + e] * a;
    }
    __shared__ float red[4][64];
    red[jg][e] = acc;
    __syncthreads();
    if (jg == 0)
        g_agg[(size_t)bi * EE + e] = red[0][e] + red[1][e] + red[2][e] + red[3][e];
}

// ============================================================
// Kernel 2: NI = nodes @ Wi + eb1 ; NJ = nodes @ Wj  (exact fp32)
// ============================================================
__global__ __launch_bounds__(256) void k_ninj(const float* __restrict__ nodes,
                                              const float* __restrict__ ew1,
                                              const float* __restrict__ eb1)
{
    __shared__ float sA[16 * DD];
    const int tid   = threadIdx.x;
    const int cbase = blockIdx.x * 256;
    const int r0    = blockIdx.y * 16;
    const int z     = blockIdx.z;
    const int rg    = tid >> 6;
    const int cc    = tid & 63;

    #pragma unroll
    for (int t = 0; t < 48; t++) {
        int lin = t * 256 + tid;
        sA[lin] = nodes[(size_t)r0 * DD + lin];
    }
    __syncthreads();

    const int woff = EE + z * DD;
    float acc[4][4];
    #pragma unroll
    for (int q = 0; q < 4; q++)
        #pragma unroll
        for (int x = 0; x < 4; x++) acc[q][x] = 0.f;

    #pragma unroll 4
    for (int k = 0; k < DD; k++) {
        float4 w = __ldg((const float4*)&ew1[(size_t)(woff + k) * HH + cbase + cc * 4]);
        #pragma unroll
        for (int q = 0; q < 4; q++) {
            float a = sA[(rg * 4 + q) * DD + k];
            acc[q][0] += a * w.x; acc[q][1] += a * w.y;
            acc[q][2] += a * w.z; acc[q][3] += a * w.w;
        }
    }

    float* dst = (z == 0) ? g_NI : g_NJ;
    float4 bb = make_float4(0.f, 0.f, 0.f, 0.f);
    if (z == 0) bb = __ldg((const float4*)&eb1[cbase + cc * 4]);
    #pragma unroll
    for (int q = 0; q < 4; q++) {
        int g = r0 + rg * 4 + q;
        float4 o = make_float4(acc[q][0] + bb.x, acc[q][1] + bb.y,
                               acc[q][2] + bb.z, acc[q][3] + bb.w);
        *(float4*)&dst[(size_t)g * HH + cbase + cc * 4] = o;
    }
}

// ============================================================
// Kernel 3: node path (exact fp32)
// ============================================================
#define MK (EE + DD)
__global__ __launch_bounds__(256) void k_node(const float* __restrict__ nodes,
                                              const float* __restrict__ nw1,
                                              const float* __restrict__ nb1,
                                              const float* __restrict__ ng,
                                              const float* __restrict__ nbt,
                                              const float* __restrict__ nw2,
                                              const float* __restrict__ nb2,
                                              float* __restrict__ out_nodes)
{
    __shared__ float sM[8 * MK];
    __shared__ float sH[8 * 516];
    const int tid = threadIdx.x;
    const int r0  = blockIdx.x * 8;

    for (int t = 0; t < 26; t++) {
        int lin = t * 256 + tid;
        int r = lin / MK, c = lin - r * MK;
        int g = r0 + r;
        float v = (c < EE) ? g_agg[(size_t)g * EE + c]
                           : nodes[(size_t)g * DD + (c - EE)] * (float)NN;
        sM[lin] = v;
    }
    __syncthreads();

    const int rg = tid >> 7;
    const int hc = tid & 127;
    float acc[4][4];
    #pragma unroll
    for (int q = 0; q < 4; q++)
        #pragma unroll
        for (int x = 0; x < 4; x++) acc[q][x] = 0.f;

    #pragma unroll 4
    for (int k = 0; k < MK; k++) {
        float4 w = __ldg((const float4*)&nw1[(size_t)k * HH + hc * 4]);
        #pragma unroll
        for (int q = 0; q < 4; q++) {
            float a = sM[(rg * 4 + q) * MK + k];
            acc[q][0] += a * w.x; acc[q][1] += a * w.y;
            acc[q][2] += a * w.z; acc[q][3] += a * w.w;
        }
    }
    {
        float4 b4 = __ldg((const float4*)&nb1[hc * 4]);
        #pragma unroll
        for (int q = 0; q < 4; q++) {
            float* d = &sH[(rg * 4 + q) * 516 + hc * 4];
            *(float4*)d = make_float4(acc[q][0] + b4.x, acc[q][1] + b4.y,
                                      acc[q][2] + b4.z, acc[q][3] + b4.w);
        }
    }
    __syncthreads();

    {
        int wid = tid >> 5, lane = tid & 31;
        float s = 0.f, ss = 0.f;
        #pragma unroll
        for (int m = 0; m < 16; m++) {
            float v = sH[wid * 516 + lane + m * 32];
            s += v; ss += v * v;
        }
        #pragma unroll
        for (int m = 16; m >= 1; m >>= 1) {
            s  += __shfl_xor_sync(0xffffffffu, s, m);
            ss += __shfl_xor_sync(0xffffffffu, ss, m);
        }
        float mu = s * (1.f / HH);
        float var = ss * (1.f / HH) - mu * mu;
        float rs = rsqrtf(var + 1e-5f);
        #pragma unroll
        for (int m = 0; m < 16; m++) {
            int h = lane + m * 32;
            float v = sH[wid * 516 + h];
            v = (v - mu) * rs * __ldg(&ng[h]) + __ldg(&nbt[h]);
            sH[wid * 516 + h] = fmaxf(v, 0.f);
        }
    }
    __syncthreads();

    float acc2[8][3];
    #pragma unroll
    for (int r = 0; r < 8; r++)
        #pragma unroll
        for (int k = 0; k < 3; k++) acc2[r][k] = 0.f;

    #pragma unroll 2
    for (int h = 0; h < HH; h++) {
        float w0 = __ldg(&nw2[(size_t)h * DD + tid]);
        float w1 = __ldg(&nw2[(size_t)h * DD + tid + 256]);
        float w2 = __ldg(&nw2[(size_t)h * DD + tid + 512]);
        #pragma unroll
        for (int r = 0; r < 8; r++) {
            float a = sH[r * 516 + h];
            acc2[r][0] += a * w0; acc2[r][1] += a * w1; acc2[r][2] += a * w2;
        }
    }
    #pragma unroll
    for (int r = 0; r < 8; r++) {
        int g = r0 + r;
        #pragma unroll
        for (int k = 0; k < 3; k++) {
            int d = tid + k * 256;
            out_nodes[(size_t)g * DD + d] =
                __ldg(&nodes[(size_t)g * DD + d]) + acc2[r][k] + __ldg(&nb2[d]);
        }
    }
}

// ============================================================
// Kernel 4: fused edge path with mma.sync tf32.
// CTA = one (b,i) x 64-j tile.
// smem: sE[64][68] tf32 | sW[128][68] / [64][132] tf32 | sHe[64][516] f32
// ============================================================
#define OFF_E   0
#define OFF_W   4352
#define OFF_HE  13056
#define OFF_SUM 46080
#define OFF_SQ  46144
#define OFF_MU  46208
#define OFF_RS  46272
#define EDGE_SMEM_F 46336
#define EDGE_SMEM_BYTES (EDGE_SMEM_F * 4)

__global__ __launch_bounds__(256, 1) void k_edge_mma(
    const float* __restrict__ edges,
    const float* __restrict__ ew1,   // We = first 64 rows
    const float* __restrict__ eg,
    const float* __restrict__ ebt,
    const float* __restrict__ ew2,
    const float* __restrict__ eb2,
    float* __restrict__ out_edges)
{
    extern __shared__ float smem[];
    uint32_t* su = (uint32_t*)smem;
    const int tid = threadIdx.x;
    const int w = tid >> 5, lane = tid & 31;
    const int g = lane >> 2, tig = lane & 3;
    const int b = blockIdx.z, i = blockIdx.y, jt = blockIdx.x;
    const int j0 = jt * 64;

    // ---- stage edge tile A [64 j][68 k-stride], tf32 ----
    const float* etile = edges + ((size_t)((size_t)b * NN + i) * NN + j0) * EE;
    #pragma unroll
    for (int t = 0; t < 4; t++) {
        int q = t * 256 + tid;           // 1024 quads
        int j = q >> 4, k0 = (q & 15) * 4;
        float4 v = __ldg((const float4*)&etile[j * EE + k0]);
        *(uint4*)&su[OFF_E + j * 68 + k0] =
            make_uint4(f32_to_tf32(v.x), f32_to_tf32(v.y),
                       f32_to_tf32(v.z), f32_to_tf32(v.w));
    }
    if (tid < 64) { smem[OFF_SUM + tid] = 0.f; smem[OFF_SQ + tid] = 0.f; }

    const float* nip = g_NI + (size_t)((size_t)b * NN + i) * HH;
    const float* njb = g_NJ + (size_t)((size_t)b * NN + j0) * HH;

    // ---------------- GEMM1: he = A @ We, 4 n-chunks of 128 ----------------
    const int mt1 = (w & 1) * 32;        // warp m-tile (of 64)
    const int nt1 = (w >> 1) * 32;       // warp n-tile (of 128 chunk)
    float rsum[4] = {0.f, 0.f, 0.f, 0.f}, rsq[4] = {0.f, 0.f, 0.f, 0.f};

    for (int ch = 0; ch < 4; ch++) {
        __syncthreads();                 // sW free / A+zero visible
        // stage We chunk -> sW[n 128][68 k], tf32
        #pragma unroll
        for (int t = 0; t < 8; t++) {
            int q = t * 256 + tid;       // 2048 quads
            int n = q >> 4, k0 = (q & 15) * 4;
            int ngl = ch * 128 + n;
            uint4 o;
            o.x = f32_to_tf32(__ldg(&ew1[(size_t)(k0 + 0) * HH + ngl]));
            o.y = f32_to_tf32(__ldg(&ew1[(size_t)(k0 + 1) * HH + ngl]));
            o.z = f32_to_tf32(__ldg(&ew1[(size_t)(k0 + 2) * HH + ngl]));
            o.w = f32_to_tf32(__ldg(&ew1[(size_t)(k0 + 3) * HH + ngl]));
            *(uint4*)&su[OFF_W + n * 68 + k0] = o;
        }
        __syncthreads();

        float c[2][4][4];
        #pragma unroll
        for (int mi = 0; mi < 2; mi++)
            #pragma unroll
            for (int ni = 0; ni < 4; ni++)
                #pragma unroll
                for (int x = 0; x < 4; x++) c[mi][ni][x] = 0.f;

        #pragma unroll
        for (int kk = 0; kk < 8; kk++) {
            int k0 = kk * 8;
            uint32_t a[2][4];
            #pragma unroll
            for (int mi = 0; mi < 2; mi++) {
                int r0 = (mt1 + mi * 16 + g) * 68;
                int r1 = r0 + 8 * 68;
                a[mi][0] = su[OFF_E + r0 + k0 + tig];
                a[mi][1] = su[OFF_E + r1 + k0 + tig];
                a[mi][2] = su[OFF_E + r0 + k0 + tig + 4];
                a[mi][3] = su[OFF_E + r1 + k0 + tig + 4];
            }
            #pragma unroll
            for (int ni = 0; ni < 4; ni++) {
                int n = (nt1 + ni * 8 + g) * 68;
                uint32_t b0 = su[OFF_W + n + k0 + tig];
                uint32_t b1 = su[OFF_W + n + k0 + tig + 4];
                mma_tf32(c[0][ni], a[0][0], a[0][1], a[0][2], a[0][3], b0, b1);
                mma_tf32(c[1][ni], a[1][0], a[1][1], a[1][2], a[1][3], b0, b1);
            }
        }

        // epilogue: += NI + NJ, write sHe, accumulate stats
        float2 niv[4];
        #pragma unroll
        for (int ni = 0; ni < 4; ni++)
            niv[ni] = __ldg((const float2*)&nip[ch * 128 + nt1 + ni * 8 + 2 * tig]);
        #pragma unroll
        for (int mi = 0; mi < 2; mi++) {
            #pragma unroll
            for (int rr = 0; rr < 2; rr++) {
                int row = mt1 + mi * 16 + g + rr * 8;
                const float* njp = njb + (size_t)row * HH;
                float s = 0.f, q2 = 0.f;
                #pragma unroll
                for (int ni = 0; ni < 4; ni++) {
                    int col = ch * 128 + nt1 + ni * 8 + 2 * tig;
                    float2 nj = __ldg((const float2*)&njp[col]);
                    float v0 = c[mi][ni][rr * 2 + 0] + niv[ni].x + nj.x;
                    float v1 = c[mi][ni][rr * 2 + 1] + niv[ni].y + nj.y;
                    s  += v0 + v1;
                    q2 += v0 * v0 + v1 * v1;
                    *(float2*)&smem[OFF_HE + row * 516 + col] = make_float2(v0, v1);
                }
                rsum[mi * 2 + rr] += s;
                rsq[mi * 2 + rr]  += q2;
            }
        }
    }

    // ---- LN stats reduction ----
    #pragma unroll
    for (int x = 0; x < 4; x++) {
        float s = rsum[x], q2 = rsq[x];
        s  += __shfl_xor_sync(0xffffffffu, s, 1);
        s  += __shfl_xor_sync(0xffffffffu, s, 2);
        q2 += __shfl_xor_sync(0xffffffffu, q2, 1);
        q2 += __shfl_xor_sync(0xffffffffu, q2, 2);
        if (tig == 0) {
            int row = mt1 + (x >> 1) * 16 + g + (x & 1) * 8;
            atomicAdd(&smem[OFF_SUM + row], s);
            atomicAdd(&smem[OFF_SQ + row], q2);
        }
    }
    __syncthreads();
    if (tid < 64) {
        float mu = smem[OFF_SUM + tid] * (1.f / HH);
        float var = smem[OFF_SQ + tid] * (1.f / HH) - mu * mu;
        smem[OFF_MU + tid] = mu;
        smem[OFF_RS + tid] = rsqrtf(var + 1e-5f);
    }
    __syncthreads();

    // ---- LN + relu + round-to-tf32 (in place) ----
    #pragma unroll
    for (int t = 0; t < 32; t++) {
        int lin = t * 256 + tid;         // 8192 quads over [64][512]
        int r = lin >> 7, c4 = (lin & 127) * 4;
        float4 v = *(float4*)&smem[OFF_HE + r * 516 + c4];
        float mu = smem[OFF_MU + r], rs = smem[OFF_RS + r];
        float4 g4 = __ldg((const float4*)&eg[c4]);
        float4 b4 = __ldg((const float4*)&ebt[c4]);
        uint4 o;
        o.x = f32_to_tf32(fmaxf((v.x - mu) * rs * g4.x + b4.x, 0.f));
        o.y = f32_to_tf32(fmaxf((v.y - mu) * rs * g4.y + b4.y, 0.f));
        o.z = f32_to_tf32(fmaxf((v.z - mu) * rs * g4.z + b4.z, 0.f));
        o.w = f32_to_tf32(fmaxf((v.w - mu) * rs * g4.w + b4.w, 0.f));
        *(uint4*)&su[OFF_HE + r * 516 + c4] = o;
    }

    // ---------------- GEMM2: out = relu_he @ ew2, 4 k-chunks of 128 ----------------
    const int mt2 = (w & 3) * 16;
    const int nt2 = (w >> 2) * 32;
    float c2[4][4];
    #pragma unroll
    for (int ni = 0; ni < 4; ni++)
        #pragma unroll
        for (int x = 0; x < 4; x++) c2[ni][x] = 0.f;

    for (int kc = 0; kc < 4; kc++) {
        __syncthreads();                 // sW free (prev chunk consumed)
        // stage ew2 chunk -> sW2[n 64][132 k], tf32
        #pragma unroll
        for (int t = 0; t < 8; t++) {
            int q = t * 256 + tid;       // 2048 quads
            int n = q >> 5, k0 = (q & 31) * 4;
            uint4 o;
            o.x = f32_to_tf32(__ldg(&ew2[(size_t)(kc * 128 + k0 + 0) * EE + n]));
            o.y = f32_to_tf32(__ldg(&ew2[(size_t)(kc * 128 + k0 + 1) * EE + n]));
            o.z = f32_to_tf32(__ldg(&ew2[(size_t)(kc * 128 + k0 + 2) * EE + n]));
            o.w = f32_to_tf32(__ldg(&ew2[(size_t)(kc * 128 + k0 + 3) * EE + n]));
            *(uint4*)&su[OFF_W + n * 132 + k0] = o;
        }
        __syncthreads();

        #pragma unroll
        for (int kk = 0; kk < 16; kk++) {
            int k0 = kk * 8;
            int r0 = (mt2 + g) * 516 + kc * 128;
            int r1 = r0 + 8 * 516;
            uint32_t a0 = su[OFF_HE + r0 + k0 + tig];
            uint32_t a1 = su[OFF_HE + r1 + k0 + tig];
            uint32_t a2 = su[OFF_HE + r0 + k0 + tig + 4];
            uint32_t a3 = su[OFF_HE + r1 + k0 + tig + 4];
            #pragma unroll
            for (int ni = 0; ni < 4; ni++) {
                int n = (nt2 + ni * 8 + g) * 132;
                uint32_t b0 = su[OFF_W + n + k0 + tig];
                uint32_t b1 = su[OFF_W + n + k0 + tig + 4];
                mma_tf32(c2[ni], a0, a1, a2, a3, b0, b1);
            }
        }
    }

    // ---- residual (fresh fp32 edges) + eb2 + store ----
    float2 bv[4];
    #pragma unroll
    for (int ni = 0; ni < 4; ni++)
        bv[ni] = __ldg((const float2*)&eb2[nt2 + ni * 8 + 2 * tig]);
    #pragma unroll
    for (int rr = 0; rr < 2; rr++) {
        int row = mt2 + g + rr * 8;
        size_t obase = ((size_t)((size_t)b * NN + i) * NN + (j0 + row)) * EE;
        #pragma unroll
        for (int ni = 0; ni < 4; ni++) {
            int col = nt2 + ni * 8 + 2 * tig;
            float2 e2 = __ldg((const float2*)&edges[obase + col]);
            float2 o = make_float2(e2.x + c2[ni][rr * 2 + 0] + bv[ni].x,
                                   e2.y + c2[ni][rr * 2 + 1] + bv[ni].y);
            *(float2*)&out_edges[obase + col] = o;
        }
    }
}

// ============================================================
extern "C" void kernel_launch(void* const* d_in, const int* in_sizes, int n_in,
                              void* d_out, int out_size)
{
    const float* nodes = (const float*)d_in[0];
    const float* edges = (const float*)d_in[1];
    const float* adj   = (const float*)d_in[2];
    const float* nw1   = (const float*)d_in[3];
    const float* nb1   = (const float*)d_in[4];
    const float* ng    = (const float*)d_in[5];
    const float* nbt   = (const float*)d_in[6];
    const float* nw2   = (const float*)d_in[7];
    const float* nb2   = (const float*)d_in[8];
    const float* ew1   = (const float*)d_in[9];
    const float* eb1   = (const float*)d_in[10];
    const float* eg    = (const float*)d_in[11];
    const float* ebt   = (const float*)d_in[12];
    const float* ew2   = (const float*)d_in[13];
    const float* eb2   = (const float*)d_in[14];

    float* out_nodes = (float*)d_out;
    float* out_edges = out_nodes + (size_t)BB * NN * DD;

    cudaFuncSetAttribute(k_edge_mma, cudaFuncAttributeMaxDynamicSharedMemorySize,
                         EDGE_SMEM_BYTES);

    k_agg <<<BB * NN, 256>>>(edges, adj);
    k_ninj<<<dim3(2, 48, 2), 256>>>(nodes, ew1, eb1);
    k_node<<<96, 256>>>(nodes, nw1, nb1, ng, nbt, nw2, nb2, out_nodes);
    k_edge_mma<<<dim3(6, NN, BB), 256, EDGE_SMEM_BYTES>>>(edges, ew1, eg, ebt, ew2, eb2, out_edges);
}

// round 6
// speedup vs baseline: 1.0443x; 1.0443x over previous
#include <cuda_runtime.h>
#include <cstdint>

#define BB 2
#define NN 384
#define DD 768
#define EE 64
#define HH 512
#define JT 128

// -------- scratch (no allocations allowed) --------
__device__ float g_agg[BB * NN * EE];     //  192 KB
__device__ float g_NI [BB * NN * HH];     // 1.5 MB  (nodes@Wi + eb1)
__device__ float g_NJ [BB * NN * HH];     // 1.5 MB  (nodes@Wj)

__device__ __forceinline__ uint32_t f32_to_tf32(float f) {
    uint32_t r;
    asm("cvt.rna.tf32.f32 %0, %1;" : "=r"(r) : "f"(f));
    return r;
}
__device__ __forceinline__ void mma_tf32(float c[4],
                                         uint32_t a0, uint32_t a1, uint32_t a2, uint32_t a3,
                                         uint32_t b0, uint32_t b1) {
    asm volatile("mma.sync.aligned.m16n8k8.row.col.f32.tf32.tf32.f32 "
        "{%0,%1,%2,%3}, {%4,%5,%6,%7}, {%8,%9}, {%0,%1,%2,%3};"
        : "+f"(c[0]), "+f"(c[1]), "+f"(c[2]), "+f"(c[3])
        : "r"(a0), "r"(a1), "r"(a2), "r"(a3), "r"(b0), "r"(b1));
}

// ============================================================
// Kernel 1: agg[b,i,e] = sum_j edges[b,i,j,e] * adj[b,i,j]
// ============================================================
__global__ __launch_bounds__(256) void k_agg(const float* __restrict__ edges,
                                             const float* __restrict__ adj)
{
    int bi = blockIdx.x;
    int e  = threadIdx.x & 63;
    int jg = threadIdx.x >> 6;
    const float* erow = edges + (size_t)bi * NN * EE;
    const float* arow = adj   + (size_t)bi * NN;
    float acc = 0.f;
    for (int j = jg; j < NN; j += 4) {
        float a = arow[j];
        if (a != 0.f) acc += erow[(size_t)j * EE + e] * a;
    }
    __shared__ float red[4][64];
    red[jg][e] = acc;
    __syncthreads();
    if (jg == 0)
        g_agg[(size_t)bi * EE + e] = red[0][e] + red[1][e] + red[2][e] + red[3][e];
}

// ============================================================
// Kernel 2: NI = nodes @ Wi + eb1 ; NJ = nodes @ Wj  (exact fp32)
// ============================================================
__global__ __launch_bounds__(256) void k_ninj(const float* __restrict__ nodes,
                                              const float* __restrict__ ew1,
                                              const float* __restrict__ eb1)
{
    __shared__ float sA[16 * DD];
    const int tid   = threadIdx.x;
    const int cbase = blockIdx.x * 256;
    const int r0    = blockIdx.y * 16;
    const int z     = blockIdx.z;
    const int rg    = tid >> 6;
    const int cc    = tid & 63;

    #pragma unroll
    for (int t = 0; t < 48; t++) {
        int lin = t * 256 + tid;
        sA[lin] = nodes[(size_t)r0 * DD + lin];
    }
    __syncthreads();

    const int woff = EE + z * DD;
    float acc[4][4];
    #pragma unroll
    for (int q = 0; q < 4; q++)
        #pragma unroll
        for (int x = 0; x < 4; x++) acc[q][x] = 0.f;

    #pragma unroll 4
    for (int k = 0; k < DD; k++) {
        float4 w = __ldg((const float4*)&ew1[(size_t)(woff + k) * HH + cbase + cc * 4]);
        #pragma unroll
        for (int q = 0; q < 4; q++) {
            float a = sA[(rg * 4 + q) * DD + k];
            acc[q][0] += a * w.x; acc[q][1] += a * w.y;
            acc[q][2] += a * w.z; acc[q][3] += a * w.w;
        }
    }

    float* dst = (z == 0) ? g_NI : g_NJ;
    float4 bb = make_float4(0.f, 0.f, 0.f, 0.f);
    if (z == 0) bb = __ldg((const float4*)&eb1[cbase + cc * 4]);
    #pragma unroll
    for (int q = 0; q < 4; q++) {
        int g = r0 + rg * 4 + q;
        float4 o = make_float4(acc[q][0] + bb.x, acc[q][1] + bb.y,
                               acc[q][2] + bb.z, acc[q][3] + bb.w);
        *(float4*)&dst[(size_t)g * HH + cbase + cc * 4] = o;
    }
}

// ============================================================
// Kernel 3: node path (exact fp32)
// ============================================================
#define MK (EE + DD)
__global__ __launch_bounds__(256) void k_node(const float* __restrict__ nodes,
                                              const float* __restrict__ nw1,
                                              const float* __restrict__ nb1,
                                              const float* __restrict__ ng,
                                              const float* __restrict__ nbt,
                                              const float* __restrict__ nw2,
                                              const float* __restrict__ nb2,
                                              float* __restrict__ out_nodes)
{
    __shared__ float sM[8 * MK];
    __shared__ float sH[8 * 516];
    const int tid = threadIdx.x;
    const int r0  = blockIdx.x * 8;

    for (int t = 0; t < 26; t++) {
        int lin = t * 256 + tid;
        int r = lin / MK, c = lin - r * MK;
        int g = r0 + r;
        float v = (c < EE) ? g_agg[(size_t)g * EE + c]
                           : nodes[(size_t)g * DD + (c - EE)] * (float)NN;
        sM[lin] = v;
    }
    __syncthreads();

    const int rg = tid >> 7;
    const int hc = tid & 127;
    float acc[4][4];
    #pragma unroll
    for (int q = 0; q < 4; q++)
        #pragma unroll
        for (int x = 0; x < 4; x++) acc[q][x] = 0.f;

    #pragma unroll 4
    for (int k = 0; k < MK; k++) {
        float4 w = __ldg((const float4*)&nw1[(size_t)k * HH + hc * 4]);
        #pragma unroll
        for (int q = 0; q < 4; q++) {
            float a = sM[(rg * 4 + q) * MK + k];
            acc[q][0] += a * w.x; acc[q][1] += a * w.y;
            acc[q][2] += a * w.z; acc[q][3] += a * w.w;
        }
    }
    {
        float4 b4 = __ldg((const float4*)&nb1[hc * 4]);
        #pragma unroll
        for (int q = 0; q < 4; q++) {
            float* d = &sH[(rg * 4 + q) * 516 + hc * 4];
            *(float4*)d = make_float4(acc[q][0] + b4.x, acc[q][1] + b4.y,
                                      acc[q][2] + b4.z, acc[q][3] + b4.w);
        }
    }
    __syncthreads();

    {
        int wid = tid >> 5, lane = tid & 31;
        float s = 0.f, ss = 0.f;
        #pragma unroll
        for (int m = 0; m < 16; m++) {
            float v = sH[wid * 516 + lane + m * 32];
            s += v; ss += v * v;
        }
        #pragma unroll
        for (int m = 16; m >= 1; m >>= 1) {
            s  += __shfl_xor_sync(0xffffffffu, s, m);
            ss += __shfl_xor_sync(0xffffffffu, ss, m);
        }
        float mu = s * (1.f / HH);
        float var = ss * (1.f / HH) - mu * mu;
        float rs = rsqrtf(var + 1e-5f);
        #pragma unroll
        for (int m = 0; m < 16; m++) {
            int h = lane + m * 32;
            float v = sH[wid * 516 + h];
            v = (v - mu) * rs * __ldg(&ng[h]) + __ldg(&nbt[h]);
            sH[wid * 516 + h] = fmaxf(v, 0.f);
        }
    }
    __syncthreads();

    float acc2[8][3];
    #pragma unroll
    for (int r = 0; r < 8; r++)
        #pragma unroll
        for (int k = 0; k < 3; k++) acc2[r][k] = 0.f;

    #pragma unroll 2
    for (int h = 0; h < HH; h++) {
        float w0 = __ldg(&nw2[(size_t)h * DD + tid]);
        float w1 = __ldg(&nw2[(size_t)h * DD + tid + 256]);
        float w2 = __ldg(&nw2[(size_t)h * DD + tid + 512]);
        #pragma unroll
        for (int r = 0; r < 8; r++) {
            float a = sH[r * 516 + h];
            acc2[r][0] += a * w0; acc2[r][1] += a * w1; acc2[r][2] += a * w2;
        }
    }
    #pragma unroll
    for (int r = 0; r < 8; r++) {
        int g = r0 + r;
        #pragma unroll
        for (int k = 0; k < 3; k++) {
            int d = tid + k * 256;
            out_nodes[(size_t)g * DD + d] =
                __ldg(&nodes[(size_t)g * DD + d]) + acc2[r][k] + __ldg(&nb2[d]);
        }
    }
}

// ============================================================
// Kernel 4: recompute-style fused edge path, 2 CTAs/SM.
// CTA = (b,i) x 128-j tile.  Pass A: stats only.  Pass B:
// recompute he chunk -> LN -> A' -> GEMM2 accumulate.
// ============================================================
#define OFF_E    0        // [128][68] tf32
#define OFF_W    8704     // [64][68] tf32 (W1 / W2 chunks)
#define OFF_H    13056    // [128][68] f32 / tf32 bounce buffer
#define OFF_NI   21760    // [512]
#define OFF_EG   22272    // [512]
#define OFF_EBT  22784    // [512]
#define OFF_SUM  23296    // [256]
#define OFF_SQ   23552    // [256]
#define OFF_MU   23808    // [128]
#define OFF_RS   23936    // [128]
#define EDGE_SMEM_BYTES (24064 * 4)

// GEMM over k=64: out 128x64, warp tile 32x32 (4m x 2n), accumulate into c.
__device__ __forceinline__ void gemm64(const uint32_t* su, int offA, int offB,
                                       int mt, int nt, int g, int tig,
                                       float c[2][4][4]) {
    #pragma unroll
    for (int kk = 0; kk < 8; kk++) {
        int k0 = kk * 8;
        uint32_t a[2][4];
        #pragma unroll
        for (int mi = 0; mi < 2; mi++) {
            int r0 = offA + (mt + mi * 16 + g) * 68 + k0 + tig;
            a[mi][0] = su[r0];
            a[mi][1] = su[r0 + 8 * 68];
            a[mi][2] = su[r0 + 4];
            a[mi][3] = su[r0 + 8 * 68 + 4];
        }
        #pragma unroll
        for (int ni = 0; ni < 4; ni++) {
            int nb = offB + (nt + ni * 8 + g) * 68 + k0 + tig;
            uint32_t b0 = su[nb], b1 = su[nb + 4];
            mma_tf32(c[0][ni], a[0][0], a[0][1], a[0][2], a[0][3], b0, b1);
            mma_tf32(c[1][ni], a[1][0], a[1][1], a[1][2], a[1][3], b0, b1);
        }
    }
}

__device__ __forceinline__ void store_frags(float* smem, int mt, int nt,
                                            int g, int tig, const float c[2][4][4]) {
    #pragma unroll
    for (int mi = 0; mi < 2; mi++)
        #pragma unroll
        for (int rr = 0; rr < 2; rr++) {
            int row = mt + mi * 16 + rr * 8 + g;
            #pragma unroll
            for (int ni = 0; ni < 4; ni++)
                *(float2*)&smem[OFF_H + row * 68 + nt + ni * 8 + 2 * tig] =
                    make_float2(c[mi][ni][rr * 2 + 0], c[mi][ni][rr * 2 + 1]);
        }
}

// stage 64x64 W tile: su[offW + n*68 + k] = tf32(src[(row0+k)*ld + colbase + n])
__device__ __forceinline__ void stage_w(uint32_t* su, const float* src,
                                        int row0, int ld, int colbase, int tid) {
    #pragma unroll
    for (int t = 0; t < 4; t++) {
        int q = t * 256 + tid;
        int n = q >> 4, k0 = (q & 15) * 4;
        const float* p = src + (size_t)(row0 + k0) * ld + colbase + n;
        uint4 o;
        o.x = f32_to_tf32(__ldg(p));
        o.y = f32_to_tf32(__ldg(p + ld));
        o.z = f32_to_tf32(__ldg(p + 2 * ld));
        o.w = f32_to_tf32(__ldg(p + 3 * ld));
        *(uint4*)&su[OFF_W + n * 68 + k0] = o;
    }
}

__global__ __launch_bounds__(256, 2) void k_edge_mma(
    const float* __restrict__ edges,
    const float* __restrict__ ew1,   // We = first 64 rows
    const float* __restrict__ eg,
    const float* __restrict__ ebt,
    const float* __restrict__ ew2,
    const float* __restrict__ eb2,
    float* __restrict__ out_edges)
{
    extern __shared__ float smem[];
    uint32_t* su = (uint32_t*)smem;
    const int tid = threadIdx.x;
    const int w = tid >> 5, lane = tid & 31;
    const int g = lane >> 2, tig = lane & 3;
    const int mt = (w & 3) * 32, nt = (w >> 2) * 32;
    const int b = blockIdx.z, i = blockIdx.y;
    const int j0 = blockIdx.x * JT;
    const int rrow = tid >> 1, rhalf = tid & 1;   // row-pass mapping

    // ---- stage edge tile [128][68] tf32 + NI/eg/ebt caches ----
    const float* etile = edges + ((size_t)((size_t)b * NN + i) * NN + j0) * EE;
    #pragma unroll
    for (int t = 0; t < 8; t++) {
        int q = t * 256 + tid;               // 2048 quads
        int j = q >> 4, k0 = (q & 15) * 4;
        float4 v = __ldg((const float4*)&etile[j * EE + k0]);
        *(uint4*)&su[OFF_E + j * 68 + k0] =
            make_uint4(f32_to_tf32(v.x), f32_to_tf32(v.y),
                       f32_to_tf32(v.z), f32_to_tf32(v.w));
    }
    const float* nip = g_NI + (size_t)((size_t)b * NN + i) * HH;
    #pragma unroll
    for (int t = 0; t < 2; t++) {
        int c = t * 256 + tid;
        smem[OFF_NI + c]  = __ldg(&nip[c]);
        smem[OFF_EG + c]  = __ldg(&eg[c]);
        smem[OFF_EBT + c] = __ldg(&ebt[c]);
    }

    const float* njrow = g_NJ + (size_t)((size_t)b * NN + j0 + rrow) * HH + rhalf * 32;

    // ================= pass A: LN statistics =================
    float accS = 0.f, accQ = 0.f;
    for (int ch = 0; ch < 8; ch++) {
        __syncthreads();
        stage_w(su, ew1, 0, HH, ch * 64, tid);
        __syncthreads();
        float c[2][4][4];
        #pragma unroll
        for (int mi = 0; mi < 2; mi++)
            #pragma unroll
            for (int ni = 0; ni < 4; ni++)
                #pragma unroll
                for (int x = 0; x < 4; x++) c[mi][ni][x] = 0.f;
        gemm64(su, OFF_E, OFF_W, mt, nt, g, tig, c);
        store_frags(smem, mt, nt, g, tig, c);
        __syncthreads();
        // row pass: he = M + NI + NJ, accumulate stats
        const int hb = OFF_H + rrow * 68 + rhalf * 32;
        const int cb = ch * 64 + rhalf * 32;
        #pragma unroll
        for (int c4 = 0; c4 < 8; c4++) {
            float4 m  = *(float4*)&smem[hb + c4 * 4];
            float4 nj = __ldg((const float4*)&njrow[ch * 64 + c4 * 4]);
            float4 ni = *(float4*)&smem[OFF_NI + cb + c4 * 4];
            float v0 = m.x + ni.x + nj.x, v1 = m.y + ni.y + nj.y;
            float v2 = m.z + ni.z + nj.z, v3 = m.w + ni.w + nj.w;
            accS += v0 + v1 + v2 + v3;
            accQ += v0 * v0 + v1 * v1 + v2 * v2 + v3 * v3;
        }
    }
    __syncthreads();
    smem[OFF_SUM + tid] = accS;
    smem[OFF_SQ + tid]  = accQ;
    __syncthreads();
    if (tid < 128) {
        float s = smem[OFF_SUM + 2 * tid] + smem[OFF_SUM + 2 * tid + 1];
        float q = smem[OFF_SQ + 2 * tid]  + smem[OFF_SQ + 2 * tid + 1];
        float mu = s * (1.f / HH);
        float var = q * (1.f / HH) - mu * mu;
        smem[OFF_MU + tid] = mu;
        smem[OFF_RS + tid] = rsqrtf(var + 1e-5f);
    }

    // ================= pass B: recompute + LN + GEMM2 =================
    float c2[2][4][4];
    #pragma unroll
    for (int mi = 0; mi < 2; mi++)
        #pragma unroll
        for (int ni = 0; ni < 4; ni++)
            #pragma unroll
            for (int x = 0; x < 4; x++) c2[mi][ni][x] = 0.f;

    for (int kc = 0; kc < 8; kc++) {
        __syncthreads();                     // sW free, sHeA free, MU visible
        stage_w(su, ew1, 0, HH, kc * 64, tid);
        __syncthreads();
        float c[2][4][4];
        #pragma unroll
        for (int mi = 0; mi < 2; mi++)
            #pragma unroll
            for (int ni = 0; ni < 4; ni++)
                #pragma unroll
                for (int x = 0; x < 4; x++) c[mi][ni][x] = 0.f;
        gemm64(su, OFF_E, OFF_W, mt, nt, g, tig, c);
        store_frags(smem, mt, nt, g, tig, c);
        __syncthreads();                     // M ready; sW1 consumed
        // stage W2 chunk (ew2 rows kc*64..) and run LN row pass
        stage_w(su, ew2, kc * 64, EE, 0, tid);
        {
            const int hb = OFF_H + rrow * 68 + rhalf * 32;
            const int cb = kc * 64 + rhalf * 32;
            float mu = smem[OFF_MU + rrow], rs = smem[OFF_RS + rrow];
            #pragma unroll
            for (int c4 = 0; c4 < 8; c4++) {
                float4 m  = *(float4*)&smem[hb + c4 * 4];
                float4 nj = __ldg((const float4*)&njrow[kc * 64 + c4 * 4]);
                float4 ni = *(float4*)&smem[OFF_NI + cb + c4 * 4];
                float4 gg = *(float4*)&smem[OFF_EG + cb + c4 * 4];
                float4 bb = *(float4*)&smem[OFF_EBT + cb + c4 * 4];
                uint4 o;
                o.x = f32_to_tf32(fmaxf((m.x + ni.x + nj.x - mu) * rs * gg.x + bb.x, 0.f));
                o.y = f32_to_tf32(fmaxf((m.y + ni.y + nj.y - mu) * rs * gg.y + bb.y, 0.f));
                o.z = f32_to_tf32(fmaxf((m.z + ni.z + nj.z - mu) * rs * gg.z + bb.z, 0.f));
                o.w = f32_to_tf32(fmaxf((m.w + ni.w + nj.w - mu) * rs * gg.w + bb.w, 0.f));
                *(uint4*)&su[hb + c4 * 4] = o;
            }
        }
        __syncthreads();                     // A' + W2 ready
        gemm64(su, OFF_H, OFF_W, mt, nt, g, tig, c2);
    }

    // ---- epilogue: bounce c2 through smem, coalesced residual+store ----
    __syncthreads();
    store_frags(smem, mt, nt, g, tig, c2);
    __syncthreads();
    {
        size_t gbase = ((size_t)((size_t)b * NN + i) * NN + j0 + rrow) * EE + rhalf * 32;
        const int hb = OFF_H + rrow * 68 + rhalf * 32;
        #pragma unroll
        for (int c4 = 0; c4 < 8; c4++) {
            float4 m  = *(float4*)&smem[hb + c4 * 4];
            float4 e4 = __ldg((const float4*)&edges[gbase + c4 * 4]);
            float4 b4 = __ldg((const float4*)&eb2[rhalf * 32 + c4 * 4]);
            float4 o = make_float4(e4.x + m.x + b4.x, e4.y + m.y + b4.y,
                                   e4.z + m.z + b4.z, e4.w + m.w + b4.w);
            *(float4*)&out_edges[gbase + c4 * 4] = o;
        }
    }
}

// ============================================================
extern "C" void kernel_launch(void* const* d_in, const int* in_sizes, int n_in,
                              void* d_out, int out_size)
{
    const float* nodes = (const float*)d_in[0];
    const float* edges = (const float*)d_in[1];
    const float* adj   = (const float*)d_in[2];
    const float* nw1   = (const float*)d_in[3];
    const float* nb1   = (const float*)d_in[4];
    const float* ng    = (const float*)d_in[5];
    const float* nbt   = (const float*)d_in[6];
    const float* nw2   = (const float*)d_in[7];
    const float* nb2   = (const float*)d_in[8];
    const float* ew1   = (const float*)d_in[9];
    const float* eb1   = (const float*)d_in[10];
    const float* eg    = (const float*)d_in[11];
    const float* ebt   = (const float*)d_in[12];
    const float* ew2   = (const float*)d_in[13];
    const float* eb2   = (const float*)d_in[14];

    float* out_nodes = (float*)d_out;
    float* out_edges = out_nodes + (size_t)BB * NN * DD;

    cudaFuncSetAttribute(k_edge_mma, cudaFuncAttributeMaxDynamicSharedMemorySize,
                         EDGE_SMEM_BYTES);

    k_agg <<<BB * NN, 256>>>(edges, adj);
    k_ninj<<<dim3(2, 48, 2), 256>>>(nodes, ew1, eb1);
    k_node<<<96, 256>>>(nodes, nw1, nb1, ng, nbt, nw2, nb2, out_nodes);
    k_edge_mma<<<dim3(NN / JT, NN, BB), 256, EDGE_SMEM_BYTES>>>(edges, ew1, eg, ebt, ew2, eb2, out_edges);
}

// round 7
// speedup vs baseline: 1.4475x; 1.3860x over previous
#include <cuda_runtime.h>
#include <cuda_fp16.h>
#include <cstdint>

#define BB 2
#define NN 384
#define DD 768
#define EE 64
#define HH 512
#define JT 128

// -------- scratch (no allocations allowed) --------
__device__ float g_agg[BB * NN * EE];     //  192 KB
__device__ float g_NI [BB * NN * HH];     // 1.5 MB  (nodes@Wi + eb1)
__device__ float g_NJ [BB * NN * HH];     // 1.5 MB  (nodes@Wj)

__device__ __forceinline__ uint32_t pack2(float a, float b) {
    __half2 h = __floats2half2_rn(a, b);
    return *reinterpret_cast<uint32_t*>(&h);
}
__device__ __forceinline__ void ldm_x4(uint32_t& r0, uint32_t& r1,
                                       uint32_t& r2, uint32_t& r3, uint32_t addr) {
    asm volatile("ldmatrix.sync.aligned.m8n8.x4.shared.b16 {%0,%1,%2,%3}, [%4];"
                 : "=r"(r0), "=r"(r1), "=r"(r2), "=r"(r3) : "r"(addr));
}
__device__ __forceinline__ void mma_f16(float c[4],
                                        uint32_t a0, uint32_t a1, uint32_t a2, uint32_t a3,
                                        uint32_t b0, uint32_t b1) {
    asm volatile("mma.sync.aligned.m16n8k16.row.col.f32.f16.f16.f32 "
        "{%0,%1,%2,%3}, {%4,%5,%6,%7}, {%8,%9}, {%0,%1,%2,%3};"
        : "+f"(c[0]), "+f"(c[1]), "+f"(c[2]), "+f"(c[3])
        : "r"(a0), "r"(a1), "r"(a2), "r"(a3), "r"(b0), "r"(b1));
}

// ============================================================
// Kernel 1: agg[b,i,e] = sum_j edges[b,i,j,e] * adj[b,i,j]
// ============================================================
__global__ __launch_bounds__(256) void k_agg(const float* __restrict__ edges,
                                             const float* __restrict__ adj)
{
    int bi = blockIdx.x;
    int e  = threadIdx.x & 63;
    int jg = threadIdx.x >> 6;
    const float* erow = edges + (size_t)bi * NN * EE;
    const float* arow = adj   + (size_t)bi * NN;
    float acc = 0.f;
    for (int j = jg; j < NN; j += 4) {
        float a = arow[j];
        if (a != 0.f) acc += erow[(size_t)j * EE + e] * a;
    }
    __shared__ float red[4][64];
    red[jg][e] = acc;
    __syncthreads();
    if (jg == 0)
        g_agg[(size_t)bi * EE + e] = red[0][e] + red[1][e] + red[2][e] + red[3][e];
}

// ============================================================
// Kernel 2: NI = nodes @ Wi + eb1 ; NJ = nodes @ Wj  (exact fp32)
// ============================================================
__global__ __launch_bounds__(256) void k_ninj(const float* __restrict__ nodes,
                                              const float* __restrict__ ew1,
                                              const float* __restrict__ eb1)
{
    __shared__ float sA[16 * DD];
    const int tid   = threadIdx.x;
    const int cbase = blockIdx.x * 256;
    const int r0    = blockIdx.y * 16;
    const int z     = blockIdx.z;
    const int rg    = tid >> 6;
    const int cc    = tid & 63;

    #pragma unroll
    for (int t = 0; t < 48; t++) {
        int lin = t * 256 + tid;
        sA[lin] = nodes[(size_t)r0 * DD + lin];
    }
    __syncthreads();

    const int woff = EE + z * DD;
    float acc[4][4];
    #pragma unroll
    for (int q = 0; q < 4; q++)
        #pragma unroll
        for (int x = 0; x < 4; x++) acc[q][x] = 0.f;

    #pragma unroll 4
    for (int k = 0; k < DD; k++) {
        float4 w = __ldg((const float4*)&ew1[(size_t)(woff + k) * HH + cbase + cc * 4]);
        #pragma unroll
        for (int q = 0; q < 4; q++) {
            float a = sA[(rg * 4 + q) * DD + k];
            acc[q][0] += a * w.x; acc[q][1] += a * w.y;
            acc[q][2] += a * w.z; acc[q][3] += a * w.w;
        }
    }

    float* dst = (z == 0) ? g_NI : g_NJ;
    float4 bb = make_float4(0.f, 0.f, 0.f, 0.f);
    if (z == 0) bb = __ldg((const float4*)&eb1[cbase + cc * 4]);
    #pragma unroll
    for (int q = 0; q < 4; q++) {
        int g = r0 + rg * 4 + q;
        float4 o = make_float4(acc[q][0] + bb.x, acc[q][1] + bb.y,
                               acc[q][2] + bb.z, acc[q][3] + bb.w);
        *(float4*)&dst[(size_t)g * HH + cbase + cc * 4] = o;
    }
}

// ============================================================
// Kernel 3: node path (exact fp32)
// ============================================================
#define MK (EE + DD)
__global__ __launch_bounds__(256) void k_node(const float* __restrict__ nodes,
                                              const float* __restrict__ nw1,
                                              const float* __restrict__ nb1,
                                              const float* __restrict__ ng,
                                              const float* __restrict__ nbt,
                                              const float* __restrict__ nw2,
                                              const float* __restrict__ nb2,
                                              float* __restrict__ out_nodes)
{
    __shared__ float sM[8 * MK];
    __shared__ float sH[8 * 516];
    const int tid = threadIdx.x;
    const int r0  = blockIdx.x * 8;

    for (int t = 0; t < 26; t++) {
        int lin = t * 256 + tid;
        int r = lin / MK, c = lin - r * MK;
        int g = r0 + r;
        float v = (c < EE) ? g_agg[(size_t)g * EE + c]
                           : nodes[(size_t)g * DD + (c - EE)] * (float)NN;
        sM[lin] = v;
    }
    __syncthreads();

    const int rg = tid >> 7;
    const int hc = tid & 127;
    float acc[4][4];
    #pragma unroll
    for (int q = 0; q < 4; q++)
        #pragma unroll
        for (int x = 0; x < 4; x++) acc[q][x] = 0.f;

    #pragma unroll 4
    for (int k = 0; k < MK; k++) {
        float4 w = __ldg((const float4*)&nw1[(size_t)k * HH + hc * 4]);
        #pragma unroll
        for (int q = 0; q < 4; q++) {
            float a = sM[(rg * 4 + q) * MK + k];
            acc[q][0] += a * w.x; acc[q][1] += a * w.y;
            acc[q][2] += a * w.z; acc[q][3] += a * w.w;
        }
    }
    {
        float4 b4 = __ldg((const float4*)&nb1[hc * 4]);
        #pragma unroll
        for (int q = 0; q < 4; q++) {
            float* d = &sH[(rg * 4 + q) * 516 + hc * 4];
            *(float4*)d = make_float4(acc[q][0] + b4.x, acc[q][1] + b4.y,
                                      acc[q][2] + b4.z, acc[q][3] + b4.w);
        }
    }
    __syncthreads();

    {
        int wid = tid >> 5, lane = tid & 31;
        float s = 0.f, ss = 0.f;
        #pragma unroll
        for (int m = 0; m < 16; m++) {
            float v = sH[wid * 516 + lane + m * 32];
            s += v; ss += v * v;
        }
        #pragma unroll
        for (int m = 16; m >= 1; m >>= 1) {
            s  += __shfl_xor_sync(0xffffffffu, s, m);
            ss += __shfl_xor_sync(0xffffffffu, ss, m);
        }
        float mu = s * (1.f / HH);
        float var = ss * (1.f / HH) - mu * mu;
        float rs = rsqrtf(var + 1e-5f);
        #pragma unroll
        for (int m = 0; m < 16; m++) {
            int h = lane + m * 32;
            float v = sH[wid * 516 + h];
            v = (v - mu) * rs * __ldg(&ng[h]) + __ldg(&nbt[h]);
            sH[wid * 516 + h] = fmaxf(v, 0.f);
        }
    }
    __syncthreads();

    float acc2[8][3];
    #pragma unroll
    for (int r = 0; r < 8; r++)
        #pragma unroll
        for (int k = 0; k < 3; k++) acc2[r][k] = 0.f;

    #pragma unroll 2
    for (int h = 0; h < HH; h++) {
        float w0 = __ldg(&nw2[(size_t)h * DD + tid]);
        float w1 = __ldg(&nw2[(size_t)h * DD + tid + 256]);
        float w2 = __ldg(&nw2[(size_t)h * DD + tid + 512]);
        #pragma unroll
        for (int r = 0; r < 8; r++) {
            float a = sH[r * 516 + h];
            acc2[r][0] += a * w0; acc2[r][1] += a * w1; acc2[r][2] += a * w2;
        }
    }
    #pragma unroll
    for (int r = 0; r < 8; r++) {
        int g = r0 + r;
        #pragma unroll
        for (int k = 0; k < 3; k++) {
            int d = tid + k * 256;
            out_nodes[(size_t)g * DD + d] =
                __ldg(&nodes[(size_t)g * DD + d]) + acc2[r][k] + __ldg(&nb2[d]);
        }
    }
}

// ============================================================
// Kernel 4: fp16 ldmatrix/mma fused edge path, 2 CTAs/SM.
// CTA = (b,i) x 128-j tile.  Pass A: frag-domain LN stats.
// Pass B: recompute chunk -> frag-domain LN -> fp16 A' -> GEMM2.
// ============================================================
// float region (float indices)
#define F_NI   0
#define F_EG   512
#define F_EBT  1024
#define F_SUM  1536
#define F_SQ   1664
#define F_MU   1792
#define F_RS   1920
// half region (half indices, base = float idx 2048)
#define HS     72
#define H_E    4096                  // [128][72]
#define H_W1   (H_E + 128 * HS)      // [64][72]
#define H_W2   (H_W1 + 64 * HS)      // [64][72]
#define H_A2   (H_W2 + 64 * HS)      // [128][72]
#define EDGE_SMEM_BYTES (2 * (H_A2 + 128 * HS))

// warp-tile m32 x n32 GEMM over one k=64 chunk, fp16 operands
__device__ __forceinline__ void gemm_f16(uint32_t sb, int offA, int offB,
                                         int mt, int nt, int lane, float c[2][4][4]) {
    const int lrow = lane & 15;
    const int lk8  = (lane >> 4) << 3;            // A k-offset
    const int bn   = (lane & 7) + ((lane >> 4) << 3);
    const int bk8  = ((lane >> 3) & 1) << 3;      // B k-offset
    #pragma unroll
    for (int ks = 0; ks < 4; ks++) {
        int k0 = ks * 16;
        uint32_t a[2][4], bf[2][4];
        #pragma unroll
        for (int mi = 0; mi < 2; mi++)
            ldm_x4(a[mi][0], a[mi][1], a[mi][2], a[mi][3],
                   sb + 2 * (offA + (mt + mi * 16 + lrow) * HS + k0 + lk8));
        #pragma unroll
        for (int nb = 0; nb < 2; nb++)
            ldm_x4(bf[nb][0], bf[nb][1], bf[nb][2], bf[nb][3],
                   sb + 2 * (offB + (nt + nb * 16 + bn) * HS + k0 + bk8));
        #pragma unroll
        for (int mi = 0; mi < 2; mi++) {
            mma_f16(c[mi][0], a[mi][0], a[mi][1], a[mi][2], a[mi][3], bf[0][0], bf[0][1]);
            mma_f16(c[mi][1], a[mi][0], a[mi][1], a[mi][2], a[mi][3], bf[0][2], bf[0][3]);
            mma_f16(c[mi][2], a[mi][0], a[mi][1], a[mi][2], a[mi][3], bf[1][0], bf[1][1]);
            mma_f16(c[mi][3], a[mi][0], a[mi][1], a[mi][2], a[mi][3], bf[1][2], bf[1][3]);
        }
    }
}

__global__ __launch_bounds__(256, 2) void k_edge_mma(
    const float* __restrict__ edges,
    const float* __restrict__ ew1,   // We = first 64 rows of ew1
    const float* __restrict__ eg,
    const float* __restrict__ ebt,
    const float* __restrict__ ew2,
    const float* __restrict__ eb2,
    float* __restrict__ out_edges)
{
    extern __shared__ float smem[];
    __half* sh = (__half*)smem;
    const uint32_t sb = (uint32_t)__cvta_generic_to_shared(smem);
    const int tid = threadIdx.x;
    const int w = tid >> 5, lane = tid & 31;
    const int g = lane >> 2, tig = lane & 3;
    const int mt = (w & 3) * 32, nt = (w >> 2) * 32;
    const int b = blockIdx.z, i = blockIdx.y;
    const int j0 = blockIdx.x * JT;

    // ---- stage edge tile [128][HS] fp16 ----
    const float* etile = edges + ((size_t)((size_t)b * NN + i) * NN + j0) * EE;
    #pragma unroll
    for (int t = 0; t < 8; t++) {
        int q = t * 256 + tid;               // 2048 quads
        int j = q >> 4, k0 = (q & 15) * 4;
        float4 v = __ldg((const float4*)&etile[j * EE + k0]);
        *(uint2*)&sh[H_E + j * HS + k0] = make_uint2(pack2(v.x, v.y), pack2(v.z, v.w));
    }
    // ---- NI/eg/ebt caches + zero stats ----
    const float* nip = g_NI + (size_t)((size_t)b * NN + i) * HH;
    #pragma unroll
    for (int t = 0; t < 2; t++) {
        int c = t * 256 + tid;
        smem[F_NI + c]  = __ldg(&nip[c]);
        smem[F_EG + c]  = __ldg(&eg[c]);
        smem[F_EBT + c] = __ldg(&ebt[c]);
    }
    if (tid < 128) { smem[F_SUM + tid] = 0.f; smem[F_SQ + tid] = 0.f; }

    const float* njb = g_NJ + (size_t)((size_t)b * NN + j0) * HH;

    // ================= pass A: LN statistics (frag domain) =================
    float rsum[4] = {0.f, 0.f, 0.f, 0.f}, rsq[4] = {0.f, 0.f, 0.f, 0.f};
    for (int ch = 0; ch < 8; ch++) {
        __syncthreads();                     // sW1 free / staging visible
        // stage We chunk: W1[n][k] = ew1[k][ch*64+n]
        #pragma unroll
        for (int t = 0; t < 4; t++) {
            int q = t * 256 + tid;           // 1024 quads
            int n = q >> 4, k0 = (q & 15) * 4;
            const float* p = ew1 + (size_t)k0 * HH + ch * 64 + n;
            *(uint2*)&sh[H_W1 + n * HS + k0] =
                make_uint2(pack2(__ldg(p), __ldg(p + HH)),
                           pack2(__ldg(p + 2 * HH), __ldg(p + 3 * HH)));
        }
        __syncthreads();

        float c[2][4][4];
        #pragma unroll
        for (int mi = 0; mi < 2; mi++)
            #pragma unroll
            for (int nj = 0; nj < 4; nj++)
                #pragma unroll
                for (int x = 0; x < 4; x++) c[mi][nj][x] = 0.f;
        gemm_f16(sb, H_E, H_W1, mt, nt, lane, c);

        // frag-domain: += NI + NJ, accumulate stats
        #pragma unroll
        for (int mi = 0; mi < 2; mi++)
            #pragma unroll
            for (int rr = 0; rr < 2; rr++) {
                int row = mt + mi * 16 + rr * 8 + g;
                const float* njp = njb + (size_t)row * HH + ch * 64;
                float s = 0.f, q2 = 0.f;
                #pragma unroll
                for (int nj = 0; nj < 4; nj++) {
                    int cl = nt + nj * 8 + 2 * tig;
                    float2 n2 = __ldg((const float2*)&njp[cl]);
                    float v0 = c[mi][nj][rr * 2 + 0] + smem[F_NI + ch * 64 + cl] + n2.x;
                    float v1 = c[mi][nj][rr * 2 + 1] + smem[F_NI + ch * 64 + cl + 1] + n2.y;
                    s += v0 + v1; q2 += v0 * v0 + v1 * v1;
                }
                rsum[mi * 2 + rr] += s;
                rsq[mi * 2 + rr]  += q2;
            }
    }
    // reduce over tig (4 lanes share a row) then cross-warp atomics
    #pragma unroll
    for (int x = 0; x < 4; x++) {
        float s = rsum[x], q2 = rsq[x];
        s  += __shfl_xor_sync(0xffffffffu, s, 1);
        s  += __shfl_xor_sync(0xffffffffu, s, 2);
        q2 += __shfl_xor_sync(0xffffffffu, q2, 1);
        q2 += __shfl_xor_sync(0xffffffffu, q2, 2);
        if (tig == 0) {
            int row = mt + (x >> 1) * 16 + (x & 1) * 8 + g;
            atomicAdd(&smem[F_SUM + row], s);
            atomicAdd(&smem[F_SQ + row], q2);
        }
    }
    __syncthreads();
    if (tid < 128) {
        float mu = smem[F_SUM + tid] * (1.f / HH);
        float var = smem[F_SQ + tid] * (1.f / HH) - mu * mu;
        smem[F_MU + tid] = mu;
        smem[F_RS + tid] = rsqrtf(var + 1e-5f);
    }

    // ================= pass B: recompute + LN + GEMM2 =================
    float c2[2][4][4];
    #pragma unroll
    for (int mi = 0; mi < 2; mi++)
        #pragma unroll
        for (int nj = 0; nj < 4; nj++)
            #pragma unroll
            for (int x = 0; x < 4; x++) c2[mi][nj][x] = 0.f;

    for (int kc = 0; kc < 8; kc++) {
        __syncthreads();                     // prev gemm2 done; MU/RS visible (iter 0)
        // stage W1 chunk + W2 chunk
        #pragma unroll
        for (int t = 0; t < 4; t++) {
            int q = t * 256 + tid;
            int n = q >> 4, k0 = (q & 15) * 4;
            const float* p1 = ew1 + (size_t)k0 * HH + kc * 64 + n;
            *(uint2*)&sh[H_W1 + n * HS + k0] =
                make_uint2(pack2(__ldg(p1), __ldg(p1 + HH)),
                           pack2(__ldg(p1 + 2 * HH), __ldg(p1 + 3 * HH)));
            const float* p2 = ew2 + (size_t)(kc * 64 + k0) * EE + n;
            *(uint2*)&sh[H_W2 + n * HS + k0] =
                make_uint2(pack2(__ldg(p2), __ldg(p2 + EE)),
                           pack2(__ldg(p2 + 2 * EE), __ldg(p2 + 3 * EE)));
        }
        __syncthreads();

        float c[2][4][4];
        #pragma unroll
        for (int mi = 0; mi < 2; mi++)
            #pragma unroll
            for (int nj = 0; nj < 4; nj++)
                #pragma unroll
                for (int x = 0; x < 4; x++) c[mi][nj][x] = 0.f;
        gemm_f16(sb, H_E, H_W1, mt, nt, lane, c);

        // frag-domain LN + relu -> fp16 A'
        #pragma unroll
        for (int mi = 0; mi < 2; mi++)
            #pragma unroll
            for (int rr = 0; rr < 2; rr++) {
                int row = mt + mi * 16 + rr * 8 + g;
                const float* njp = njb + (size_t)row * HH + kc * 64;
                float mu = smem[F_MU + row], rs = smem[F_RS + row];
                #pragma unroll
                for (int nj = 0; nj < 4; nj++) {
                    int cl = nt + nj * 8 + 2 * tig;
                    float2 n2 = __ldg((const float2*)&njp[cl]);
                    float v0 = c[mi][nj][rr * 2 + 0] + smem[F_NI + kc * 64 + cl] + n2.x;
                    float v1 = c[mi][nj][rr * 2 + 1] + smem[F_NI + kc * 64 + cl + 1] + n2.y;
                    v0 = fmaxf((v0 - mu) * rs * smem[F_EG + kc * 64 + cl] + smem[F_EBT + kc * 64 + cl], 0.f);
                    v1 = fmaxf((v1 - mu) * rs * smem[F_EG + kc * 64 + cl + 1] + smem[F_EBT + kc * 64 + cl + 1], 0.f);
                    *(uint32_t*)&sh[H_A2 + row * HS + cl] = pack2(v0, v1);
                }
            }
        __syncthreads();                     // A' visible
        gemm_f16(sb, H_A2, H_W2, mt, nt, lane, c2);
    }

    // ---- epilogue: residual (fresh fp32 edges) + eb2, frag-domain store ----
    #pragma unroll
    for (int mi = 0; mi < 2; mi++)
        #pragma unroll
        for (int rr = 0; rr < 2; rr++) {
            int row = mt + mi * 16 + rr * 8 + g;
            size_t gbase = ((size_t)((size_t)b * NN + i) * NN + j0 + row) * EE;
            #pragma unroll
            for (int nj = 0; nj < 4; nj++) {
                int col = nt + nj * 8 + 2 * tig;
                float2 e2 = __ldg((const float2*)&edges[gbase + col]);
                float2 b2 = __ldg((const float2*)&eb2[col]);
                float2 o = make_float2(e2.x + c2[mi][nj][rr * 2 + 0] + b2.x,
                                       e2.y + c2[mi][nj][rr * 2 + 1] + b2.y);
                *(float2*)&out_edges[gbase + col] = o;
            }
        }
}

// ============================================================
extern "C" void kernel_launch(void* const* d_in, const int* in_sizes, int n_in,
                              void* d_out, int out_size)
{
    const float* nodes = (const float*)d_in[0];
    const float* edges = (const float*)d_in[1];
    const float* adj   = (const float*)d_in[2];
    const float* nw1   = (const float*)d_in[3];
    const float* nb1   = (const float*)d_in[4];
    const float* ng    = (const float*)d_in[5];
    const float* nbt   = (const float*)d_in[6];
    const float* nw2   = (const float*)d_in[7];
    const float* nb2   = (const float*)d_in[8];
    const float* ew1   = (const float*)d_in[9];
    const float* eb1   = (const float*)d_in[10];
    const float* eg    = (const float*)d_in[11];
    const float* ebt   = (const float*)d_in[12];
    const float* ew2   = (const float*)d_in[13];
    const float* eb2   = (const float*)d_in[14];

    float* out_nodes = (float*)d_out;
    float* out_edges = out_nodes + (size_t)BB * NN * DD;

    cudaFuncSetAttribute(k_edge_mma, cudaFuncAttributeMaxDynamicSharedMemorySize,
                         EDGE_SMEM_BYTES);

    k_agg <<<BB * NN, 256>>>(edges, adj);
    k_ninj<<<dim3(2, 48, 2), 256>>>(nodes, ew1, eb1);
    k_node<<<96, 256>>>(nodes, nw1, nb1, ng, nbt, nw2, nb2, out_nodes);
    k_edge_mma<<<dim3(NN / JT, NN, BB), 256, EDGE_SMEM_BYTES>>>(edges, ew1, eg, ebt, ew2, eb2, out_edges);
}

// round 8
// speedup vs baseline: 2.1875x; 1.5112x over previous
#include <cuda_runtime.h>
#include <cuda_fp16.h>
#include <cstdint>

#define BB 2
#define NN 384
#define DD 768
#define EE 64
#define HH 512
#define JT 64

// -------- scratch (no allocations allowed) --------
__device__ float g_agg[BB * NN * EE];     //  192 KB
__device__ float g_NI [BB * NN * HH];     // 1.5 MB  (nodes@Wi + eb1)
__device__ float g_NJ [BB * NN * HH];     // 1.5 MB  (nodes@Wj)

__device__ __forceinline__ uint32_t pack2(float a, float b) {
    __half2 h = __floats2half2_rn(a, b);
    return *reinterpret_cast<uint32_t*>(&h);
}
__device__ __forceinline__ float2 h2f(uint32_t u) {
    return __half22float2(*reinterpret_cast<__half2*>(&u));
}
__device__ __forceinline__ void ldm_x4(uint32_t& r0, uint32_t& r1,
                                       uint32_t& r2, uint32_t& r3, uint32_t addr) {
    asm volatile("ldmatrix.sync.aligned.m8n8.x4.shared.b16 {%0,%1,%2,%3}, [%4];"
                 : "=r"(r0), "=r"(r1), "=r"(r2), "=r"(r3) : "r"(addr));
}
__device__ __forceinline__ void mma_f16(float c[4],
                                        uint32_t a0, uint32_t a1, uint32_t a2, uint32_t a3,
                                        uint32_t b0, uint32_t b1) {
    asm volatile("mma.sync.aligned.m16n8k16.row.col.f32.f16.f16.f32 "
        "{%0,%1,%2,%3}, {%4,%5,%6,%7}, {%8,%9}, {%0,%1,%2,%3};"
        : "+f"(c[0]), "+f"(c[1]), "+f"(c[2]), "+f"(c[3])
        : "r"(a0), "r"(a1), "r"(a2), "r"(a3), "r"(b0), "r"(b1));
}

// ============================================================
// Kernel 1: agg[b,i,e] = sum_j edges[b,i,j,e] * adj[b,i,j]
// ============================================================
__global__ __launch_bounds__(256) void k_agg(const float* __restrict__ edges,
                                             const float* __restrict__ adj)
{
    int bi = blockIdx.x;
    int e  = threadIdx.x & 63;
    int jg = threadIdx.x >> 6;
    const float* erow = edges + (size_t)bi * NN * EE;
    const float* arow = adj   + (size_t)bi * NN;
    float acc = 0.f;
    for (int j = jg; j < NN; j += 4) {
        float a = arow[j];
        if (a != 0.f) acc += erow[(size_t)j * EE + e] * a;
    }
    __shared__ float red[4][64];
    red[jg][e] = acc;
    __syncthreads();
    if (jg == 0)
        g_agg[(size_t)bi * EE + e] = red[0][e] + red[1][e] + red[2][e] + red[3][e];
}

// ============================================================
// Kernel 2: NI = nodes @ Wi + eb1 ; NJ = nodes @ Wj  (exact fp32)
// ============================================================
__global__ __launch_bounds__(256) void k_ninj(const float* __restrict__ nodes,
                                              const float* __restrict__ ew1,
                                              const float* __restrict__ eb1)
{
    __shared__ float sA[16 * DD];
    const int tid   = threadIdx.x;
    const int cbase = blockIdx.x * 256;
    const int r0    = blockIdx.y * 16;
    const int z     = blockIdx.z;
    const int rg    = tid >> 6;
    const int cc    = tid & 63;

    #pragma unroll
    for (int t = 0; t < 48; t++) {
        int lin = t * 256 + tid;
        sA[lin] = nodes[(size_t)r0 * DD + lin];
    }
    __syncthreads();

    const int woff = EE + z * DD;
    float acc[4][4];
    #pragma unroll
    for (int q = 0; q < 4; q++)
        #pragma unroll
        for (int x = 0; x < 4; x++) acc[q][x] = 0.f;

    #pragma unroll 4
    for (int k = 0; k < DD; k++) {
        float4 w = __ldg((const float4*)&ew1[(size_t)(woff + k) * HH + cbase + cc * 4]);
        #pragma unroll
        for (int q = 0; q < 4; q++) {
            float a = sA[(rg * 4 + q) * DD + k];
            acc[q][0] += a * w.x; acc[q][1] += a * w.y;
            acc[q][2] += a * w.z; acc[q][3] += a * w.w;
        }
    }

    float* dst = (z == 0) ? g_NI : g_NJ;
    float4 bb = make_float4(0.f, 0.f, 0.f, 0.f);
    if (z == 0) bb = __ldg((const float4*)&eb1[cbase + cc * 4]);
    #pragma unroll
    for (int q = 0; q < 4; q++) {
        int g = r0 + rg * 4 + q;
        float4 o = make_float4(acc[q][0] + bb.x, acc[q][1] + bb.y,
                               acc[q][2] + bb.z, acc[q][3] + bb.w);
        *(float4*)&dst[(size_t)g * HH + cbase + cc * 4] = o;
    }
}

// ============================================================
// Kernel 3: node path (exact fp32)
// ============================================================
#define MK (EE + DD)
__global__ __launch_bounds__(256) void k_node(const float* __restrict__ nodes,
                                              const float* __restrict__ nw1,
                                              const float* __restrict__ nb1,
                                              const float* __restrict__ ng,
                                              const float* __restrict__ nbt,
                                              const float* __restrict__ nw2,
                                              const float* __restrict__ nb2,
                                              float* __restrict__ out_nodes)
{
    __shared__ float sM[8 * MK];
    __shared__ float sH[8 * 516];
    const int tid = threadIdx.x;
    const int r0  = blockIdx.x * 8;

    for (int t = 0; t < 26; t++) {
        int lin = t * 256 + tid;
        int r = lin / MK, c = lin - r * MK;
        int g = r0 + r;
        float v = (c < EE) ? g_agg[(size_t)g * EE + c]
                           : nodes[(size_t)g * DD + (c - EE)] * (float)NN;
        sM[lin] = v;
    }
    __syncthreads();

    const int rg = tid >> 7;
    const int hc = tid & 127;
    float acc[4][4];
    #pragma unroll
    for (int q = 0; q < 4; q++)
        #pragma unroll
        for (int x = 0; x < 4; x++) acc[q][x] = 0.f;

    #pragma unroll 4
    for (int k = 0; k < MK; k++) {
        float4 w = __ldg((const float4*)&nw1[(size_t)k * HH + hc * 4]);
        #pragma unroll
        for (int q = 0; q < 4; q++) {
            float a = sM[(rg * 4 + q) * MK + k];
            acc[q][0] += a * w.x; acc[q][1] += a * w.y;
            acc[q][2] += a * w.z; acc[q][3] += a * w.w;
        }
    }
    {
        float4 b4 = __ldg((const float4*)&nb1[hc * 4]);
        #pragma unroll
        for (int q = 0; q < 4; q++) {
            float* d = &sH[(rg * 4 + q) * 516 + hc * 4];
            *(float4*)d = make_float4(acc[q][0] + b4.x, acc[q][1] + b4.y,
                                      acc[q][2] + b4.z, acc[q][3] + b4.w);
        }
    }
    __syncthreads();

    {
        int wid = tid >> 5, lane = tid & 31;
        float s = 0.f, ss = 0.f;
        #pragma unroll
        for (int m = 0; m < 16; m++) {
            float v = sH[wid * 516 + lane + m * 32];
            s += v; ss += v * v;
        }
        #pragma unroll
        for (int m = 16; m >= 1; m >>= 1) {
            s  += __shfl_xor_sync(0xffffffffu, s, m);
            ss += __shfl_xor_sync(0xffffffffu, ss, m);
        }
        float mu = s * (1.f / HH);
        float var = ss * (1.f / HH) - mu * mu;
        float rs = rsqrtf(var + 1e-5f);
        #pragma unroll
        for (int m = 0; m < 16; m++) {
            int h = lane + m * 32;
            float v = sH[wid * 516 + h];
            v = (v - mu) * rs * __ldg(&ng[h]) + __ldg(&nbt[h]);
            sH[wid * 516 + h] = fmaxf(v, 0.f);
        }
    }
    __syncthreads();

    float acc2[8][3];
    #pragma unroll
    for (int r = 0; r < 8; r++)
        #pragma unroll
        for (int k = 0; k < 3; k++) acc2[r][k] = 0.f;

    #pragma unroll 2
    for (int h = 0; h < HH; h++) {
        float w0 = __ldg(&nw2[(size_t)h * DD + tid]);
        float w1 = __ldg(&nw2[(size_t)h * DD + tid + 256]);
        float w2 = __ldg(&nw2[(size_t)h * DD + tid + 512]);
        #pragma unroll
        for (int r = 0; r < 8; r++) {
            float a = sH[r * 516 + h];
            acc2[r][0] += a * w0; acc2[r][1] += a * w1; acc2[r][2] += a * w2;
        }
    }
    #pragma unroll
    for (int r = 0; r < 8; r++) {
        int g = r0 + r;
        #pragma unroll
        for (int k = 0; k < 3; k++) {
            int d = tid + k * 256;
            out_nodes[(size_t)g * DD + d] =
                __ldg(&nodes[(size_t)g * DD + d]) + acc2[r][k] + __ldg(&nb2[d]);
        }
    }
}

// ============================================================
// Kernel 4: single-pass fp16 fused edge path, 2 CTAs/SM.
// CTA = (b,i) x 64-j tile.  GEMM1 -> he fp16 tile (+stats).
// GEMM2 applies LN in fragment domain on the A operand.
// ============================================================
// float region (float indices)
#define F_NI   0
#define F_EG   512
#define F_EBT  1024
#define F_NJ   1536                  // [64][68], reused as output bounce
#define F_SUM  5888
#define F_SQ   5952
#define F_MU   6016
#define F_RS   6080
// half region (half indices; base = float idx 6144)
#define H_E    12288                 // [64][72]
#define H_W    16896                 // [64][72]  (W1 then W2 chunks)
#define H_HE   21504                 // [64][520]
#define EDGE_SMEM_BYTES ((21504 + 64 * 520) * 2)

// warp-tile m16 x n32 GEMM over one k=64 chunk (A,B stride 72)
__device__ __forceinline__ void gemm_16x32(uint32_t sb, int offA, int offB,
                                           int mt, int nt, int lane, float c[4][4]) {
    const int arow = lane & 15, ak8 = (lane >> 4) << 3;
    const int bn = (lane & 7) + ((lane >> 4) << 3);
    const int bk8 = ((lane >> 3) & 1) << 3;
    #pragma unroll
    for (int ks = 0; ks < 4; ks++) {
        int k0 = ks * 16;
        uint32_t a0, a1, a2, a3, p0, p1, p2, p3, q0, q1, q2, q3;
        ldm_x4(a0, a1, a2, a3, sb + 2 * (offA + (mt + arow) * 72 + k0 + ak8));
        ldm_x4(p0, p1, p2, p3, sb + 2 * (offB + (nt + bn) * 72 + k0 + bk8));
        ldm_x4(q0, q1, q2, q3, sb + 2 * (offB + (nt + 16 + bn) * 72 + k0 + bk8));
        mma_f16(c[0], a0, a1, a2, a3, p0, p1);
        mma_f16(c[1], a0, a1, a2, a3, p2, p3);
        mma_f16(c[2], a0, a1, a2, a3, q0, q1);
        mma_f16(c[3], a0, a1, a2, a3, q2, q3);
    }
}

__global__ __launch_bounds__(256, 2) void k_edge_mma(
    const float* __restrict__ edges,
    const float* __restrict__ ew1,   // We = first 64 rows of ew1
    const float* __restrict__ eg,
    const float* __restrict__ ebt,
    const float* __restrict__ ew2,
    const float* __restrict__ eb2,
    float* __restrict__ out_edges)
{
    extern __shared__ float smem[];
    __half* sh = (__half*)smem;
    const uint32_t sb = (uint32_t)__cvta_generic_to_shared(smem);
    const int tid = threadIdx.x;
    const int w = tid >> 5, lane = tid & 31;
    const int g = lane >> 2, tig = lane & 3;
    const int mt = (w & 3) * 16, ntw = (w >> 2) * 32;
    const int b = blockIdx.z, i = blockIdx.y;
    const int j0 = blockIdx.x * JT;

    // ---- stage edge tile [64][72] fp16 ----
    const float* etile = edges + ((size_t)((size_t)b * NN + i) * NN + j0) * EE;
    #pragma unroll
    for (int t = 0; t < 4; t++) {
        int q = t * 256 + tid;               // 1024 quads
        int j = q >> 4, k0 = (q & 15) * 4;
        float4 v = __ldg((const float4*)&etile[j * EE + k0]);
        *(uint2*)&sh[H_E + j * 72 + k0] = make_uint2(pack2(v.x, v.y), pack2(v.z, v.w));
    }
    // ---- NI/eg/ebt caches + zero stats ----
    const float* nip = g_NI + (size_t)((size_t)b * NN + i) * HH;
    #pragma unroll
    for (int t = 0; t < 2; t++) {
        int c = t * 256 + tid;
        smem[F_NI + c]  = __ldg(&nip[c]);
        smem[F_EG + c]  = __ldg(&eg[c]);
        smem[F_EBT + c] = __ldg(&ebt[c]);
    }
    if (tid < 64) { smem[F_SUM + tid] = 0.f; smem[F_SQ + tid] = 0.f; }

    const float* njb = g_NJ + (size_t)((size_t)b * NN + j0) * HH;

    // ================= GEMM1: he = E@We + NI + NJ, stats, fp16 tile ========
    float rsum[2] = {0.f, 0.f}, rsq[2] = {0.f, 0.f};
    for (int ch = 0; ch < 8; ch++) {
        __syncthreads();                     // H_W / F_NJ free
        // stage W1[n][k] = ew1[k][ch*64+n]  (coalesced over n)
        #pragma unroll
        for (int t = 0; t < 4; t++) {
            int q = t * 256 + tid;
            int n = q & 63, k0 = (q >> 6) * 4;
            const float* p = ew1 + (size_t)k0 * HH + ch * 64 + n;
            *(uint2*)&sh[H_W + n * 72 + k0] =
                make_uint2(pack2(__ldg(p), __ldg(p + HH)),
                           pack2(__ldg(p + 2 * HH), __ldg(p + 3 * HH)));
        }
        // stage NJ chunk [64][68] (coalesced float4)
        #pragma unroll
        for (int t = 0; t < 4; t++) {
            int q = t * 256 + tid;
            int r = q >> 4, c4 = (q & 15) * 4;
            float4 v = __ldg((const float4*)&njb[(size_t)r * HH + ch * 64 + c4]);
            *(float4*)&smem[F_NJ + r * 68 + c4] = v;
        }
        __syncthreads();

        float c[4][4];
        #pragma unroll
        for (int nj = 0; nj < 4; nj++)
            #pragma unroll
            for (int x = 0; x < 4; x++) c[nj][x] = 0.f;
        gemm_16x32(sb, H_E, H_W, mt, ntw, lane, c);

        // epilogue: += NI + NJ, stats, store fp16
        #pragma unroll
        for (int nj = 0; nj < 4; nj++) {
            int cl = ntw + nj * 8 + 2 * tig;
            float2 ni = *(float2*)&smem[F_NI + ch * 64 + cl];
            #pragma unroll
            for (int rr = 0; rr < 2; rr++) {
                int row = mt + g + rr * 8;
                float2 njv = *(float2*)&smem[F_NJ + row * 68 + cl];
                float v0 = c[nj][rr * 2 + 0] + ni.x + njv.x;
                float v1 = c[nj][rr * 2 + 1] + ni.y + njv.y;
                rsum[rr] += v0 + v1;
                rsq[rr]  += v0 * v0 + v1 * v1;
                *(uint32_t*)&sh[H_HE + row * 520 + ch * 64 + cl] = pack2(v0, v1);
            }
        }
    }

    // ---- LN stats reduction ----
    #pragma unroll
    for (int rr = 0; rr < 2; rr++) {
        float s = rsum[rr], q2 = rsq[rr];
        s  += __shfl_xor_sync(0xffffffffu, s, 1);
        s  += __shfl_xor_sync(0xffffffffu, s, 2);
        q2 += __shfl_xor_sync(0xffffffffu, q2, 1);
        q2 += __shfl_xor_sync(0xffffffffu, q2, 2);
        if (tig == 0) {
            atomicAdd(&smem[F_SUM + mt + g + rr * 8], s);
            atomicAdd(&smem[F_SQ  + mt + g + rr * 8], q2);
        }
    }
    __syncthreads();
    if (tid < 64) {
        float mu = smem[F_SUM + tid] * (1.f / HH);
        float var = smem[F_SQ + tid] * (1.f / HH) - mu * mu;
        smem[F_MU + tid] = mu;
        smem[F_RS + tid] = rsqrtf(var + 1e-5f);
    }
    __syncthreads();
    const float mu0 = smem[F_MU + mt + g],     rs0 = smem[F_RS + mt + g];
    const float mu1 = smem[F_MU + mt + g + 8], rs1 = smem[F_RS + mt + g + 8];

    // ================= GEMM2: out = LN_relu(he) @ ew2 ======================
    float c2[4][4];
    #pragma unroll
    for (int nj = 0; nj < 4; nj++)
        #pragma unroll
        for (int x = 0; x < 4; x++) c2[nj][x] = 0.f;

    const int arow = lane & 15, ak8 = (lane >> 4) << 3;
    const int bn = (lane & 7) + ((lane >> 4) << 3);
    const int bk8 = ((lane >> 3) & 1) << 3;

    for (int kc = 0; kc < 8; kc++) {
        __syncthreads();                     // H_W free
        // stage W2[n=e][k=h] = ew2[kc*64+k][n]  (coalesced over n)
        #pragma unroll
        for (int t = 0; t < 4; t++) {
            int q = t * 256 + tid;
            int n = q & 63, k0 = (q >> 6) * 4;
            const float* p = ew2 + (size_t)(kc * 64 + k0) * EE + n;
            *(uint2*)&sh[H_W + n * 72 + k0] =
                make_uint2(pack2(__ldg(p), __ldg(p + EE)),
                           pack2(__ldg(p + 2 * EE), __ldg(p + 3 * EE)));
        }
        __syncthreads();

        #pragma unroll
        for (int ks = 0; ks < 4; ks++) {
            int k0 = ks * 16;
            uint32_t a0, a1, a2, a3, p0, p1, p2, p3, q0, q1, q2, q3;
            ldm_x4(a0, a1, a2, a3,
                   sb + 2 * (H_HE + (mt + arow) * 520 + kc * 64 + k0 + ak8));
            // frag-domain LN + relu on A:
            // reg cols: a0/a1 -> cb, a2/a3 -> cb+8; rows: a0/a2 -> r0, a1/a3 -> r1
            {
                int cb = kc * 64 + k0 + 2 * tig;
                float2 eg0 = *(float2*)&smem[F_EG + cb];
                float2 eg8 = *(float2*)&smem[F_EG + cb + 8];
                float2 eb0 = *(float2*)&smem[F_EBT + cb];
                float2 eb8 = *(float2*)&smem[F_EBT + cb + 8];
                float a00 = rs0 * eg0.x, a01 = rs0 * eg0.y;
                float a10 = rs1 * eg0.x, a11 = rs1 * eg0.y;
                float a08 = rs0 * eg8.x, a09 = rs0 * eg8.y;
                float a18 = rs1 * eg8.x, a19 = rs1 * eg8.y;
                float2 v;
                v = h2f(a0);
                a0 = pack2(fmaxf(v.x * a00 + (eb0.x - mu0 * a00), 0.f),
                           fmaxf(v.y * a01 + (eb0.y - mu0 * a01), 0.f));
                v = h2f(a1);
                a1 = pack2(fmaxf(v.x * a10 + (eb0.x - mu1 * a10), 0.f),
                           fmaxf(v.y * a11 + (eb0.y - mu1 * a11), 0.f));
                v = h2f(a2);
                a2 = pack2(fmaxf(v.x * a08 + (eb8.x - mu0 * a08), 0.f),
                           fmaxf(v.y * a09 + (eb8.y - mu0 * a09), 0.f));
                v = h2f(a3);
                a3 = pack2(fmaxf(v.x * a18 + (eb8.x - mu1 * a18), 0.f),
                           fmaxf(v.y * a19 + (eb8.y - mu1 * a19), 0.f));
            }
            ldm_x4(p0, p1, p2, p3, sb + 2 * (H_W + (ntw + bn) * 72 + k0 + bk8));
            ldm_x4(q0, q1, q2, q3, sb + 2 * (H_W + (ntw + 16 + bn) * 72 + k0 + bk8));
            mma_f16(c2[0], a0, a1, a2, a3, p0, p1);
            mma_f16(c2[1], a0, a1, a2, a3, p2, p3);
            mma_f16(c2[2], a0, a1, a2, a3, q0, q1);
            mma_f16(c2[3], a0, a1, a2, a3, q2, q3);
        }
    }

    // ---- epilogue: bounce via smem, coalesced residual + store ----
    __syncthreads();                          // F_NJ free for bounce
    #pragma unroll
    for (int nj = 0; nj < 4; nj++) {
        int cl = ntw + nj * 8 + 2 * tig;
        #pragma unroll
        for (int rr = 0; rr < 2; rr++) {
            int row = mt + g + rr * 8;
            *(float2*)&smem[F_NJ + row * 68 + cl] =
                make_float2(c2[nj][rr * 2 + 0], c2[nj][rr * 2 + 1]);
        }
    }
    __syncthreads();
    #pragma unroll
    for (int t = 0; t < 4; t++) {
        int q = t * 256 + tid;
        int r = q >> 4, c4 = (q & 15) * 4;
        float4 m = *(float4*)&smem[F_NJ + r * 68 + c4];
        size_t gbase = ((size_t)((size_t)b * NN + i) * NN + j0 + r) * EE + c4;
        float4 e4 = __ldg((const float4*)&edges[gbase]);
        float4 b4 = __ldg((const float4*)&eb2[c4]);
        float4 o = make_float4(e4.x + m.x + b4.x, e4.y + m.y + b4.y,
                               e4.z + m.z + b4.z, e4.w + m.w + b4.w);
        *(float4*)&out_edges[gbase] = o;
    }
}

// ============================================================
extern "C" void kernel_launch(void* const* d_in, const int* in_sizes, int n_in,
                              void* d_out, int out_size)
{
    const float* nodes = (const float*)d_in[0];
    const float* edges = (const float*)d_in[1];
    const float* adj   = (const float*)d_in[2];
    const float* nw1   = (const float*)d_in[3];
    const float* nb1   = (const float*)d_in[4];
    const float* ng    = (const float*)d_in[5];
    const float* nbt   = (const float*)d_in[6];
    const float* nw2   = (const float*)d_in[7];
    const float* nb2   = (const float*)d_in[8];
    const float* ew1   = (const float*)d_in[9];
    const float* eb1   = (const float*)d_in[10];
    const float* eg    = (const float*)d_in[11];
    const float* ebt   = (const float*)d_in[12];
    const float* ew2   = (const float*)d_in[13];
    const float* eb2   = (const float*)d_in[14];

    float* out_nodes = (float*)d_out;
    float* out_edges = out_nodes + (size_t)BB * NN * DD;

    cudaFuncSetAttribute(k_edge_mma, cudaFuncAttributeMaxDynamicSharedMemorySize,
                         EDGE_SMEM_BYTES);

    k_agg <<<BB * NN, 256>>>(edges, adj);
    k_ninj<<<dim3(2, 48, 2), 256>>>(nodes, ew1, eb1);
    k_node<<<96, 256>>>(nodes, nw1, nb1, ng, nbt, nw2, nb2, out_nodes);
    k_edge_mma<<<dim3(NN / JT, NN, BB), 256, EDGE_SMEM_BYTES>>>(edges, ew1, eg, ebt, ew2, eb2, out_edges);
}

// round 9
// speedup vs baseline: 2.3041x; 1.0533x over previous
#include <cuda_runtime.h>
#include <cuda_fp16.h>
#include <cstdint>

#define BB 2
#define NN 384
#define DD 768
#define EE 64
#define HH 512
#define JT 64

// -------- scratch (no allocations allowed) --------
__device__ float  g_agg[BB * NN * EE];     //  192 KB
__device__ float  g_NI [BB * NN * HH];     // 1.5 MB  (nodes@Wi + eb1)
__device__ __half g_NJh[BB * NN * HH];     // 768 KB  (nodes@Wj, fp16)

__device__ __forceinline__ uint32_t pack2(float a, float b) {
    __half2 h = __floats2half2_rn(a, b);
    return *reinterpret_cast<uint32_t*>(&h);
}
__device__ __forceinline__ float2 h2f(uint32_t u) {
    return __half22float2(*reinterpret_cast<__half2*>(&u));
}
__device__ __forceinline__ void ldm_x4(uint32_t& r0, uint32_t& r1,
                                       uint32_t& r2, uint32_t& r3, uint32_t addr) {
    asm volatile("ldmatrix.sync.aligned.m8n8.x4.shared.b16 {%0,%1,%2,%3}, [%4];"
                 : "=r"(r0), "=r"(r1), "=r"(r2), "=r"(r3) : "r"(addr));
}
__device__ __forceinline__ void mma_f16(float c[4],
                                        uint32_t a0, uint32_t a1, uint32_t a2, uint32_t a3,
                                        uint32_t b0, uint32_t b1) {
    asm volatile("mma.sync.aligned.m16n8k16.row.col.f32.f16.f16.f32 "
        "{%0,%1,%2,%3}, {%4,%5,%6,%7}, {%8,%9}, {%0,%1,%2,%3};"
        : "+f"(c[0]), "+f"(c[1]), "+f"(c[2]), "+f"(c[3])
        : "r"(a0), "r"(a1), "r"(a2), "r"(a3), "r"(b0), "r"(b1));
}

// ============================================================
// Kernel 1: agg[b,i,e] = sum_j edges[b,i,j,e] * adj[b,i,j]
// ============================================================
__global__ __launch_bounds__(256) void k_agg(const float* __restrict__ edges,
                                             const float* __restrict__ adj)
{
    int bi = blockIdx.x;
    int e  = threadIdx.x & 63;
    int jg = threadIdx.x >> 6;
    const float* erow = edges + (size_t)bi * NN * EE;
    const float* arow = adj   + (size_t)bi * NN;
    float acc = 0.f;
    for (int j = jg; j < NN; j += 16) {           // 4x unrolled for MLP
        float a0 = arow[j], a1 = arow[j + 4], a2 = arow[j + 8], a3 = arow[j + 12];
        if (a0 != 0.f) acc += erow[(size_t)j * EE + e] * a0;
        if (a1 != 0.f) acc += erow[(size_t)(j + 4) * EE + e] * a1;
        if (a2 != 0.f) acc += erow[(size_t)(j + 8) * EE + e] * a2;
        if (a3 != 0.f) acc += erow[(size_t)(j + 12) * EE + e] * a3;
    }
    __shared__ float red[4][64];
    red[jg][e] = acc;
    __syncthreads();
    if (jg == 0)
        g_agg[(size_t)bi * EE + e] = red[0][e] + red[1][e] + red[2][e] + red[3][e];
}

// ============================================================
// Kernel 2: NI = nodes @ Wi + eb1 (fp32) ; NJ = nodes @ Wj (fp16)
// ============================================================
__global__ __launch_bounds__(256) void k_ninj(const float* __restrict__ nodes,
                                              const float* __restrict__ ew1,
                                              const float* __restrict__ eb1)
{
    __shared__ float sA[16 * DD];
    const int tid   = threadIdx.x;
    const int cbase = blockIdx.x * 256;
    const int r0    = blockIdx.y * 16;
    const int z     = blockIdx.z;
    const int rg    = tid >> 6;
    const int cc    = tid & 63;

    #pragma unroll
    for (int t = 0; t < 48; t++) {
        int lin = t * 256 + tid;
        sA[lin] = nodes[(size_t)r0 * DD + lin];
    }
    __syncthreads();

    const int woff = EE + z * DD;
    float acc[4][4];
    #pragma unroll
    for (int q = 0; q < 4; q++)
        #pragma unroll
        for (int x = 0; x < 4; x++) acc[q][x] = 0.f;

    #pragma unroll 4
    for (int k = 0; k < DD; k++) {
        float4 w = __ldg((const float4*)&ew1[(size_t)(woff + k) * HH + cbase + cc * 4]);
        #pragma unroll
        for (int q = 0; q < 4; q++) {
            float a = sA[(rg * 4 + q) * DD + k];
            acc[q][0] += a * w.x; acc[q][1] += a * w.y;
            acc[q][2] += a * w.z; acc[q][3] += a * w.w;
        }
    }

    if (z == 0) {
        float4 bb = __ldg((const float4*)&eb1[cbase + cc * 4]);
        #pragma unroll
        for (int q = 0; q < 4; q++) {
            int g = r0 + rg * 4 + q;
            float4 o = make_float4(acc[q][0] + bb.x, acc[q][1] + bb.y,
                                   acc[q][2] + bb.z, acc[q][3] + bb.w);
            *(float4*)&g_NI[(size_t)g * HH + cbase + cc * 4] = o;
        }
    } else {
        #pragma unroll
        for (int q = 0; q < 4; q++) {
            int g = r0 + rg * 4 + q;
            *(uint2*)&g_NJh[(size_t)g * HH + cbase + cc * 4] =
                make_uint2(pack2(acc[q][0], acc[q][1]), pack2(acc[q][2], acc[q][3]));
        }
    }
}

// ============================================================
// Kernel 3: node path (exact fp32)
// ============================================================
#define MK (EE + DD)
__global__ __launch_bounds__(256) void k_node(const float* __restrict__ nodes,
                                              const float* __restrict__ nw1,
                                              const float* __restrict__ nb1,
                                              const float* __restrict__ ng,
                                              const float* __restrict__ nbt,
                                              const float* __restrict__ nw2,
                                              const float* __restrict__ nb2,
                                              float* __restrict__ out_nodes)
{
    __shared__ float sM[8 * MK];
    __shared__ float sH[8 * 516];
    const int tid = threadIdx.x;
    const int r0  = blockIdx.x * 8;

    for (int t = 0; t < 26; t++) {
        int lin = t * 256 + tid;
        int r = lin / MK, c = lin - r * MK;
        int g = r0 + r;
        float v = (c < EE) ? g_agg[(size_t)g * EE + c]
                           : nodes[(size_t)g * DD + (c - EE)] * (float)NN;
        sM[lin] = v;
    }
    __syncthreads();

    const int rg = tid >> 7;
    const int hc = tid & 127;
    float acc[4][4];
    #pragma unroll
    for (int q = 0; q < 4; q++)
        #pragma unroll
        for (int x = 0; x < 4; x++) acc[q][x] = 0.f;

    #pragma unroll 4
    for (int k = 0; k < MK; k++) {
        float4 w = __ldg((const float4*)&nw1[(size_t)k * HH + hc * 4]);
        #pragma unroll
        for (int q = 0; q < 4; q++) {
            float a = sM[(rg * 4 + q) * MK + k];
            acc[q][0] += a * w.x; acc[q][1] += a * w.y;
            acc[q][2] += a * w.z; acc[q][3] += a * w.w;
        }
    }
    {
        float4 b4 = __ldg((const float4*)&nb1[hc * 4]);
        #pragma unroll
        for (int q = 0; q < 4; q++) {
            float* d = &sH[(rg * 4 + q) * 516 + hc * 4];
            *(float4*)d = make_float4(acc[q][0] + b4.x, acc[q][1] + b4.y,
                                      acc[q][2] + b4.z, acc[q][3] + b4.w);
        }
    }
    __syncthreads();

    {
        int wid = tid >> 5, lane = tid & 31;
        float s = 0.f, ss = 0.f;
        #pragma unroll
        for (int m = 0; m < 16; m++) {
            float v = sH[wid * 516 + lane + m * 32];
            s += v; ss += v * v;
        }
        #pragma unroll
        for (int m = 16; m >= 1; m >>= 1) {
            s  += __shfl_xor_sync(0xffffffffu, s, m);
            ss += __shfl_xor_sync(0xffffffffu, ss, m);
        }
        float mu = s * (1.f / HH);
        float var = ss * (1.f / HH) - mu * mu;
        float rs = rsqrtf(var + 1e-5f);
        #pragma unroll
        for (int m = 0; m < 16; m++) {
            int h = lane + m * 32;
            float v = sH[wid * 516 + h];
            v = (v - mu) * rs * __ldg(&ng[h]) + __ldg(&nbt[h]);
            sH[wid * 516 + h] = fmaxf(v, 0.f);
        }
    }
    __syncthreads();

    float acc2[8][3];
    #pragma unroll
    for (int r = 0; r < 8; r++)
        #pragma unroll
        for (int k = 0; k < 3; k++) acc2[r][k] = 0.f;

    #pragma unroll 2
    for (int h = 0; h < HH; h++) {
        float w0 = __ldg(&nw2[(size_t)h * DD + tid]);
        float w1 = __ldg(&nw2[(size_t)h * DD + tid + 256]);
        float w2 = __ldg(&nw2[(size_t)h * DD + tid + 512]);
        #pragma unroll
        for (int r = 0; r < 8; r++) {
            float a = sH[r * 516 + h];
            acc2[r][0] += a * w0; acc2[r][1] += a * w1; acc2[r][2] += a * w2;
        }
    }
    #pragma unroll
    for (int r = 0; r < 8; r++) {
        int g = r0 + r;
        #pragma unroll
        for (int k = 0; k < 3; k++) {
            int d = tid + k * 256;
            out_nodes[(size_t)g * DD + d] =
                __ldg(&nodes[(size_t)g * DD + d]) + acc2[r][k] + __ldg(&nb2[d]);
        }
    }
}

// ============================================================
// Kernel 4: single-pass fp16 fused edge path, 2 CTAs/SM,
// register-prefetched staging + separated coalesced LN pass.
// ============================================================
// float region (float indices)
#define F_NI   0          // [512]
#define F_SUM  512        // [64]
#define F_SQ   576        // [64]
#define F_MU   640        // [64]
#define F_RS   704        // [64]  -> ends 768
#define F_OUT  768        // [64][68] floats (aliases dead half region)
// half region (half indices into sh)
#define H_NJ   1536                  // [64][72]
#define H_E    (H_NJ + 64 * 72)      // [64][72]
#define H_W    (H_E + 64 * 72)       // [64][72] (W1 / W2 chunks)
#define H_HE   (H_W + 64 * 72)       // [64][520]
#define EDGE_SMEM_BYTES ((H_HE + 64 * 520) * 2)

// warp-tile m16 x n32 GEMM over one k=64 chunk; B stride 72
__device__ __forceinline__ void gemm_16x32(uint32_t sb, int offA, int strideA, int colA,
                                           int offB, int mt, int nt, int lane,
                                           float c[4][4]) {
    const int arow = lane & 15, ak8 = (lane >> 4) << 3;
    const int bn = (lane & 7) + ((lane >> 4) << 3);
    const int bk8 = ((lane >> 3) & 1) << 3;
    #pragma unroll
    for (int ks = 0; ks < 4; ks++) {
        int k0 = ks * 16;
        uint32_t a0, a1, a2, a3, p0, p1, p2, p3, q0, q1, q2, q3;
        ldm_x4(a0, a1, a2, a3, sb + 2 * (offA + (mt + arow) * strideA + colA + k0 + ak8));
        ldm_x4(p0, p1, p2, p3, sb + 2 * (offB + (nt + bn) * 72 + k0 + bk8));
        ldm_x4(q0, q1, q2, q3, sb + 2 * (offB + (nt + 16 + bn) * 72 + k0 + bk8));
        mma_f16(c[0], a0, a1, a2, a3, p0, p1);
        mma_f16(c[1], a0, a1, a2, a3, p2, p3);
        mma_f16(c[2], a0, a1, a2, a3, q0, q1);
        mma_f16(c[3], a0, a1, a2, a3, q2, q3);
    }
}

__global__ __launch_bounds__(256, 2) void k_edge_mma(
    const float* __restrict__ edges,
    const float* __restrict__ ew1,   // We = first 64 rows of ew1
    const float* __restrict__ eg,
    const float* __restrict__ ebt,
    const float* __restrict__ ew2,
    const float* __restrict__ eb2,
    float* __restrict__ out_edges)
{
    extern __shared__ float smem[];
    __half* sh = (__half*)smem;
    const uint32_t sb = (uint32_t)__cvta_generic_to_shared(smem);
    const int tid = threadIdx.x;
    const int w = tid >> 5, lane = tid & 31;
    const int g = lane >> 2, tig = lane & 3;
    const int mt = (w & 3) * 16, ntw = (w >> 2) * 32;
    const int b = blockIdx.z, i = blockIdx.y;
    const int j0 = blockIdx.x * JT;

    uint2 wreg[4];
    uint4 njreg[2];

    // ---- stage edge tile [64][72] fp16 ----
    const float* etile = edges + ((size_t)((size_t)b * NN + i) * NN + j0) * EE;
    #pragma unroll
    for (int t = 0; t < 4; t++) {
        int q = t * 256 + tid;
        int j = q >> 4, k0 = (q & 15) * 4;
        float4 v = __ldg((const float4*)&etile[j * EE + k0]);
        *(uint2*)&sh[H_E + j * 72 + k0] = make_uint2(pack2(v.x, v.y), pack2(v.z, v.w));
    }
    // ---- NI cache + zero stats ----
    const float* nip = g_NI + (size_t)((size_t)b * NN + i) * HH;
    smem[F_NI + tid] = __ldg(&nip[tid]);
    smem[F_NI + 256 + tid] = __ldg(&nip[256 + tid]);
    if (tid < 64) { smem[F_SUM + tid] = 0.f; smem[F_SQ + tid] = 0.f; }

    const __half* njb = g_NJh + (size_t)((size_t)b * NN + j0) * HH;

    // prefetch chunk 0 of W1 + NJ into registers
    #pragma unroll
    for (int t = 0; t < 4; t++) {
        int q = t * 256 + tid;
        int n = q & 63, k0 = (q >> 6) * 4;
        const float* p = ew1 + (size_t)k0 * HH + n;
        wreg[t] = make_uint2(pack2(__ldg(p), __ldg(p + HH)),
                             pack2(__ldg(p + 2 * HH), __ldg(p + 3 * HH)));
    }
    #pragma unroll
    for (int t = 0; t < 2; t++) {
        int q = t * 256 + tid;
        int r = q >> 3, c0 = (q & 7) * 8;
        njreg[t] = *(const uint4*)&njb[(size_t)r * HH + c0];
    }

    // ================= GEMM1: he = E@We + NI + NJ, stats ===================
    float rsum[2] = {0.f, 0.f}, rsq[2] = {0.f, 0.f};
    for (int ch = 0; ch < 8; ch++) {
        // STS prefetched W1 + NJ
        #pragma unroll
        for (int t = 0; t < 4; t++) {
            int q = t * 256 + tid;
            int n = q & 63, k0 = (q >> 6) * 4;
            *(uint2*)&sh[H_W + n * 72 + k0] = wreg[t];
        }
        #pragma unroll
        for (int t = 0; t < 2; t++) {
            int q = t * 256 + tid;
            int r = q >> 3, c0 = (q & 7) * 8;
            *(uint4*)&sh[H_NJ + r * 72 + c0] = njreg[t];
        }
        __syncthreads();
        // prefetch next chunk
        if (ch < 7) {
            #pragma unroll
            for (int t = 0; t < 4; t++) {
                int q = t * 256 + tid;
                int n = q & 63, k0 = (q >> 6) * 4;
                const float* p = ew1 + (size_t)k0 * HH + (ch + 1) * 64 + n;
                wreg[t] = make_uint2(pack2(__ldg(p), __ldg(p + HH)),
                                     pack2(__ldg(p + 2 * HH), __ldg(p + 3 * HH)));
            }
            #pragma unroll
            for (int t = 0; t < 2; t++) {
                int q = t * 256 + tid;
                int r = q >> 3, c0 = (q & 7) * 8;
                njreg[t] = *(const uint4*)&njb[(size_t)r * HH + (ch + 1) * 64 + c0];
            }
        }

        float c[4][4];
        #pragma unroll
        for (int nj = 0; nj < 4; nj++)
            #pragma unroll
            for (int x = 0; x < 4; x++) c[nj][x] = 0.f;
        gemm_16x32(sb, H_E, 72, 0, H_W, mt, ntw, lane, c);

        // epilogue: += NI + NJ, stats, store fp16 raw he
        #pragma unroll
        for (int nj = 0; nj < 4; nj++) {
            int cl = ntw + nj * 8 + 2 * tig;
            float2 ni = *(float2*)&smem[F_NI + ch * 64 + cl];
            #pragma unroll
            for (int rr = 0; rr < 2; rr++) {
                int row = mt + g + rr * 8;
                float2 njv = h2f(*(uint32_t*)&sh[H_NJ + row * 72 + cl]);
                float v0 = c[nj][rr * 2 + 0] + ni.x + njv.x;
                float v1 = c[nj][rr * 2 + 1] + ni.y + njv.y;
                rsum[rr] += v0 + v1;
                rsq[rr]  += v0 * v0 + v1 * v1;
                *(uint32_t*)&sh[H_HE + row * 520 + ch * 64 + cl] = pack2(v0, v1);
            }
        }
        __syncthreads();
    }

    // ---- LN stats reduction ----
    #pragma unroll
    for (int rr = 0; rr < 2; rr++) {
        float s = rsum[rr], q2 = rsq[rr];
        s  += __shfl_xor_sync(0xffffffffu, s, 1);
        s  += __shfl_xor_sync(0xffffffffu, s, 2);
        q2 += __shfl_xor_sync(0xffffffffu, q2, 1);
        q2 += __shfl_xor_sync(0xffffffffu, q2, 2);
        if (tig == 0) {
            atomicAdd(&smem[F_SUM + mt + g + rr * 8], s);
            atomicAdd(&smem[F_SQ  + mt + g + rr * 8], q2);
        }
    }
    __syncthreads();
    if (tid < 64) {
        float mu = smem[F_SUM + tid] * (1.f / HH);
        float var = smem[F_SQ + tid] * (1.f / HH) - mu * mu;
        smem[F_MU + tid] = mu;
        smem[F_RS + tid] = rsqrtf(var + 1e-5f);
    }
    // prefetch W2 chunk 0 (hides behind LN pass)
    #pragma unroll
    for (int t = 0; t < 4; t++) {
        int q = t * 256 + tid;
        int n = q & 63, k0 = (q >> 6) * 4;
        const float* p = ew2 + (size_t)k0 * EE + n;
        wreg[t] = make_uint2(pack2(__ldg(p), __ldg(p + EE)),
                             pack2(__ldg(p + 2 * EE), __ldg(p + 3 * EE)));
    }
    __syncthreads();

    // ---- coalesced in-place LN + relu pass over he ----
    {
        int wr = w * 8;                       // this warp's 8 rows
        #pragma unroll
        for (int pass = 0; pass < 2; pass++) {
            int cb = pass * 256 + lane * 8;   // column base (halves)
            float4 g0 = __ldg((const float4*)&eg[cb]);
            float4 g1 = __ldg((const float4*)&eg[cb + 4]);
            float4 t0 = __ldg((const float4*)&ebt[cb]);
            float4 t1 = __ldg((const float4*)&ebt[cb + 4]);
            #pragma unroll
            for (int r = 0; r < 8; r++) {
                int row = wr + r;
                float mu = smem[F_MU + row], rs = smem[F_RS + row];
                uint4 u = *(uint4*)&sh[H_HE + row * 520 + cb];
                float2 v;
                v = h2f(u.x);
                u.x = pack2(fmaxf((v.x - mu) * rs * g0.x + t0.x, 0.f),
                            fmaxf((v.y - mu) * rs * g0.y + t0.y, 0.f));
                v = h2f(u.y);
                u.y = pack2(fmaxf((v.x - mu) * rs * g0.z + t0.z, 0.f),
                            fmaxf((v.y - mu) * rs * g0.w + t0.w, 0.f));
                v = h2f(u.z);
                u.z = pack2(fmaxf((v.x - mu) * rs * g1.x + t1.x, 0.f),
                            fmaxf((v.y - mu) * rs * g1.y + t1.y, 0.f));
                v = h2f(u.w);
                u.w = pack2(fmaxf((v.x - mu) * rs * g1.z + t1.z, 0.f),
                            fmaxf((v.y - mu) * rs * g1.w + t1.w, 0.f));
                *(uint4*)&sh[H_HE + row * 520 + cb] = u;
            }
        }
    }
    __syncthreads();

    // ================= GEMM2: out = ln_relu_he @ ew2 =======================
    float c2[4][4];
    #pragma unroll
    for (int nj = 0; nj < 4; nj++)
        #pragma unroll
        for (int x = 0; x < 4; x++) c2[nj][x] = 0.f;

    for (int kc = 0; kc < 8; kc++) {
        #pragma unroll
        for (int t = 0; t < 4; t++) {
            int q = t * 256 + tid;
            int n = q & 63, k0 = (q >> 6) * 4;
            *(uint2*)&sh[H_W + n * 72 + k0] = wreg[t];
        }
        __syncthreads();
        if (kc < 7) {
            #pragma unroll
            for (int t = 0; t < 4; t++) {
                int q = t * 256 + tid;
                int n = q & 63, k0 = (q >> 6) * 4;
                const float* p = ew2 + (size_t)((kc + 1) * 64 + k0) * EE + n;
                wreg[t] = make_uint2(pack2(__ldg(p), __ldg(p + EE)),
                                     pack2(__ldg(p + 2 * EE), __ldg(p + 3 * EE)));
            }
        }
        gemm_16x32(sb, H_HE, 520, kc * 64, H_W, mt, ntw, lane, c2);
        __syncthreads();
    }

    // ---- epilogue: bounce via smem, coalesced residual + store ----
    #pragma unroll
    for (int nj = 0; nj < 4; nj++) {
        int cl = ntw + nj * 8 + 2 * tig;
        #pragma unroll
        for (int rr = 0; rr < 2; rr++) {
            int row = mt + g + rr * 8;
            *(float2*)&smem[F_OUT + row * 68 + cl] =
                make_float2(c2[nj][rr * 2 + 0], c2[nj][rr * 2 + 1]);
        }
    }
    __syncthreads();
    #pragma unroll
    for (int t = 0; t < 4; t++) {
        int q = t * 256 + tid;
        int r = q >> 4, c4 = (q & 15) * 4;
        float4 m = *(float4*)&smem[F_OUT + r * 68 + c4];
        size_t gbase = ((size_t)((size_t)b * NN + i) * NN + j0 + r) * EE + c4;
        float4 e4 = __ldg((const float4*)&edges[gbase]);
        float4 b4 = __ldg((const float4*)&eb2[c4]);
        float4 o = make_float4(e4.x + m.x + b4.x, e4.y + m.y + b4.y,
                               e4.z + m.z + b4.z, e4.w + m.w + b4.w);
        *(float4*)&out_edges[gbase] = o;
    }
}

// ============================================================
extern "C" void kernel_launch(void* const* d_in, const int* in_sizes, int n_in,
                              void* d_out, int out_size)
{
    const float* nodes = (const float*)d_in[0];
    const float* edges = (const float*)d_in[1];
    const float* adj   = (const float*)d_in[2];
    const float* nw1   = (const float*)d_in[3];
    const float* nb1   = (const float*)d_in[4];
    const float* ng    = (const float*)d_in[5];
    const float* nbt   = (const float*)d_in[6];
    const float* nw2   = (const float*)d_in[7];
    const float* nb2   = (const float*)d_in[8];
    const float* ew1   = (const float*)d_in[9];
    const float* eb1   = (const float*)d_in[10];
    const float* eg    = (const float*)d_in[11];
    const float* ebt   = (const float*)d_in[12];
    const float* ew2   = (const float*)d_in[13];
    const float* eb2   = (const float*)d_in[14];

    float* out_nodes = (float*)d_out;
    float* out_edges = out_nodes + (size_t)BB * NN * DD;

    cudaFuncSetAttribute(k_edge_mma, cudaFuncAttributeMaxDynamicSharedMemorySize,
                         EDGE_SMEM_BYTES);

    k_agg <<<BB * NN, 256>>>(edges, adj);
    k_ninj<<<dim3(2, 48, 2), 256>>>(nodes, ew1, eb1);
    k_node<<<96, 256>>>(nodes, nw1, nb1, ng, nbt, nw2, nb2, out_nodes);
    k_edge_mma<<<dim3(NN / JT, NN, BB), 256, EDGE_SMEM_BYTES>>>(edges, ew1, eg, ebt, ew2, eb2, out_edges);
}

// round 10
// speedup vs baseline: 3.0230x; 1.3120x over previous
#include <cuda_runtime.h>
#include <cuda_fp16.h>
#include <cstdint>

#define BB 2
#define NN 384
#define DD 768
#define EE 64
#define HH 512
#define JT 64

// -------- scratch (no allocations allowed) --------
__device__ float  g_NI [BB * NN * HH];     // 1.5 MB  (nodes@Wi + eb1)
__device__ __half g_NJh[BB * NN * HH];     // 768 KB  (nodes@Wj, fp16)
__device__ __half g_heh[BB * NN * HH];     // 768 KB  (node-path LN'ed hidden)

__device__ __forceinline__ uint32_t pack2(float a, float b) {
    __half2 h = __floats2half2_rn(a, b);
    return *reinterpret_cast<uint32_t*>(&h);
}
__device__ __forceinline__ float2 h2f(uint32_t u) {
    return __half22float2(*reinterpret_cast<__half2*>(&u));
}
__device__ __forceinline__ void ldm_x4(uint32_t& r0, uint32_t& r1,
                                       uint32_t& r2, uint32_t& r3, uint32_t addr) {
    asm volatile("ldmatrix.sync.aligned.m8n8.x4.shared.b16 {%0,%1,%2,%3}, [%4];"
                 : "=r"(r0), "=r"(r1), "=r"(r2), "=r"(r3) : "r"(addr));
}
__device__ __forceinline__ void mma_f16(float c[4],
                                        uint32_t a0, uint32_t a1, uint32_t a2, uint32_t a3,
                                        uint32_t b0, uint32_t b1) {
    asm volatile("mma.sync.aligned.m16n8k16.row.col.f32.f16.f16.f32 "
        "{%0,%1,%2,%3}, {%4,%5,%6,%7}, {%8,%9}, {%0,%1,%2,%3};"
        : "+f"(c[0]), "+f"(c[1]), "+f"(c[2]), "+f"(c[3])
        : "r"(a0), "r"(a1), "r"(a2), "r"(a3), "r"(b0), "r"(b1));
}

// warp-tile m16 x n32 GEMM over one k=64 chunk; B stride 72 halves
__device__ __forceinline__ void gemm_16x32(uint32_t sb, int offA, int strideA, int colA,
                                           int offB, int mt, int nt, int lane,
                                           float c[4][4]) {
    const int arow = lane & 15, ak8 = (lane >> 4) << 3;
    const int bn = (lane & 7) + ((lane >> 4) << 3);
    const int bk8 = ((lane >> 3) & 1) << 3;
    #pragma unroll
    for (int ks = 0; ks < 4; ks++) {
        int k0 = ks * 16;
        uint32_t a0, a1, a2, a3, p0, p1, p2, p3, q0, q1, q2, q3;
        ldm_x4(a0, a1, a2, a3, sb + 2 * (offA + (mt + arow) * strideA + colA + k0 + ak8));
        ldm_x4(p0, p1, p2, p3, sb + 2 * (offB + (nt + bn) * 72 + k0 + bk8));
        ldm_x4(q0, q1, q2, q3, sb + 2 * (offB + (nt + 16 + bn) * 72 + k0 + bk8));
        mma_f16(c[0], a0, a1, a2, a3, p0, p1);
        mma_f16(c[1], a0, a1, a2, a3, p2, p3);
        mma_f16(c[2], a0, a1, a2, a3, q0, q1);
        mma_f16(c[3], a0, a1, a2, a3, q2, q3);
    }
}

// ============================================================
// Kernel 1: NI = nodes@Wi + eb1 (fp32 out); NJ = nodes@Wj (fp16 out)
// fp16 mma.  grid (8 col-tiles of 128, 12 row-tiles of 64).
// ============================================================
__global__ __launch_bounds__(256) void k_ninj_mma(const float* __restrict__ nodes,
                                                  const float* __restrict__ ew1,
                                                  const float* __restrict__ eb1)
{
    __shared__ __half sh[64 * 72 + 128 * 72];
    const int H_A = 0, H_B = 64 * 72;
    const uint32_t sb = (uint32_t)__cvta_generic_to_shared(sh);
    const int tid = threadIdx.x;
    const int w = tid >> 5, lane = tid & 31;
    const int g = lane >> 2, tig = lane & 3;
    const int mt = (w & 3) * 16, ntb = (w >> 2) * 64;
    const int gc = blockIdx.x * 128;
    const int r0 = blockIdx.y * 64;
    const bool is_ni = (gc < HH);
    const int woff = is_ni ? EE : (EE + DD);
    const int col0 = is_ni ? gc : (gc - HH);

    float cacc[2][4][4];
    #pragma unroll
    for (int s = 0; s < 2; s++)
        #pragma unroll
        for (int nj = 0; nj < 4; nj++)
            #pragma unroll
            for (int x = 0; x < 4; x++) cacc[s][nj][x] = 0.f;

    for (int kc = 0; kc < 12; kc++) {
        __syncthreads();
        // stage A [64 r][64 k] from nodes fp32 (coalesced float4)
        {
            int q = tid;                       // + t*256 for 4 iters
            #pragma unroll
            for (int t = 0; t < 4; t++, q += 256) {
                int r = q >> 4, k0 = (q & 15) * 4;
                float4 v = __ldg((const float4*)&nodes[(size_t)(r0 + r) * DD + kc * 64 + k0]);
                *(uint2*)&sh[H_A + r * 72 + k0] =
                    make_uint2(pack2(v.x, v.y), pack2(v.z, v.w));
            }
        }
        // stage B [128 n][64 k] = ew1[(woff+kc*64+k)*HH + col0+n]  (coalesced over n)
        {
            int q = tid;
            #pragma unroll
            for (int t = 0; t < 8; t++, q += 256) {
                int n = q & 127, k0 = (q >> 7) * 4;
                const float* p = ew1 + (size_t)(woff + kc * 64 + k0) * HH + col0 + n;
                *(uint2*)&sh[H_B + n * 72 + k0] =
                    make_uint2(pack2(__ldg(p), __ldg(p + HH)),
                               pack2(__ldg(p + 2 * HH), __ldg(p + 3 * HH)));
            }
        }
        __syncthreads();
        gemm_16x32(sb, H_A, 72, 0, H_B, mt, ntb, lane, cacc[0]);
        gemm_16x32(sb, H_A, 72, 0, H_B, mt, ntb + 32, lane, cacc[1]);
    }

    // store
    #pragma unroll
    for (int s = 0; s < 2; s++)
        #pragma unroll
        for (int nj = 0; nj < 4; nj++) {
            int coll = ntb + s * 32 + nj * 8 + 2 * tig;
            #pragma unroll
            for (int rr = 0; rr < 2; rr++) {
                int row = mt + g + rr * 8;
                float v0 = cacc[s][nj][rr * 2 + 0];
                float v1 = cacc[s][nj][rr * 2 + 1];
                if (is_ni) {
                    float2 e = __ldg((const float2*)&eb1[gc + coll]);
                    *(float2*)&g_NI[(size_t)(r0 + row) * HH + gc + coll] =
                        make_float2(v0 + e.x, v1 + e.y);
                } else {
                    *(uint32_t*)&g_NJh[(size_t)(r0 + row) * HH + col0 + coll] = pack2(v0, v1);
                }
            }
        }
}

// ============================================================
// Kernel 2: node path part 1 — agg (fused) + GEMM1 + LN -> g_heh fp16.
// grid 48 blocks x 16 rows.  he held in register fragments.
// ============================================================
#define N1_SUM 0
#define N1_SQ  16
#define N1_MU  32
#define N1_RS  48
#define N1_AGG 64                     // float [16][64] -> ends 1088
#define N1H_A  2176                   // half idx: [16][72]
#define N1H_B  (N1H_A + 16 * 72)      // [512][72]; also reused as he bounce [16][520]
#define N1_SMEM_BYTES ((N1H_B + 512 * 72) * 2)

__global__ __launch_bounds__(256) void k_node1(
    const float* __restrict__ nodes, const float* __restrict__ edges,
    const float* __restrict__ adj, const float* __restrict__ nw1,
    const float* __restrict__ nb1, const float* __restrict__ ng,
    const float* __restrict__ nbt)
{
    extern __shared__ float smem[];
    __half* sh = (__half*)smem;
    const uint32_t sb = (uint32_t)__cvta_generic_to_shared(smem);
    const int tid = threadIdx.x;
    const int w = tid >> 5, lane = tid & 31;
    const int g = lane >> 2, tig = lane & 3;
    const int r0 = blockIdx.x * 16;
    const int b = r0 / NN, i0 = r0 % NN;

    if (tid < 16) { smem[N1_SUM + tid] = 0.f; smem[N1_SQ + tid] = 0.f; }

    // ---- fused agg: rows r0..r0+15 ----
    {
        int r = tid >> 4, e4 = (tid & 15) * 4;
        const float* er = edges + (size_t)((size_t)(b * NN + i0 + r) * NN) * EE;
        const float* ar = adj + (size_t)(b * NN + i0 + r) * NN;
        float4 acc = make_float4(0.f, 0.f, 0.f, 0.f);
        for (int j = 0; j < NN; j += 4) {
            float a0 = ar[j], a1 = ar[j + 1], a2 = ar[j + 2], a3 = ar[j + 3];
            if (a0 != 0.f) { float4 v = __ldg((const float4*)&er[(size_t)j * EE + e4]);
                acc.x += v.x * a0; acc.y += v.y * a0; acc.z += v.z * a0; acc.w += v.w * a0; }
            if (a1 != 0.f) { float4 v = __ldg((const float4*)&er[(size_t)(j + 1) * EE + e4]);
                acc.x += v.x * a1; acc.y += v.y * a1; acc.z += v.z * a1; acc.w += v.w * a1; }
            if (a2 != 0.f) { float4 v = __ldg((const float4*)&er[(size_t)(j + 2) * EE + e4]);
                acc.x += v.x * a2; acc.y += v.y * a2; acc.z += v.z * a2; acc.w += v.w * a2; }
            if (a3 != 0.f) { float4 v = __ldg((const float4*)&er[(size_t)(j + 3) * EE + e4]);
                acc.x += v.x * a3; acc.y += v.y * a3; acc.z += v.z * a3; acc.w += v.w * a3; }
        }
        *(float4*)&smem[N1_AGG + r * 64 + e4] = acc;
    }
    __syncthreads();

    // ---- GEMM1: pre[16][512] = M[16][832] @ nw1, he in registers ----
    float cacc[2][4][4];
    #pragma unroll
    for (int s = 0; s < 2; s++)
        #pragma unroll
        for (int nj = 0; nj < 4; nj++)
            #pragma unroll
            for (int x = 0; x < 4; x++) cacc[s][nj][x] = 0.f;

    for (int kc = 0; kc < 13; kc++) {
        __syncthreads();
        // stage A chunk: kc==0 -> agg; else nodes * 384
        {
            int r = tid >> 4, k0 = (tid & 15) * 4;
            float4 v;
            if (kc == 0) v = *(float4*)&smem[N1_AGG + r * 64 + k0];
            else {
                v = __ldg((const float4*)&nodes[(size_t)(r0 + r) * DD + (kc - 1) * 64 + k0]);
                v.x *= (float)NN; v.y *= (float)NN; v.z *= (float)NN; v.w *= (float)NN;
            }
            *(uint2*)&sh[N1H_A + r * 72 + k0] = make_uint2(pack2(v.x, v.y), pack2(v.z, v.w));
        }
        // stage B [512 n][64 k] = nw1[(kc*64+k)*HH + n]  (coalesced over n)
        {
            int q = tid;
            for (int t = 0; t < 32; t++, q += 256) {
                int n = q & 511, k0 = (q >> 9) * 4;
                const float* p = nw1 + (size_t)(kc * 64 + k0) * HH + n;
                *(uint2*)&sh[N1H_B + n * 72 + k0] =
                    make_uint2(pack2(__ldg(p), __ldg(p + HH)),
                               pack2(__ldg(p + 2 * HH), __ldg(p + 3 * HH)));
            }
        }
        __syncthreads();
        gemm_16x32(sb, N1H_A, 72, 0, N1H_B, 0, w * 64, lane, cacc[0]);
        gemm_16x32(sb, N1H_A, 72, 0, N1H_B, 0, w * 64 + 32, lane, cacc[1]);
    }

    // ---- bias + stats ----
    float rsum[2] = {0.f, 0.f}, rsq[2] = {0.f, 0.f};
    #pragma unroll
    for (int s = 0; s < 2; s++)
        #pragma unroll
        for (int nj = 0; nj < 4; nj++) {
            int coll = w * 64 + s * 32 + nj * 8 + 2 * tig;
            float2 b1 = __ldg((const float2*)&nb1[coll]);
            #pragma unroll
            for (int rr = 0; rr < 2; rr++) {
                float v0 = cacc[s][nj][rr * 2 + 0] + b1.x;
                float v1 = cacc[s][nj][rr * 2 + 1] + b1.y;
                cacc[s][nj][rr * 2 + 0] = v0;
                cacc[s][nj][rr * 2 + 1] = v1;
                rsum[rr] += v0 + v1;
                rsq[rr]  += v0 * v0 + v1 * v1;
            }
        }
    #pragma unroll
    for (int rr = 0; rr < 2; rr++) {
        float s = rsum[rr], q2 = rsq[rr];
        s  += __shfl_xor_sync(0xffffffffu, s, 1);
        s  += __shfl_xor_sync(0xffffffffu, s, 2);
        q2 += __shfl_xor_sync(0xffffffffu, q2, 1);
        q2 += __shfl_xor_sync(0xffffffffu, q2, 2);
        if (tig == 0) {
            atomicAdd(&smem[N1_SUM + g + rr * 8], s);
            atomicAdd(&smem[N1_SQ + g + rr * 8], q2);
        }
    }
    __syncthreads();
    if (tid < 16) {
        float mu = smem[N1_SUM + tid] * (1.f / HH);
        float var = smem[N1_SQ + tid] * (1.f / HH) - mu * mu;
        smem[N1_MU + tid] = mu;
        smem[N1_RS + tid] = rsqrtf(var + 1e-5f);
    }
    __syncthreads();
    const float mu0 = smem[N1_MU + g],     rs0 = smem[N1_RS + g];
    const float mu1 = smem[N1_MU + g + 8], rs1 = smem[N1_RS + g + 8];

    // ---- LN + relu in frag domain, bounce to smem [16][520] ----
    #pragma unroll
    for (int s = 0; s < 2; s++)
        #pragma unroll
        for (int nj = 0; nj < 4; nj++) {
            int coll = w * 64 + s * 32 + nj * 8 + 2 * tig;
            float2 gg = __ldg((const float2*)&ng[coll]);
            float2 bb = __ldg((const float2*)&nbt[coll]);
            float v0 = fmaxf((cacc[s][nj][0] - mu0) * rs0 * gg.x + bb.x, 0.f);
            float v1 = fmaxf((cacc[s][nj][1] - mu0) * rs0 * gg.y + bb.y, 0.f);
            float v2 = fmaxf((cacc[s][nj][2] - mu1) * rs1 * gg.x + bb.x, 0.f);
            float v3 = fmaxf((cacc[s][nj][3] - mu1) * rs1 * gg.y + bb.y, 0.f);
            *(uint32_t*)&sh[N1H_B + g * 520 + coll]       = pack2(v0, v1);
            *(uint32_t*)&sh[N1H_B + (g + 8) * 520 + coll] = pack2(v2, v3);
        }
    __syncthreads();
    // coalesced store to g_heh
    {
        int q = tid;
        #pragma unroll
        for (int t = 0; t < 4; t++, q += 256) {
            int r = q >> 6, c0 = (q & 63) * 8;
            *(uint4*)&g_heh[(size_t)(r0 + r) * HH + c0] = *(uint4*)&sh[N1H_B + r * 520 + c0];
        }
    }
}

// ============================================================
// Kernel 3: node path part 2 — out = nodes + relu_he @ nw2 + nb2.
// grid (6 col-tiles of 128, 24 row-tiles of 32).
// ============================================================
#define N2H_HE 0                       // half [32][520]
#define N2H_B  (32 * 520)              // half [128][72]
#define N2F_OUT 12928                  // float idx: [32][132]
#define N2_SMEM_BYTES ((N2F_OUT + 32 * 132) * 4)

__global__ __launch_bounds__(256) void k_node2(
    const float* __restrict__ nodes, const float* __restrict__ nw2,
    const float* __restrict__ nb2, float* __restrict__ out_nodes)
{
    extern __shared__ float smem[];
    __half* sh = (__half*)smem;
    const uint32_t sb = (uint32_t)__cvta_generic_to_shared(smem);
    const int tid = threadIdx.x;
    const int w = tid >> 5, lane = tid & 31;
    const int g = lane >> 2, tig = lane & 3;
    const int mt = (w & 1) * 16, nt = (w >> 1) * 32;
    const int nc = blockIdx.x * 128;
    const int r0 = blockIdx.y * 32;

    // stage he [32][520]
    {
        int q = tid;
        #pragma unroll
        for (int t = 0; t < 8; t++, q += 256) {
            int r = q >> 6, c0 = (q & 63) * 8;
            *(uint4*)&sh[N2H_HE + r * 520 + c0] = *(const uint4*)&g_heh[(size_t)(r0 + r) * HH + c0];
        }
    }

    float c2[4][4];
    #pragma unroll
    for (int nj = 0; nj < 4; nj++)
        #pragma unroll
        for (int x = 0; x < 4; x++) c2[nj][x] = 0.f;

    for (int kc = 0; kc < 8; kc++) {
        __syncthreads();
        // stage B [128 n][64 k] = nw2[(kc*64+k)*DD + nc + n]
        {
            int q = tid;
            #pragma unroll
            for (int t = 0; t < 8; t++, q += 256) {
                int n = q & 127, k0 = (q >> 7) * 4;
                const float* p = nw2 + (size_t)(kc * 64 + k0) * DD + nc + n;
                *(uint2*)&sh[N2H_B + n * 72 + k0] =
                    make_uint2(pack2(__ldg(p), __ldg(p + DD)),
                               pack2(__ldg(p + 2 * DD), __ldg(p + 3 * DD)));
            }
        }
        __syncthreads();
        gemm_16x32(sb, N2H_HE, 520, kc * 64, N2H_B, mt, nt, lane, c2);
    }

    // bounce + coalesced residual store
    __syncthreads();
    #pragma unroll
    for (int nj = 0; nj < 4; nj++) {
        int coll = nt + nj * 8 + 2 * tig;
        #pragma unroll
        for (int rr = 0; rr < 2; rr++) {
            int row = mt + g + rr * 8;
            *(float2*)&smem[N2F_OUT + row * 132 + coll] =
                make_float2(c2[nj][rr * 2 + 0], c2[nj][rr * 2 + 1]);
        }
    }
    __syncthreads();
    {
        int q = tid;
        #pragma unroll
        for (int t = 0; t < 4; t++, q += 256) {
            int r = q >> 5, c4 = (q & 31) * 4;
            float4 m = *(float4*)&smem[N2F_OUT + r * 132 + c4];
            size_t gi = (size_t)(r0 + r) * DD + nc + c4;
            float4 n4 = __ldg((const float4*)&nodes[gi]);
            float4 b4 = __ldg((const float4*)&nb2[nc + c4]);
            *(float4*)&out_nodes[gi] = make_float4(n4.x + m.x + b4.x, n4.y + m.y + b4.y,
                                                   n4.z + m.z + b4.z, n4.w + m.w + b4.w);
        }
    }
}

// ============================================================
// Kernel 4: single-pass fp16 fused edge path (unchanged from R8).
// ============================================================
#define F_NI   0
#define F_SUM  512
#define F_SQ   576
#define F_MU   640
#define F_RS   704
#define F_OUT  768
#define H_NJ   1536
#define H_E    (H_NJ + 64 * 72)
#define H_W    (H_E + 64 * 72)
#define H_HE   (H_W + 64 * 72)
#define EDGE_SMEM_BYTES ((H_HE + 64 * 520) * 2)

__global__ __launch_bounds__(256, 2) void k_edge_mma(
    const float* __restrict__ edges,
    const float* __restrict__ ew1,
    const float* __restrict__ eg,
    const float* __restrict__ ebt,
    const float* __restrict__ ew2,
    const float* __restrict__ eb2,
    float* __restrict__ out_edges)
{
    extern __shared__ float smem[];
    __half* sh = (__half*)smem;
    const uint32_t sb = (uint32_t)__cvta_generic_to_shared(smem);
    const int tid = threadIdx.x;
    const int w = tid >> 5, lane = tid & 31;
    const int g = lane >> 2, tig = lane & 3;
    const int mt = (w & 3) * 16, ntw = (w >> 2) * 32;
    const int b = blockIdx.z, i = blockIdx.y;
    const int j0 = blockIdx.x * JT;

    uint2 wreg[4];
    uint4 njreg[2];

    const float* etile = edges + ((size_t)((size_t)b * NN + i) * NN + j0) * EE;
    #pragma unroll
    for (int t = 0; t < 4; t++) {
        int q = t * 256 + tid;
        int j = q >> 4, k0 = (q & 15) * 4;
        float4 v = __ldg((const float4*)&etile[j * EE + k0]);
        *(uint2*)&sh[H_E + j * 72 + k0] = make_uint2(pack2(v.x, v.y), pack2(v.z, v.w));
    }
    const float* nip = g_NI + (size_t)((size_t)b * NN + i) * HH;
    smem[F_NI + tid] = __ldg(&nip[tid]);
    smem[F_NI + 256 + tid] = __ldg(&nip[256 + tid]);
    if (tid < 64) { smem[F_SUM + tid] = 0.f; smem[F_SQ + tid] = 0.f; }

    const __half* njb = g_NJh + (size_t)((size_t)b * NN + j0) * HH;

    #pragma unroll
    for (int t = 0; t < 4; t++) {
        int q = t * 256 + tid;
        int n = q & 63, k0 = (q >> 6) * 4;
        const float* p = ew1 + (size_t)k0 * HH + n;
        wreg[t] = make_uint2(pack2(__ldg(p), __ldg(p + HH)),
                             pack2(__ldg(p + 2 * HH), __ldg(p + 3 * HH)));
    }
    #pragma unroll
    for (int t = 0; t < 2; t++) {
        int q = t * 256 + tid;
        int r = q >> 3, c0 = (q & 7) * 8;
        njreg[t] = *(const uint4*)&njb[(size_t)r * HH + c0];
    }

    float rsum[2] = {0.f, 0.f}, rsq[2] = {0.f, 0.f};
    for (int ch = 0; ch < 8; ch++) {
        #pragma unroll
        for (int t = 0; t < 4; t++) {
            int q = t * 256 + tid;
            int n = q & 63, k0 = (q >> 6) * 4;
            *(uint2*)&sh[H_W + n * 72 + k0] = wreg[t];
        }
        #pragma unroll
        for (int t = 0; t < 2; t++) {
            int q = t * 256 + tid;
            int r = q >> 3, c0 = (q & 7) * 8;
            *(uint4*)&sh[H_NJ + r * 72 + c0] = njreg[t];
        }
        __syncthreads();
        if (ch < 7) {
            #pragma unroll
            for (int t = 0; t < 4; t++) {
                int q = t * 256 + tid;
                int n = q & 63, k0 = (q >> 6) * 4;
                const float* p = ew1 + (size_t)k0 * HH + (ch + 1) * 64 + n;
                wreg[t] = make_uint2(pack2(__ldg(p), __ldg(p + HH)),
                                     pack2(__ldg(p + 2 * HH), __ldg(p + 3 * HH)));
            }
            #pragma unroll
            for (int t = 0; t < 2; t++) {
                int q = t * 256 + tid;
                int r = q >> 3, c0 = (q & 7) * 8;
                njreg[t] = *(const uint4*)&njb[(size_t)r * HH + (ch + 1) * 64 + c0];
            }
        }

        float c[4][4];
        #pragma unroll
        for (int nj = 0; nj < 4; nj++)
            #pragma unroll
            for (int x = 0; x < 4; x++) c[nj][x] = 0.f;
        gemm_16x32(sb, H_E, 72, 0, H_W, mt, ntw, lane, c);

        #pragma unroll
        for (int nj = 0; nj < 4; nj++) {
            int cl = ntw + nj * 8 + 2 * tig;
            float2 ni = *(float2*)&smem[F_NI + ch * 64 + cl];
            #pragma unroll
            for (int rr = 0; rr < 2; rr++) {
                int row = mt + g + rr * 8;
                float2 njv = h2f(*(uint32_t*)&sh[H_NJ + row * 72 + cl]);
                float v0 = c[nj][rr * 2 + 0] + ni.x + njv.x;
                float v1 = c[nj][rr * 2 + 1] + ni.y + njv.y;
                rsum[rr] += v0 + v1;
                rsq[rr]  += v0 * v0 + v1 * v1;
                *(uint32_t*)&sh[H_HE + row * 520 + ch * 64 + cl] = pack2(v0, v1);
            }
        }
        __syncthreads();
    }

    #pragma unroll
    for (int rr = 0; rr < 2; rr++) {
        float s = rsum[rr], q2 = rsq[rr];
        s  += __shfl_xor_sync(0xffffffffu, s, 1);
        s  += __shfl_xor_sync(0xffffffffu, s, 2);
        q2 += __shfl_xor_sync(0xffffffffu, q2, 1);
        q2 += __shfl_xor_sync(0xffffffffu, q2, 2);
        if (tig == 0) {
            atomicAdd(&smem[F_SUM + mt + g + rr * 8], s);
            atomicAdd(&smem[F_SQ  + mt + g + rr * 8], q2);
        }
    }
    __syncthreads();
    if (tid < 64) {
        float mu = smem[F_SUM + tid] * (1.f / HH);
        float var = smem[F_SQ + tid] * (1.f / HH) - mu * mu;
        smem[F_MU + tid] = mu;
        smem[F_RS + tid] = rsqrtf(var + 1e-5f);
    }
    #pragma unroll
    for (int t = 0; t < 4; t++) {
        int q = t * 256 + tid;
        int n = q & 63, k0 = (q >> 6) * 4;
        const float* p = ew2 + (size_t)k0 * EE + n;
        wreg[t] = make_uint2(pack2(__ldg(p), __ldg(p + EE)),
                             pack2(__ldg(p + 2 * EE), __ldg(p + 3 * EE)));
    }
    __syncthreads();

    {
        int wr = w * 8;
        #pragma unroll
        for (int pass = 0; pass < 2; pass++) {
            int cb = pass * 256 + lane * 8;
            float4 g0 = __ldg((const float4*)&eg[cb]);
            float4 g1 = __ldg((const float4*)&eg[cb + 4]);
            float4 t0 = __ldg((const float4*)&ebt[cb]);
            float4 t1 = __ldg((const float4*)&ebt[cb + 4]);
            #pragma unroll
            for (int r = 0; r < 8; r++) {
                int row = wr + r;
                float mu = smem[F_MU + row], rs = smem[F_RS + row];
                uint4 u = *(uint4*)&sh[H_HE + row * 520 + cb];
                float2 v;
                v = h2f(u.x);
                u.x = pack2(fmaxf((v.x - mu) * rs * g0.x + t0.x, 0.f),
                            fmaxf((v.y - mu) * rs * g0.y + t0.y, 0.f));
                v = h2f(u.y);
                u.y = pack2(fmaxf((v.x - mu) * rs * g0.z + t0.z, 0.f),
                            fmaxf((v.y - mu) * rs * g0.w + t0.w, 0.f));
                v = h2f(u.z);
                u.z = pack2(fmaxf((v.x - mu) * rs * g1.x + t1.x, 0.f),
                            fmaxf((v.y - mu) * rs * g1.y + t1.y, 0.f));
                v = h2f(u.w);
                u.w = pack2(fmaxf((v.x - mu) * rs * g1.z + t1.z, 0.f),
                            fmaxf((v.y - mu) * rs * g1.w + t1.w, 0.f));
                *(uint4*)&sh[H_HE + row * 520 + cb] = u;
            }
        }
    }
    __syncthreads();

    float c2[4][4];
    #pragma unroll
    for (int nj = 0; nj < 4; nj++)
        #pragma unroll
        for (int x = 0; x < 4; x++) c2[nj][x] = 0.f;

    for (int kc = 0; kc < 8; kc++) {
        #pragma unroll
        for (int t = 0; t < 4; t++) {
            int q = t * 256 + tid;
            int n = q & 63, k0 = (q >> 6) * 4;
            *(uint2*)&sh[H_W + n * 72 + k0] = wreg[t];
        }
        __syncthreads();
        if (kc < 7) {
            #pragma unroll
            for (int t = 0; t < 4; t++) {
                int q = t * 256 + tid;
                int n = q & 63, k0 = (q >> 6) * 4;
                const float* p = ew2 + (size_t)((kc + 1) * 64 + k0) * EE + n;
                wreg[t] = make_uint2(pack2(__ldg(p), __ldg(p + EE)),
                                     pack2(__ldg(p + 2 * EE), __ldg(p + 3 * EE)));
            }
        }
        gemm_16x32(sb, H_HE, 520, kc * 64, H_W, mt, ntw, lane, c2);
        __syncthreads();
    }

    #pragma unroll
    for (int nj = 0; nj < 4; nj++) {
        int cl = ntw + nj * 8 + 2 * tig;
        #pragma unroll
        for (int rr = 0; rr < 2; rr++) {
            int row = mt + g + rr * 8;
            *(float2*)&smem[F_OUT + row * 68 + cl] =
                make_float2(c2[nj][rr * 2 + 0], c2[nj][rr * 2 + 1]);
        }
    }
    __syncthreads();
    #pragma unroll
    for (int t = 0; t < 4; t++) {
        int q = t * 256 + tid;
        int r = q >> 4, c4 = (q & 15) * 4;
        float4 m = *(float4*)&smem[F_OUT + r * 68 + c4];
        size_t gbase = ((size_t)((size_t)b * NN + i) * NN + j0 + r) * EE + c4;
        float4 e4 = __ldg((const float4*)&edges[gbase]);
        float4 b4 = __ldg((const float4*)&eb2[c4]);
        float4 o = make_float4(e4.x + m.x + b4.x, e4.y + m.y + b4.y,
                               e4.z + m.z + b4.z, e4.w + m.w + b4.w);
        *(float4*)&out_edges[gbase] = o;
    }
}

// ============================================================
extern "C" void kernel_launch(void* const* d_in, const int* in_sizes, int n_in,
                              void* d_out, int out_size)
{
    const float* nodes = (const float*)d_in[0];
    const float* edges = (const float*)d_in[1];
    const float* adj   = (const float*)d_in[2];
    const float* nw1   = (const float*)d_in[3];
    const float* nb1   = (const float*)d_in[4];
    const float* ng    = (const float*)d_in[5];
    const float* nbt   = (const float*)d_in[6];
    const float* nw2   = (const float*)d_in[7];
    const float* nb2   = (const float*)d_in[8];
    const float* ew1   = (const float*)d_in[9];
    const float* eb1   = (const float*)d_in[10];
    const float* eg    = (const float*)d_in[11];
    const float* ebt   = (const float*)d_in[12];
    const float* ew2   = (const float*)d_in[13];
    const float* eb2   = (const float*)d_in[14];

    float* out_nodes = (float*)d_out;
    float* out_edges = out_nodes + (size_t)BB * NN * DD;

    cudaFuncSetAttribute(k_edge_mma, cudaFuncAttributeMaxDynamicSharedMemorySize,
                         EDGE_SMEM_BYTES);
    cudaFuncSetAttribute(k_node1, cudaFuncAttributeMaxDynamicSharedMemorySize,
                         N1_SMEM_BYTES);
    cudaFuncSetAttribute(k_node2, cudaFuncAttributeMaxDynamicSharedMemorySize,
                         N2_SMEM_BYTES);

    k_ninj_mma<<<dim3(8, 12), 256>>>(nodes, ew1, eb1);
    k_node1<<<48, 256, N1_SMEM_BYTES>>>(nodes, edges, adj, nw1, nb1, ng, nbt);
    k_node2<<<dim3(6, 24), 256, N2_SMEM_BYTES>>>(nodes, nw2, nb2, out_nodes);
    k_edge_mma<<<dim3(NN / JT, NN, BB), 256, EDGE_SMEM_BYTES>>>(edges, ew1, eg, ebt, ew2, eb2, out_edges);
}

// round 11
// speedup vs baseline: 4.0721x; 1.3471x over previous
#include <cuda_runtime.h>
#include <cuda_fp16.h>
#include <cstdint>

#define BB 2
#define NN 384
#define DD 768
#define EE 64
#define HH 512
#define JT 64

// -------- scratch (no allocations allowed) --------
__device__ float  g_NI [BB * NN * HH];     // 1.5 MB  (nodes@Wi + eb1)
__device__ __half g_NJh[BB * NN * HH];     // 768 KB  (nodes@Wj, fp16)
__device__ __half g_heh[BB * NN * HH];     // 768 KB  (node-path LN'ed hidden)

__device__ __forceinline__ uint32_t pack2(float a, float b) {
    __half2 h = __floats2half2_rn(a, b);
    return *reinterpret_cast<uint32_t*>(&h);
}
__device__ __forceinline__ float2 h2f(uint32_t u) {
    return __half22float2(*reinterpret_cast<__half2*>(&u));
}
__device__ __forceinline__ void ldm_x4(uint32_t& r0, uint32_t& r1,
                                       uint32_t& r2, uint32_t& r3, uint32_t addr) {
    asm volatile("ldmatrix.sync.aligned.m8n8.x4.shared.b16 {%0,%1,%2,%3}, [%4];"
                 : "=r"(r0), "=r"(r1), "=r"(r2), "=r"(r3) : "r"(addr));
}
__device__ __forceinline__ void mma_f16(float c[4],
                                        uint32_t a0, uint32_t a1, uint32_t a2, uint32_t a3,
                                        uint32_t b0, uint32_t b1) {
    asm volatile("mma.sync.aligned.m16n8k16.row.col.f32.f16.f16.f32 "
        "{%0,%1,%2,%3}, {%4,%5,%6,%7}, {%8,%9}, {%0,%1,%2,%3};"
        : "+f"(c[0]), "+f"(c[1]), "+f"(c[2]), "+f"(c[3])
        : "r"(a0), "r"(a1), "r"(a2), "r"(a3), "r"(b0), "r"(b1));
}

// warp-tile m16 x n32 GEMM over one k=64 chunk; B stride 72 halves
__device__ __forceinline__ void gemm_16x32(uint32_t sb, int offA, int strideA, int colA,
                                           int offB, int mt, int nt, int lane,
                                           float c[4][4]) {
    const int arow = lane & 15, ak8 = (lane >> 4) << 3;
    const int bn = (lane & 7) + ((lane >> 4) << 3);
    const int bk8 = ((lane >> 3) & 1) << 3;
    #pragma unroll
    for (int ks = 0; ks < 4; ks++) {
        int k0 = ks * 16;
        uint32_t a0, a1, a2, a3, p0, p1, p2, p3, q0, q1, q2, q3;
        ldm_x4(a0, a1, a2, a3, sb + 2 * (offA + (mt + arow) * strideA + colA + k0 + ak8));
        ldm_x4(p0, p1, p2, p3, sb + 2 * (offB + (nt + bn) * 72 + k0 + bk8));
        ldm_x4(q0, q1, q2, q3, sb + 2 * (offB + (nt + 16 + bn) * 72 + k0 + bk8));
        mma_f16(c[0], a0, a1, a2, a3, p0, p1);
        mma_f16(c[1], a0, a1, a2, a3, p2, p3);
        mma_f16(c[2], a0, a1, a2, a3, q0, q1);
        mma_f16(c[3], a0, a1, a2, a3, q2, q3);
    }
}

// ============================================================
// Kernel 1: NI = nodes@Wi + eb1 (fp32 out); NJ = nodes@Wj (fp16 out)
// ============================================================
__global__ __launch_bounds__(256) void k_ninj_mma(const float* __restrict__ nodes,
                                                  const float* __restrict__ ew1,
                                                  const float* __restrict__ eb1)
{
    __shared__ __half sh[64 * 72 + 128 * 72];
    const int H_A = 0, H_B = 64 * 72;
    const uint32_t sb = (uint32_t)__cvta_generic_to_shared(sh);
    const int tid = threadIdx.x;
    const int w = tid >> 5, lane = tid & 31;
    const int g = lane >> 2, tig = lane & 3;
    const int mt = (w & 3) * 16, ntb = (w >> 2) * 64;
    const int gc = blockIdx.x * 128;
    const int r0 = blockIdx.y * 64;
    const bool is_ni = (gc < HH);
    const int woff = is_ni ? EE : (EE + DD);
    const int col0 = is_ni ? gc : (gc - HH);

    float cacc[2][4][4];
    #pragma unroll
    for (int s = 0; s < 2; s++)
        #pragma unroll
        for (int nj = 0; nj < 4; nj++)
            #pragma unroll
            for (int x = 0; x < 4; x++) cacc[s][nj][x] = 0.f;

    for (int kc = 0; kc < 12; kc++) {
        __syncthreads();
        {
            int q = tid;
            #pragma unroll
            for (int t = 0; t < 4; t++, q += 256) {
                int r = q >> 4, k0 = (q & 15) * 4;
                float4 v = __ldg((const float4*)&nodes[(size_t)(r0 + r) * DD + kc * 64 + k0]);
                *(uint2*)&sh[H_A + r * 72 + k0] =
                    make_uint2(pack2(v.x, v.y), pack2(v.z, v.w));
            }
        }
        {
            int q = tid;
            #pragma unroll
            for (int t = 0; t < 8; t++, q += 256) {
                int n = q & 127, k0 = (q >> 7) * 4;
                const float* p = ew1 + (size_t)(woff + kc * 64 + k0) * HH + col0 + n;
                *(uint2*)&sh[H_B + n * 72 + k0] =
                    make_uint2(pack2(__ldg(p), __ldg(p + HH)),
                               pack2(__ldg(p + 2 * HH), __ldg(p + 3 * HH)));
            }
        }
        __syncthreads();
        gemm_16x32(sb, H_A, 72, 0, H_B, mt, ntb, lane, cacc[0]);
        gemm_16x32(sb, H_A, 72, 0, H_B, mt, ntb + 32, lane, cacc[1]);
    }

    #pragma unroll
    for (int s = 0; s < 2; s++)
        #pragma unroll
        for (int nj = 0; nj < 4; nj++) {
            int coll = ntb + s * 32 + nj * 8 + 2 * tig;
            #pragma unroll
            for (int rr = 0; rr < 2; rr++) {
                int row = mt + g + rr * 8;
                float v0 = cacc[s][nj][rr * 2 + 0];
                float v1 = cacc[s][nj][rr * 2 + 1];
                if (is_ni) {
                    float2 e = __ldg((const float2*)&eb1[gc + coll]);
                    *(float2*)&g_NI[(size_t)(r0 + row) * HH + gc + coll] =
                        make_float2(v0 + e.x, v1 + e.y);
                } else {
                    *(uint32_t*)&g_NJh[(size_t)(r0 + row) * HH + col0 + coll] = pack2(v0, v1);
                }
            }
        }
}

// ============================================================
// Kernel 2: node path part 1 — agg (fused) + GEMM1 + LN -> g_heh fp16.
// ============================================================
#define N1_SUM 0
#define N1_SQ  16
#define N1_MU  32
#define N1_RS  48
#define N1_AGG 64
#define N1H_A  2176
#define N1H_B  (N1H_A + 16 * 72)
#define N1_SMEM_BYTES ((N1H_B + 512 * 72) * 2)

__global__ __launch_bounds__(256) void k_node1(
    const float* __restrict__ nodes, const float* __restrict__ edges,
    const float* __restrict__ adj, const float* __restrict__ nw1,
    const float* __restrict__ nb1, const float* __restrict__ ng,
    const float* __restrict__ nbt)
{
    extern __shared__ float smem[];
    __half* sh = (__half*)smem;
    const uint32_t sb = (uint32_t)__cvta_generic_to_shared(smem);
    const int tid = threadIdx.x;
    const int w = tid >> 5, lane = tid & 31;
    const int g = lane >> 2, tig = lane & 3;
    const int r0 = blockIdx.x * 16;
    const int b = r0 / NN, i0 = r0 % NN;

    if (tid < 16) { smem[N1_SUM + tid] = 0.f; smem[N1_SQ + tid] = 0.f; }

    {
        int r = tid >> 4, e4 = (tid & 15) * 4;
        const float* er = edges + (size_t)((size_t)(b * NN + i0 + r) * NN) * EE;
        const float* ar = adj + (size_t)(b * NN + i0 + r) * NN;
        float4 acc = make_float4(0.f, 0.f, 0.f, 0.f);
        for (int j = 0; j < NN; j += 4) {
            float a0 = ar[j], a1 = ar[j + 1], a2 = ar[j + 2], a3 = ar[j + 3];
            if (a0 != 0.f) { float4 v = __ldg((const float4*)&er[(size_t)j * EE + e4]);
                acc.x += v.x * a0; acc.y += v.y * a0; acc.z += v.z * a0; acc.w += v.w * a0; }
            if (a1 != 0.f) { float4 v = __ldg((const float4*)&er[(size_t)(j + 1) * EE + e4]);
                acc.x += v.x * a1; acc.y += v.y * a1; acc.z += v.z * a1; acc.w += v.w * a1; }
            if (a2 != 0.f) { float4 v = __ldg((const float4*)&er[(size_t)(j + 2) * EE + e4]);
                acc.x += v.x * a2; acc.y += v.y * a2; acc.z += v.z * a2; acc.w += v.w * a2; }
            if (a3 != 0.f) { float4 v = __ldg((const float4*)&er[(size_t)(j + 3) * EE + e4]);
                acc.x += v.x * a3; acc.y += v.y * a3; acc.z += v.z * a3; acc.w += v.w * a3; }
        }
        *(float4*)&smem[N1_AGG + r * 64 + e4] = acc;
    }
    __syncthreads();

    float cacc[2][4][4];
    #pragma unroll
    for (int s = 0; s < 2; s++)
        #pragma unroll
        for (int nj = 0; nj < 4; nj++)
            #pragma unroll
            for (int x = 0; x < 4; x++) cacc[s][nj][x] = 0.f;

    for (int kc = 0; kc < 13; kc++) {
        __syncthreads();
        {
            int r = tid >> 4, k0 = (tid & 15) * 4;
            float4 v;
            if (kc == 0) v = *(float4*)&smem[N1_AGG + r * 64 + k0];
            else {
                v = __ldg((const float4*)&nodes[(size_t)(r0 + r) * DD + (kc - 1) * 64 + k0]);
                v.x *= (float)NN; v.y *= (float)NN; v.z *= (float)NN; v.w *= (float)NN;
            }
            *(uint2*)&sh[N1H_A + r * 72 + k0] = make_uint2(pack2(v.x, v.y), pack2(v.z, v.w));
        }
        {
            int q = tid;
            for (int t = 0; t < 32; t++, q += 256) {
                int n = q & 511, k0 = (q >> 9) * 4;
                const float* p = nw1 + (size_t)(kc * 64 + k0) * HH + n;
                *(uint2*)&sh[N1H_B + n * 72 + k0] =
                    make_uint2(pack2(__ldg(p), __ldg(p + HH)),
                               pack2(__ldg(p + 2 * HH), __ldg(p + 3 * HH)));
            }
        }
        __syncthreads();
        gemm_16x32(sb, N1H_A, 72, 0, N1H_B, 0, w * 64, lane, cacc[0]);
        gemm_16x32(sb, N1H_A, 72, 0, N1H_B, 0, w * 64 + 32, lane, cacc[1]);
    }

    float rsum[2] = {0.f, 0.f}, rsq[2] = {0.f, 0.f};
    #pragma unroll
    for (int s = 0; s < 2; s++)
        #pragma unroll
        for (int nj = 0; nj < 4; nj++) {
            int coll = w * 64 + s * 32 + nj * 8 + 2 * tig;
            float2 b1 = __ldg((const float2*)&nb1[coll]);
            #pragma unroll
            for (int rr = 0; rr < 2; rr++) {
                float v0 = cacc[s][nj][rr * 2 + 0] + b1.x;
                float v1 = cacc[s][nj][rr * 2 + 1] + b1.y;
                cacc[s][nj][rr * 2 + 0] = v0;
                cacc[s][nj][rr * 2 + 1] = v1;
                rsum[rr] += v0 + v1;
                rsq[rr]  += v0 * v0 + v1 * v1;
            }
        }
    #pragma unroll
    for (int rr = 0; rr < 2; rr++) {
        float s = rsum[rr], q2 = rsq[rr];
        s  += __shfl_xor_sync(0xffffffffu, s, 1);
        s  += __shfl_xor_sync(0xffffffffu, s, 2);
        q2 += __shfl_xor_sync(0xffffffffu, q2, 1);
        q2 += __shfl_xor_sync(0xffffffffu, q2, 2);
        if (tig == 0) {
            atomicAdd(&smem[N1_SUM + g + rr * 8], s);
            atomicAdd(&smem[N1_SQ + g + rr * 8], q2);
        }
    }
    __syncthreads();
    if (tid < 16) {
        float mu = smem[N1_SUM + tid] * (1.f / HH);
        float var = smem[N1_SQ + tid] * (1.f / HH) - mu * mu;
        smem[N1_MU + tid] = mu;
        smem[N1_RS + tid] = rsqrtf(var + 1e-5f);
    }
    __syncthreads();
    const float mu0 = smem[N1_MU + g],     rs0 = smem[N1_RS + g];
    const float mu1 = smem[N1_MU + g + 8], rs1 = smem[N1_RS + g + 8];

    #pragma unroll
    for (int s = 0; s < 2; s++)
        #pragma unroll
        for (int nj = 0; nj < 4; nj++) {
            int coll = w * 64 + s * 32 + nj * 8 + 2 * tig;
            float2 gg = __ldg((const float2*)&ng[coll]);
            float2 bb = __ldg((const float2*)&nbt[coll]);
            float v0 = fmaxf((cacc[s][nj][0] - mu0) * rs0 * gg.x + bb.x, 0.f);
            float v1 = fmaxf((cacc[s][nj][1] - mu0) * rs0 * gg.y + bb.y, 0.f);
            float v2 = fmaxf((cacc[s][nj][2] - mu1) * rs1 * gg.x + bb.x, 0.f);
            float v3 = fmaxf((cacc[s][nj][3] - mu1) * rs1 * gg.y + bb.y, 0.f);
            *(uint32_t*)&sh[N1H_B + g * 520 + coll]       = pack2(v0, v1);
            *(uint32_t*)&sh[N1H_B + (g + 8) * 520 + coll] = pack2(v2, v3);
        }
    __syncthreads();
    {
        int q = tid;
        #pragma unroll
        for (int t = 0; t < 4; t++, q += 256) {
            int r = q >> 6, c0 = (q & 63) * 8;
            *(uint4*)&g_heh[(size_t)(r0 + r) * HH + c0] = *(uint4*)&sh[N1H_B + r * 520 + c0];
        }
    }
}

// ============================================================
// Kernel 3: node path part 2 — out = nodes + relu_he @ nw2 + nb2.
// ============================================================
#define N2H_HE 0
#define N2H_B  (32 * 520)
#define N2F_OUT 12928
#define N2_SMEM_BYTES ((N2F_OUT + 32 * 132) * 4)

__global__ __launch_bounds__(256) void k_node2(
    const float* __restrict__ nodes, const float* __restrict__ nw2,
    const float* __restrict__ nb2, float* __restrict__ out_nodes)
{
    extern __shared__ float smem[];
    __half* sh = (__half*)smem;
    const uint32_t sb = (uint32_t)__cvta_generic_to_shared(smem);
    const int tid = threadIdx.x;
    const int w = tid >> 5, lane = tid & 31;
    const int g = lane >> 2, tig = lane & 3;
    const int mt = (w & 1) * 16, nt = (w >> 1) * 32;
    const int nc = blockIdx.x * 128;
    const int r0 = blockIdx.y * 32;

    {
        int q = tid;
        #pragma unroll
        for (int t = 0; t < 8; t++, q += 256) {
            int r = q >> 6, c0 = (q & 63) * 8;
            *(uint4*)&sh[N2H_HE + r * 520 + c0] = *(const uint4*)&g_heh[(size_t)(r0 + r) * HH + c0];
        }
    }

    float c2[4][4];
    #pragma unroll
    for (int nj = 0; nj < 4; nj++)
        #pragma unroll
        for (int x = 0; x < 4; x++) c2[nj][x] = 0.f;

    for (int kc = 0; kc < 8; kc++) {
        __syncthreads();
        {
            int q = tid;
            #pragma unroll
            for (int t = 0; t < 8; t++, q += 256) {
                int n = q & 127, k0 = (q >> 7) * 4;
                const float* p = nw2 + (size_t)(kc * 64 + k0) * DD + nc + n;
                *(uint2*)&sh[N2H_B + n * 72 + k0] =
                    make_uint2(pack2(__ldg(p), __ldg(p + DD)),
                               pack2(__ldg(p + 2 * DD), __ldg(p + 3 * DD)));
            }
        }
        __syncthreads();
        gemm_16x32(sb, N2H_HE, 520, kc * 64, N2H_B, mt, nt, lane, c2);
    }

    __syncthreads();
    #pragma unroll
    for (int nj = 0; nj < 4; nj++) {
        int coll = nt + nj * 8 + 2 * tig;
        #pragma unroll
        for (int rr = 0; rr < 2; rr++) {
            int row = mt + g + rr * 8;
            *(float2*)&smem[N2F_OUT + row * 132 + coll] =
                make_float2(c2[nj][rr * 2 + 0], c2[nj][rr * 2 + 1]);
        }
    }
    __syncthreads();
    {
        int q = tid;
        #pragma unroll
        for (int t = 0; t < 4; t++, q += 256) {
            int r = q >> 5, c4 = (q & 31) * 4;
            float4 m = *(float4*)&smem[N2F_OUT + r * 132 + c4];
            size_t gi = (size_t)(r0 + r) * DD + nc + c4;
            float4 n4 = __ldg((const float4*)&nodes[gi]);
            float4 b4 = __ldg((const float4*)&nb2[nc + c4]);
            *(float4*)&out_nodes[gi] = make_float4(n4.x + m.x + b4.x, n4.y + m.y + b4.y,
                                                   n4.z + m.z + b4.z, n4.w + m.w + b4.w);
        }
    }
}

// ============================================================
// Kernel 4: fp16 fused edge path; E-frag hoist, double-buffered W,
// NJ direct-LDG epilogue, one sync per chunk.  2 CTAs/SM.
// ============================================================
#define F_NI   0
#define F_SUM  512
#define F_SQ   576
#define F_MU   640
#define F_RS   704
#define F_OUT  768                  // aliases H_E/H_W0 (dead at epilogue)
#define H_E    1536                 // half idx: [64][72]
#define H_W0   (H_E + 64 * 72)      // [64][72]
#define H_W1   (H_W0 + 64 * 72)     // [64][72]
#define H_HE   (H_W1 + 64 * 72)     // [64][520]
#define EDGE_SMEM_BYTES ((H_HE + 64 * 520) * 2)

__global__ __launch_bounds__(256, 2) void k_edge_mma(
    const float* __restrict__ edges,
    const float* __restrict__ ew1,
    const float* __restrict__ eg,
    const float* __restrict__ ebt,
    const float* __restrict__ ew2,
    const float* __restrict__ eb2,
    float* __restrict__ out_edges)
{
    extern __shared__ float smem[];
    __half* sh = (__half*)smem;
    const uint32_t sb = (uint32_t)__cvta_generic_to_shared(smem);
    const int tid = threadIdx.x;
    const int w = tid >> 5, lane = tid & 31;
    const int g = lane >> 2, tig = lane & 3;
    const int mt = (w & 3) * 16, ntw = (w >> 2) * 32;
    const int b = blockIdx.z, i = blockIdx.y;
    const int j0 = blockIdx.x * JT;

    const int arow = lane & 15, ak8 = (lane >> 4) << 3;
    const int bn = (lane & 7) + ((lane >> 4) << 3);
    const int bk8 = ((lane >> 3) & 1) << 3;

    uint2 wreg[4];

    // ---- stage E [64][72] fp16 ----
    const float* etile = edges + ((size_t)((size_t)b * NN + i) * NN + j0) * EE;
    #pragma unroll
    for (int t = 0; t < 4; t++) {
        int q = t * 256 + tid;
        int j = q >> 4, k0 = (q & 15) * 4;
        float4 v = __ldg((const float4*)&etile[j * EE + k0]);
        *(uint2*)&sh[H_E + j * 72 + k0] = make_uint2(pack2(v.x, v.y), pack2(v.z, v.w));
    }
    // ---- NI cache + zero stats ----
    const float* nip = g_NI + (size_t)((size_t)b * NN + i) * HH;
    smem[F_NI + tid] = __ldg(&nip[tid]);
    smem[F_NI + 256 + tid] = __ldg(&nip[256 + tid]);
    if (tid < 64) { smem[F_SUM + tid] = 0.f; smem[F_SQ + tid] = 0.f; }

    // prefetch W1 chunk0
    #pragma unroll
    for (int t = 0; t < 4; t++) {
        int q = t * 256 + tid;
        int n = q & 63, k0 = (q >> 6) * 4;
        const float* p = ew1 + (size_t)k0 * HH + n;
        wreg[t] = make_uint2(pack2(__ldg(p), __ldg(p + HH)),
                             pack2(__ldg(p + 2 * HH), __ldg(p + 3 * HH)));
    }
    __syncthreads();                       // E visible

    // ---- hoist E fragments (chunk-invariant A operand) ----
    uint32_t ef[4][4];
    #pragma unroll
    for (int ks = 0; ks < 4; ks++)
        ldm_x4(ef[ks][0], ef[ks][1], ef[ks][2], ef[ks][3],
               sb + 2 * (H_E + (mt + arow) * 72 + ks * 16 + ak8));

    // STS W chunk0 -> buf0
    #pragma unroll
    for (int t = 0; t < 4; t++) {
        int q = t * 256 + tid;
        int n = q & 63, k0 = (q >> 6) * 4;
        *(uint2*)&sh[H_W0 + n * 72 + k0] = wreg[t];
    }
    __syncthreads();

    const __half* njb = g_NJh + (size_t)((size_t)b * NN + j0) * HH;

    // ================= GEMM1: he = E@We + NI + NJ ==========================
    float rsum[2] = {0.f, 0.f}, rsq[2] = {0.f, 0.f};
    for (int ch = 0; ch < 8; ch++) {
        if (ch < 7) {
            #pragma unroll
            for (int t = 0; t < 4; t++) {
                int q = t * 256 + tid;
                int n = q & 63, k0 = (q >> 6) * 4;
                const float* p = ew1 + (size_t)k0 * HH + (ch + 1) * 64 + n;
                wreg[t] = make_uint2(pack2(__ldg(p), __ldg(p + HH)),
                                     pack2(__ldg(p + 2 * HH), __ldg(p + 3 * HH)));
            }
        }
        const int bufo = (ch & 1) ? H_W1 : H_W0;
        float c[4][4];
        #pragma unroll
        for (int nj = 0; nj < 4; nj++)
            #pragma unroll
            for (int x = 0; x < 4; x++) c[nj][x] = 0.f;
        #pragma unroll
        for (int ks = 0; ks < 4; ks++) {
            int k0 = ks * 16;
            uint32_t p0, p1, p2, p3, q0, q1, q2, q3;
            ldm_x4(p0, p1, p2, p3, sb + 2 * (bufo + (ntw + bn) * 72 + k0 + bk8));
            ldm_x4(q0, q1, q2, q3, sb + 2 * (bufo + (ntw + 16 + bn) * 72 + k0 + bk8));
            mma_f16(c[0], ef[ks][0], ef[ks][1], ef[ks][2], ef[ks][3], p0, p1);
            mma_f16(c[1], ef[ks][0], ef[ks][1], ef[ks][2], ef[ks][3], p2, p3);
            mma_f16(c[2], ef[ks][0], ef[ks][1], ef[ks][2], ef[ks][3], q0, q1);
            mma_f16(c[3], ef[ks][0], ef[ks][1], ef[ks][2], ef[ks][3], q2, q3);
        }

        // epilogue: += NI (smem) + NJ (direct gmem fp16), stats, store raw he
        #pragma unroll
        for (int nj = 0; nj < 4; nj++) {
            int cl = ntw + nj * 8 + 2 * tig;
            float2 ni = *(float2*)&smem[F_NI + ch * 64 + cl];
            #pragma unroll
            for (int rr = 0; rr < 2; rr++) {
                int row = mt + g + rr * 8;
                float2 njv = h2f(__ldg((const unsigned int*)&njb[(size_t)row * HH + ch * 64 + cl]));
                float v0 = c[nj][rr * 2 + 0] + ni.x + njv.x;
                float v1 = c[nj][rr * 2 + 1] + ni.y + njv.y;
                rsum[rr] += v0 + v1;
                rsq[rr]  += v0 * v0 + v1 * v1;
                *(uint32_t*)&sh[H_HE + row * 520 + ch * 64 + cl] = pack2(v0, v1);
            }
        }
        if (ch < 7) {
            const int nbuf = (ch & 1) ? H_W0 : H_W1;
            #pragma unroll
            for (int t = 0; t < 4; t++) {
                int q = t * 256 + tid;
                int n = q & 63, k0 = (q >> 6) * 4;
                *(uint2*)&sh[nbuf + n * 72 + k0] = wreg[t];
            }
        }
        __syncthreads();
    }

    // ---- LN stats reduction ----
    #pragma unroll
    for (int rr = 0; rr < 2; rr++) {
        float s = rsum[rr], q2 = rsq[rr];
        s  += __shfl_xor_sync(0xffffffffu, s, 1);
        s  += __shfl_xor_sync(0xffffffffu, s, 2);
        q2 += __shfl_xor_sync(0xffffffffu, q2, 1);
        q2 += __shfl_xor_sync(0xffffffffu, q2, 2);
        if (tig == 0) {
            atomicAdd(&smem[F_SUM + mt + g + rr * 8], s);
            atomicAdd(&smem[F_SQ  + mt + g + rr * 8], q2);
        }
    }
    __syncthreads();
    if (tid < 64) {
        float mu = smem[F_SUM + tid] * (1.f / HH);
        float var = smem[F_SQ + tid] * (1.f / HH) - mu * mu;
        smem[F_MU + tid] = mu;
        smem[F_RS + tid] = rsqrtf(var + 1e-5f);
    }
    // prefetch W2 chunk0
    #pragma unroll
    for (int t = 0; t < 4; t++) {
        int q = t * 256 + tid;
        int n = q & 63, k0 = (q >> 6) * 4;
        const float* p = ew2 + (size_t)k0 * EE + n;
        wreg[t] = make_uint2(pack2(__ldg(p), __ldg(p + EE)),
                             pack2(__ldg(p + 2 * EE), __ldg(p + 3 * EE)));
    }
    __syncthreads();                        // MU/RS visible

    // ---- coalesced in-place LN + relu pass over he ----
    {
        int wr = w * 8;
        #pragma unroll
        for (int pass = 0; pass < 2; pass++) {
            int cb = pass * 256 + lane * 8;
            float4 g0 = __ldg((const float4*)&eg[cb]);
            float4 g1 = __ldg((const float4*)&eg[cb + 4]);
            float4 t0 = __ldg((const float4*)&ebt[cb]);
            float4 t1 = __ldg((const float4*)&ebt[cb + 4]);
            #pragma unroll
            for (int r = 0; r < 8; r++) {
                int row = wr + r;
                float mu = smem[F_MU + row], rs = smem[F_RS + row];
                uint4 u = *(uint4*)&sh[H_HE + row * 520 + cb];
                float2 v;
                v = h2f(u.x);
                u.x = pack2(fmaxf((v.x - mu) * rs * g0.x + t0.x, 0.f),
                            fmaxf((v.y - mu) * rs * g0.y + t0.y, 0.f));
                v = h2f(u.y);
                u.y = pack2(fmaxf((v.x - mu) * rs * g0.z + t0.z, 0.f),
                            fmaxf((v.y - mu) * rs * g0.w + t0.w, 0.f));
                v = h2f(u.z);
                u.z = pack2(fmaxf((v.x - mu) * rs * g1.x + t1.x, 0.f),
                            fmaxf((v.y - mu) * rs * g1.y + t1.y, 0.f));
                v = h2f(u.w);
                u.w = pack2(fmaxf((v.x - mu) * rs * g1.z + t1.z, 0.f),
                            fmaxf((v.y - mu) * rs * g1.w + t1.w, 0.f));
                *(uint4*)&sh[H_HE + row * 520 + cb] = u;
            }
        }
    }
    // STS W2 chunk0 -> buf0
    #pragma unroll
    for (int t = 0; t < 4; t++) {
        int q = t * 256 + tid;
        int n = q & 63, k0 = (q >> 6) * 4;
        *(uint2*)&sh[H_W0 + n * 72 + k0] = wreg[t];
    }
    __syncthreads();

    // ================= GEMM2: out = ln_relu_he @ ew2 =======================
    float c2[4][4];
    #pragma unroll
    for (int nj = 0; nj < 4; nj++)
        #pragma unroll
        for (int x = 0; x < 4; x++) c2[nj][x] = 0.f;

    for (int kc = 0; kc < 8; kc++) {
        if (kc < 7) {
            #pragma unroll
            for (int t = 0; t < 4; t++) {
                int q = t * 256 + tid;
                int n = q & 63, k0 = (q >> 6) * 4;
                const float* p = ew2 + (size_t)((kc + 1) * 64 + k0) * EE + n;
                wreg[t] = make_uint2(pack2(__ldg(p), __ldg(p + EE)),
                                     pack2(__ldg(p + 2 * EE), __ldg(p + 3 * EE)));
            }
        }
        const int bufo = (kc & 1) ? H_W1 : H_W0;
        #pragma unroll
        for (int ks = 0; ks < 4; ks++) {
            int k0 = ks * 16;
            uint32_t a0, a1, a2, a3, p0, p1, p2, p3, q0, q1, q2, q3;
            ldm_x4(a0, a1, a2, a3,
                   sb + 2 * (H_HE + (mt + arow) * 520 + kc * 64 + k0 + ak8));
            ldm_x4(p0, p1, p2, p3, sb + 2 * (bufo + (ntw + bn) * 72 + k0 + bk8));
            ldm_x4(q0, q1, q2, q3, sb + 2 * (bufo + (ntw + 16 + bn) * 72 + k0 + bk8));
            mma_f16(c2[0], a0, a1, a2, a3, p0, p1);
            mma_f16(c2[1], a0, a1, a2, a3, p2, p3);
            mma_f16(c2[2], a0, a1, a2, a3, q0, q1);
            mma_f16(c2[3], a0, a1, a2, a3, q2, q3);
        }
        if (kc < 7) {
            const int nbuf = (kc & 1) ? H_W0 : H_W1;
            #pragma unroll
            for (int t = 0; t < 4; t++) {
                int q = t * 256 + tid;
                int n = q & 63, k0 = (q >> 6) * 4;
                *(uint2*)&sh[nbuf + n * 72 + k0] = wreg[t];
            }
        }
        __syncthreads();
    }

    // ---- epilogue: bounce via smem (aliases E/W0), coalesced store ----
    #pragma unroll
    for (int nj = 0; nj < 4; nj++) {
        int cl = ntw + nj * 8 + 2 * tig;
        #pragma unroll
        for (int rr = 0; rr < 2; rr++) {
            int row = mt + g + rr * 8;
            *(float2*)&smem[F_OUT + row * 68 + cl] =
                make_float2(c2[nj][rr * 2 + 0], c2[nj][rr * 2 + 1]);
        }
    }
    __syncthreads();
    #pragma unroll
    for (int t = 0; t < 4; t++) {
        int q = t * 256 + tid;
        int r = q >> 4, c4 = (q & 15) * 4;
        float4 m = *(float4*)&smem[F_OUT + r * 68 + c4];
        size_t gbase = ((size_t)((size_t)b * NN + i) * NN + j0 + r) * EE + c4;
        float4 e4 = __ldg((const float4*)&edges[gbase]);
        float4 b4 = __ldg((const float4*)&eb2[c4]);
        float4 o = make_float4(e4.x + m.x + b4.x, e4.y + m.y + b4.y,
                               e4.z + m.z + b4.z, e4.w + m.w + b4.w);
        *(float4*)&out_edges[gbase] = o;
    }
}

// ============================================================
extern "C" void kernel_launch(void* const* d_in, const int* in_sizes, int n_in,
                              void* d_out, int out_size)
{
    const float* nodes = (const float*)d_in[0];
    const float* edges = (const float*)d_in[1];
    const float* adj   = (const float*)d_in[2];
    const float* nw1   = (const float*)d_in[3];
    const float* nb1   = (const float*)d_in[4];
    const float* ng    = (const float*)d_in[5];
    const float* nbt   = (const float*)d_in[6];
    const float* nw2   = (const float*)d_in[7];
    const float* nb2   = (const float*)d_in[8];
    const float* ew1   = (const float*)d_in[9];
    const float* eb1   = (const float*)d_in[10];
    const float* eg    = (const float*)d_in[11];
    const float* ebt   = (const float*)d_in[12];
    const float* ew2   = (const float*)d_in[13];
    const float* eb2   = (const float*)d_in[14];

    float* out_nodes = (float*)d_out;
    float* out_edges = out_nodes + (size_t)BB * NN * DD;

    cudaFuncSetAttribute(k_edge_mma, cudaFuncAttributeMaxDynamicSharedMemorySize,
                         EDGE_SMEM_BYTES);
    cudaFuncSetAttribute(k_node1, cudaFuncAttributeMaxDynamicSharedMemorySize,
                         N1_SMEM_BYTES);
    cudaFuncSetAttribute(k_node2, cudaFuncAttributeMaxDynamicSharedMemorySize,
                         N2_SMEM_BYTES);

    // fork a side stream so the (node1 -> node2) chain overlaps (ninj -> edge)
    static cudaStream_t s2 = nullptr;
    static cudaEvent_t evFork = nullptr, evJoin = nullptr;
    if (s2 == nullptr) {
        if (cudaStreamCreateWithFlags(&s2, cudaStreamNonBlocking) != cudaSuccess)
            s2 = nullptr;
        if (s2) {
            cudaEventCreateWithFlags(&evFork, cudaEventDisableTiming);
            cudaEventCreateWithFlags(&evJoin, cudaEventDisableTiming);
        }
    }

    if (s2) {
        cudaEventRecord(evFork, 0);
        cudaStreamWaitEvent(s2, evFork, 0);
        k_node1<<<48, 256, N1_SMEM_BYTES, s2>>>(nodes, edges, adj, nw1, nb1, ng, nbt);
        k_node2<<<dim3(6, 24), 256, N2_SMEM_BYTES, s2>>>(nodes, nw2, nb2, out_nodes);
        cudaEventRecord(evJoin, s2);
        k_ninj_mma<<<dim3(8, 12), 256>>>(nodes, ew1, eb1);
        k_edge_mma<<<dim3(NN / JT, NN, BB), 256, EDGE_SMEM_BYTES>>>(edges, ew1, eg, ebt, ew2, eb2, out_edges);
        cudaStreamWaitEvent(0, evJoin, 0);
    } else {
        k_ninj_mma<<<dim3(8, 12), 256>>>(nodes, ew1, eb1);
        k_node1<<<48, 256, N1_SMEM_BYTES>>>(nodes, edges, adj, nw1, nb1, ng, nbt);
        k_node2<<<dim3(6, 24), 256, N2_SMEM_BYTES>>>(nodes, nw2, nb2, out_nodes);
        k_edge_mma<<<dim3(NN / JT, NN, BB), 256, EDGE_SMEM_BYTES>>>(edges, ew1, eg, ebt, ew2, eb2, out_edges);
    }
}

// round 12
// speedup vs baseline: 5.3108x; 1.3042x over previous
#include <cuda_runtime.h>
#include <cuda_fp16.h>
#include <cstdint>

#define BB 2
#define NN 384
#define DD 768
#define EE 64
#define HH 512
#define JT 64

// -------- scratch (no allocations allowed) --------
__device__ float  g_NI [BB * NN * HH];       // 1.5 MB
__device__ __half g_NJh[BB * NN * HH];       // 768 KB
__device__ __half g_heh[BB * NN * HH];       // 768 KB
__device__ __half g_w1h[8 * 64 * 64];        // We  chunks [ch][n][k]
__device__ __half g_w2h[8 * 64 * 64];        // ew2 chunks [kc][n][k]
__device__ __half g_wijh[2 * 512 * 768];     // Wi/Wj transposed [z][n][k]

__device__ __forceinline__ uint32_t pack2(float a, float b) {
    __half2 h = __floats2half2_rn(a, b);
    return *reinterpret_cast<uint32_t*>(&h);
}
__device__ __forceinline__ float2 h2f(uint32_t u) {
    return __half22float2(*reinterpret_cast<__half2*>(&u));
}
__device__ __forceinline__ void ldm_x4(uint32_t& r0, uint32_t& r1,
                                       uint32_t& r2, uint32_t& r3, uint32_t addr) {
    asm volatile("ldmatrix.sync.aligned.m8n8.x4.shared.b16 {%0,%1,%2,%3}, [%4];"
                 : "=r"(r0), "=r"(r1), "=r"(r2), "=r"(r3) : "r"(addr));
}
__device__ __forceinline__ void mma_f16(float c[4],
                                        uint32_t a0, uint32_t a1, uint32_t a2, uint32_t a3,
                                        uint32_t b0, uint32_t b1) {
    asm volatile("mma.sync.aligned.m16n8k16.row.col.f32.f16.f16.f32 "
        "{%0,%1,%2,%3}, {%4,%5,%6,%7}, {%8,%9}, {%0,%1,%2,%3};"
        : "+f"(c[0]), "+f"(c[1]), "+f"(c[2]), "+f"(c[3])
        : "r"(a0), "r"(a1), "r"(a2), "r"(a3), "r"(b0), "r"(b1));
}
__device__ __forceinline__ void cp16(uint32_t dst, const void* src) {
    asm volatile("cp.async.cg.shared.global [%0], [%1], 16;" :: "r"(dst), "l"(src));
}
#define CP_COMMIT() asm volatile("cp.async.commit_group;" ::: "memory")
#define CP_WAIT0()  asm volatile("cp.async.wait_group 0;" ::: "memory")

// warp-tile m16 x n32 GEMM over one k=64 chunk; B stride 72 halves
__device__ __forceinline__ void gemm_16x32(uint32_t sb, int offA, int strideA, int colA,
                                           int offB, int mt, int nt, int lane,
                                           float c[4][4]) {
    const int arow = lane & 15, ak8 = (lane >> 4) << 3;
    const int bn = (lane & 7) + ((lane >> 4) << 3);
    const int bk8 = ((lane >> 3) & 1) << 3;
    #pragma unroll
    for (int ks = 0; ks < 4; ks++) {
        int k0 = ks * 16;
        uint32_t a0, a1, a2, a3, p0, p1, p2, p3, q0, q1, q2, q3;
        ldm_x4(a0, a1, a2, a3, sb + 2 * (offA + (mt + arow) * strideA + colA + k0 + ak8));
        ldm_x4(p0, p1, p2, p3, sb + 2 * (offB + (nt + bn) * 72 + k0 + bk8));
        ldm_x4(q0, q1, q2, q3, sb + 2 * (offB + (nt + 16 + bn) * 72 + k0 + bk8));
        mma_f16(c[0], a0, a1, a2, a3, p0, p1);
        mma_f16(c[1], a0, a1, a2, a3, p2, p3);
        mma_f16(c[2], a0, a1, a2, a3, q0, q1);
        mma_f16(c[3], a0, a1, a2, a3, q2, q3);
    }
}

// ============================================================
// Kernel 0: weight pre-conversion to fp16 staging layouts
// ============================================================
__global__ __launch_bounds__(256) void k_prep(const float* __restrict__ ew1,
                                              const float* __restrict__ ew2)
{
    int idx = blockIdx.x * 256 + threadIdx.x;
    int stride = gridDim.x * 256;
    for (int i = idx; i < 8 * 64 * 64; i += stride) {
        int ch = i >> 12, r = i & 4095, n = r >> 6, k = r & 63;
        g_w1h[i] = __float2half_rn(ew1[(size_t)k * HH + ch * 64 + n]);
    }
    for (int i = idx; i < 8 * 64 * 64; i += stride) {
        int kc = i >> 12, r = i & 4095, n = r >> 6, k = r & 63;
        g_w2h[i] = __float2half_rn(ew2[(size_t)(kc * 64 + k) * EE + n]);
    }
    for (int i = idx; i < 2 * 512 * 768; i += stride) {
        int z = i / (512 * 768), r = i % (512 * 768), n = r / 768, k = r % 768;
        g_wijh[i] = __float2half_rn(ew1[(size_t)(EE + z * DD + k) * HH + n]);
    }
}

// ============================================================
// Kernel 1: NI = nodes@Wi + eb1 (fp32 out); NJ = nodes@Wj (fp16 out)
// B via cp.async from g_wijh; A double-buffered via registers.
// ============================================================
#define NJ_A0 0
#define NJ_A1 (64 * 72)
#define NJ_B0 (2 * 64 * 72)
#define NJ_B1 (NJ_B0 + 128 * 72)
#define NINJ_SMEM_BYTES ((NJ_B1 + 128 * 72) * 2)

__global__ __launch_bounds__(256) void k_ninj_mma(const float* __restrict__ nodes,
                                                  const float* __restrict__ eb1)
{
    extern __shared__ __half shn[];
    const uint32_t sb = (uint32_t)__cvta_generic_to_shared(shn);
    const int tid = threadIdx.x;
    const int w = tid >> 5, lane = tid & 31;
    const int g = lane >> 2, tig = lane & 3;
    const int mt = (w & 3) * 16, ntb = (w >> 2) * 64;
    const int gc = blockIdx.x * 128;
    const int r0 = blockIdx.y * 64;
    const bool is_ni = (gc < HH);
    const int z = is_ni ? 0 : 1;
    const int col0 = is_ni ? gc : (gc - HH);
    const __half* wsrc = g_wijh + (size_t)z * 512 * 768;

    float cacc[2][4][4];
    #pragma unroll
    for (int s = 0; s < 2; s++)
        #pragma unroll
        for (int nj = 0; nj < 4; nj++)
            #pragma unroll
            for (int x = 0; x < 4; x++) cacc[s][nj][x] = 0.f;

    // prefetch A0 to regs; issue B0 cp.async
    uint2 areg[4];
    #pragma unroll
    for (int t = 0; t < 4; t++) {
        int q = t * 256 + tid;
        int r = q >> 4, k0 = (q & 15) * 4;
        float4 v = __ldg((const float4*)&nodes[(size_t)(r0 + r) * DD + k0]);
        areg[t] = make_uint2(pack2(v.x, v.y), pack2(v.z, v.w));
    }
    #pragma unroll
    for (int t = 0; t < 4; t++) {
        int q = t * 256 + tid;                 // 1024 segs
        int n = q >> 3, k8 = (q & 7) * 8;
        cp16(sb + 2 * (NJ_B0 + n * 72 + k8), wsrc + (size_t)(col0 + n) * 768 + k8);
    }
    CP_COMMIT();

    for (int kc = 0; kc < 12; kc++) {
        const int abuf = (kc & 1) ? NJ_A1 : NJ_A0;
        // STS A_kc
        #pragma unroll
        for (int t = 0; t < 4; t++) {
            int q = t * 256 + tid;
            int r = q >> 4, k0 = (q & 15) * 4;
            *(uint2*)&shn[abuf + r * 72 + k0] = areg[t];
        }
        // prefetch A_{kc+1}
        if (kc < 11) {
            #pragma unroll
            for (int t = 0; t < 4; t++) {
                int q = t * 256 + tid;
                int r = q >> 4, k0 = (q & 15) * 4;
                float4 v = __ldg((const float4*)&nodes[(size_t)(r0 + r) * DD + (kc + 1) * 64 + k0]);
                areg[t] = make_uint2(pack2(v.x, v.y), pack2(v.z, v.w));
            }
        }
        CP_WAIT0();
        __syncthreads();
        if (kc < 11) {
            const int nb = (kc & 1) ? NJ_B0 : NJ_B1;
            #pragma unroll
            for (int t = 0; t < 4; t++) {
                int q = t * 256 + tid;
                int n = q >> 3, k8 = (q & 7) * 8;
                cp16(sb + 2 * (nb + n * 72 + k8),
                     wsrc + (size_t)(col0 + n) * 768 + (kc + 1) * 64 + k8);
            }
            CP_COMMIT();
        }
        const int bbuf = (kc & 1) ? NJ_B1 : NJ_B0;
        gemm_16x32(sb, abuf, 72, 0, bbuf, mt, ntb, lane, cacc[0]);
        gemm_16x32(sb, abuf, 72, 0, bbuf, mt, ntb + 32, lane, cacc[1]);
        __syncthreads();                       // consumption done before A STS / B issue reuse
    }

    #pragma unroll
    for (int s = 0; s < 2; s++)
        #pragma unroll
        for (int nj = 0; nj < 4; nj++) {
            int coll = ntb + s * 32 + nj * 8 + 2 * tig;
            #pragma unroll
            for (int rr = 0; rr < 2; rr++) {
                int row = mt + g + rr * 8;
                float v0 = cacc[s][nj][rr * 2 + 0];
                float v1 = cacc[s][nj][rr * 2 + 1];
                if (is_ni) {
                    float2 e = __ldg((const float2*)&eb1[gc + coll]);
                    *(float2*)&g_NI[(size_t)(r0 + row) * HH + gc + coll] =
                        make_float2(v0 + e.x, v1 + e.y);
                } else {
                    *(uint32_t*)&g_NJh[(size_t)(r0 + row) * HH + col0 + coll] = pack2(v0, v1);
                }
            }
        }
}

// ============================================================
// Kernel 2: node path part 1 (unchanged)
// ============================================================
#define N1_SUM 0
#define N1_SQ  16
#define N1_MU  32
#define N1_RS  48
#define N1_AGG 64
#define N1H_A  2176
#define N1H_B  (N1H_A + 16 * 72)
#define N1_SMEM_BYTES ((N1H_B + 512 * 72) * 2)

__global__ __launch_bounds__(256) void k_node1(
    const float* __restrict__ nodes, const float* __restrict__ edges,
    const float* __restrict__ adj, const float* __restrict__ nw1,
    const float* __restrict__ nb1, const float* __restrict__ ng,
    const float* __restrict__ nbt)
{
    extern __shared__ float smem[];
    __half* sh = (__half*)smem;
    const uint32_t sb = (uint32_t)__cvta_generic_to_shared(smem);
    const int tid = threadIdx.x;
    const int w = tid >> 5, lane = tid & 31;
    const int g = lane >> 2, tig = lane & 3;
    const int r0 = blockIdx.x * 16;
    const int b = r0 / NN, i0 = r0 % NN;

    if (tid < 16) { smem[N1_SUM + tid] = 0.f; smem[N1_SQ + tid] = 0.f; }

    {
        int r = tid >> 4, e4 = (tid & 15) * 4;
        const float* er = edges + (size_t)((size_t)(b * NN + i0 + r) * NN) * EE;
        const float* ar = adj + (size_t)(b * NN + i0 + r) * NN;
        float4 acc = make_float4(0.f, 0.f, 0.f, 0.f);
        for (int j = 0; j < NN; j += 4) {
            float a0 = ar[j], a1 = ar[j + 1], a2 = ar[j + 2], a3 = ar[j + 3];
            if (a0 != 0.f) { float4 v = __ldg((const float4*)&er[(size_t)j * EE + e4]);
                acc.x += v.x * a0; acc.y += v.y * a0; acc.z += v.z * a0; acc.w += v.w * a0; }
            if (a1 != 0.f) { float4 v = __ldg((const float4*)&er[(size_t)(j + 1) * EE + e4]);
                acc.x += v.x * a1; acc.y += v.y * a1; acc.z += v.z * a1; acc.w += v.w * a1; }
            if (a2 != 0.f) { float4 v = __ldg((const float4*)&er[(size_t)(j + 2) * EE + e4]);
                acc.x += v.x * a2; acc.y += v.y * a2; acc.z += v.z * a2; acc.w += v.w * a2; }
            if (a3 != 0.f) { float4 v = __ldg((const float4*)&er[(size_t)(j + 3) * EE + e4]);
                acc.x += v.x * a3; acc.y += v.y * a3; acc.z += v.z * a3; acc.w += v.w * a3; }
        }
        *(float4*)&smem[N1_AGG + r * 64 + e4] = acc;
    }
    __syncthreads();

    float cacc[2][4][4];
    #pragma unroll
    for (int s = 0; s < 2; s++)
        #pragma unroll
        for (int nj = 0; nj < 4; nj++)
            #pragma unroll
            for (int x = 0; x < 4; x++) cacc[s][nj][x] = 0.f;

    for (int kc = 0; kc < 13; kc++) {
        __syncthreads();
        {
            int r = tid >> 4, k0 = (tid & 15) * 4;
            float4 v;
            if (kc == 0) v = *(float4*)&smem[N1_AGG + r * 64 + k0];
            else {
                v = __ldg((const float4*)&nodes[(size_t)(r0 + r) * DD + (kc - 1) * 64 + k0]);
                v.x *= (float)NN; v.y *= (float)NN; v.z *= (float)NN; v.w *= (float)NN;
            }
            *(uint2*)&sh[N1H_A + r * 72 + k0] = make_uint2(pack2(v.x, v.y), pack2(v.z, v.w));
        }
        {
            int q = tid;
            for (int t = 0; t < 32; t++, q += 256) {
                int n = q & 511, k0 = (q >> 9) * 4;
                const float* p = nw1 + (size_t)(kc * 64 + k0) * HH + n;
                *(uint2*)&sh[N1H_B + n * 72 + k0] =
                    make_uint2(pack2(__ldg(p), __ldg(p + HH)),
                               pack2(__ldg(p + 2 * HH), __ldg(p + 3 * HH)));
            }
        }
        __syncthreads();
        gemm_16x32(sb, N1H_A, 72, 0, N1H_B, 0, w * 64, lane, cacc[0]);
        gemm_16x32(sb, N1H_A, 72, 0, N1H_B, 0, w * 64 + 32, lane, cacc[1]);
    }

    float rsum[2] = {0.f, 0.f}, rsq[2] = {0.f, 0.f};
    #pragma unroll
    for (int s = 0; s < 2; s++)
        #pragma unroll
        for (int nj = 0; nj < 4; nj++) {
            int coll = w * 64 + s * 32 + nj * 8 + 2 * tig;
            float2 b1 = __ldg((const float2*)&nb1[coll]);
            #pragma unroll
            for (int rr = 0; rr < 2; rr++) {
                float v0 = cacc[s][nj][rr * 2 + 0] + b1.x;
                float v1 = cacc[s][nj][rr * 2 + 1] + b1.y;
                cacc[s][nj][rr * 2 + 0] = v0;
                cacc[s][nj][rr * 2 + 1] = v1;
                rsum[rr] += v0 + v1;
                rsq[rr]  += v0 * v0 + v1 * v1;
            }
        }
    #pragma unroll
    for (int rr = 0; rr < 2; rr++) {
        float s = rsum[rr], q2 = rsq[rr];
        s  += __shfl_xor_sync(0xffffffffu, s, 1);
        s  += __shfl_xor_sync(0xffffffffu, s, 2);
        q2 += __shfl_xor_sync(0xffffffffu, q2, 1);
        q2 += __shfl_xor_sync(0xffffffffu, q2, 2);
        if (tig == 0) {
            atomicAdd(&smem[N1_SUM + g + rr * 8], s);
            atomicAdd(&smem[N1_SQ + g + rr * 8], q2);
        }
    }
    __syncthreads();
    if (tid < 16) {
        float mu = smem[N1_SUM + tid] * (1.f / HH);
        float var = smem[N1_SQ + tid] * (1.f / HH) - mu * mu;
        smem[N1_MU + tid] = mu;
        smem[N1_RS + tid] = rsqrtf(var + 1e-5f);
    }
    __syncthreads();
    const float mu0 = smem[N1_MU + g],     rs0 = smem[N1_RS + g];
    const float mu1 = smem[N1_MU + g + 8], rs1 = smem[N1_RS + g + 8];

    #pragma unroll
    for (int s = 0; s < 2; s++)
        #pragma unroll
        for (int nj = 0; nj < 4; nj++) {
            int coll = w * 64 + s * 32 + nj * 8 + 2 * tig;
            float2 gg = __ldg((const float2*)&ng[coll]);
            float2 bb = __ldg((const float2*)&nbt[coll]);
            float v0 = fmaxf((cacc[s][nj][0] - mu0) * rs0 * gg.x + bb.x, 0.f);
            float v1 = fmaxf((cacc[s][nj][1] - mu0) * rs0 * gg.y + bb.y, 0.f);
            float v2 = fmaxf((cacc[s][nj][2] - mu1) * rs1 * gg.x + bb.x, 0.f);
            float v3 = fmaxf((cacc[s][nj][3] - mu1) * rs1 * gg.y + bb.y, 0.f);
            *(uint32_t*)&sh[N1H_B + g * 520 + coll]       = pack2(v0, v1);
            *(uint32_t*)&sh[N1H_B + (g + 8) * 520 + coll] = pack2(v2, v3);
        }
    __syncthreads();
    {
        int q = tid;
        #pragma unroll
        for (int t = 0; t < 4; t++, q += 256) {
            int r = q >> 6, c0 = (q & 63) * 8;
            *(uint4*)&g_heh[(size_t)(r0 + r) * HH + c0] = *(uint4*)&sh[N1H_B + r * 520 + c0];
        }
    }
}

// ============================================================
// Kernel 3: node path part 2 (unchanged)
// ============================================================
#define N2H_HE 0
#define N2H_B  (32 * 520)
#define N2F_OUT 12928
#define N2_SMEM_BYTES ((N2F_OUT + 32 * 132) * 4)

__global__ __launch_bounds__(256) void k_node2(
    const float* __restrict__ nodes, const float* __restrict__ nw2,
    const float* __restrict__ nb2, float* __restrict__ out_nodes)
{
    extern __shared__ float smem[];
    __half* sh = (__half*)smem;
    const uint32_t sb = (uint32_t)__cvta_generic_to_shared(smem);
    const int tid = threadIdx.x;
    const int w = tid >> 5, lane = tid & 31;
    const int g = lane >> 2, tig = lane & 3;
    const int mt = (w & 1) * 16, nt = (w >> 1) * 32;
    const int nc = blockIdx.x * 128;
    const int r0 = blockIdx.y * 32;

    {
        int q = tid;
        #pragma unroll
        for (int t = 0; t < 8; t++, q += 256) {
            int r = q >> 6, c0 = (q & 63) * 8;
            *(uint4*)&sh[N2H_HE + r * 520 + c0] = *(const uint4*)&g_heh[(size_t)(r0 + r) * HH + c0];
        }
    }

    float c2[4][4];
    #pragma unroll
    for (int nj = 0; nj < 4; nj++)
        #pragma unroll
        for (int x = 0; x < 4; x++) c2[nj][x] = 0.f;

    for (int kc = 0; kc < 8; kc++) {
        __syncthreads();
        {
            int q = tid;
            #pragma unroll
            for (int t = 0; t < 8; t++, q += 256) {
                int n = q & 127, k0 = (q >> 7) * 4;
                const float* p = nw2 + (size_t)(kc * 64 + k0) * DD + nc + n;
                *(uint2*)&sh[N2H_B + n * 72 + k0] =
                    make_uint2(pack2(__ldg(p), __ldg(p + DD)),
                               pack2(__ldg(p + 2 * DD), __ldg(p + 3 * DD)));
            }
        }
        __syncthreads();
        gemm_16x32(sb, N2H_HE, 520, kc * 64, N2H_B, mt, nt, lane, c2);
    }

    __syncthreads();
    #pragma unroll
    for (int nj = 0; nj < 4; nj++) {
        int coll = nt + nj * 8 + 2 * tig;
        #pragma unroll
        for (int rr = 0; rr < 2; rr++) {
            int row = mt + g + rr * 8;
            *(float2*)&smem[N2F_OUT + row * 132 + coll] =
                make_float2(c2[nj][rr * 2 + 0], c2[nj][rr * 2 + 1]);
        }
    }
    __syncthreads();
    {
        int q = tid;
        #pragma unroll
        for (int t = 0; t < 4; t++, q += 256) {
            int r = q >> 5, c4 = (q & 31) * 4;
            float4 m = *(float4*)&smem[N2F_OUT + r * 132 + c4];
            size_t gi = (size_t)(r0 + r) * DD + nc + c4;
            float4 n4 = __ldg((const float4*)&nodes[gi]);
            float4 b4 = __ldg((const float4*)&nb2[nc + c4]);
            *(float4*)&out_nodes[gi] = make_float4(n4.x + m.x + b4.x, n4.y + m.y + b4.y,
                                                   n4.z + m.z + b4.z, n4.w + m.w + b4.w);
        }
    }
}

// ============================================================
// Kernel 4: fp16 fused edge path with cp.async staging.  2 CTAs/SM.
// ============================================================
#define F_NI   0
#define F_SUM  512
#define F_SQ   576
#define F_MU   640
#define F_RS   704
#define F_OUT  768                   // aliases H_E + H_NJ0 (dead at epilogue)
#define H_E    1536                  // half idx: [64][72]; doubles as NJ buf1
#define H_NJ0  (H_E + 64 * 72)       // [64][72]
#define H_W0   (H_NJ0 + 64 * 72)     // [64][72]
#define H_W1   (H_W0 + 64 * 72)      // [64][72]
#define H_HE   (H_W1 + 64 * 72)      // [64][520]
#define EDGE_SMEM_BYTES ((H_HE + 64 * 520) * 2)

__global__ __launch_bounds__(256, 2) void k_edge_mma(
    const float* __restrict__ edges,
    const float* __restrict__ eg,
    const float* __restrict__ ebt,
    const float* __restrict__ eb2,
    float* __restrict__ out_edges)
{
    extern __shared__ float smem[];
    __half* sh = (__half*)smem;
    const uint32_t sb = (uint32_t)__cvta_generic_to_shared(smem);
    const int tid = threadIdx.x;
    const int w = tid >> 5, lane = tid & 31;
    const int g = lane >> 2, tig = lane & 3;
    const int mt = (w & 3) * 16, ntw = (w >> 2) * 32;
    const int b = blockIdx.z, i = blockIdx.y;
    const int j0 = blockIdx.x * JT;

    const int arow = lane & 15, ak8 = (lane >> 4) << 3;
    const int bn = (lane & 7) + ((lane >> 4) << 3);
    const int bk8 = ((lane >> 3) & 1) << 3;

    const __half* njb = g_NJh + (size_t)((size_t)b * NN + j0) * HH;

    // ---- stage E [64][72] fp16 (fp32 src needs cvt) ----
    const float* etile = edges + ((size_t)((size_t)b * NN + i) * NN + j0) * EE;
    #pragma unroll
    for (int t = 0; t < 4; t++) {
        int q = t * 256 + tid;
        int j = q >> 4, k0 = (q & 15) * 4;
        float4 v = __ldg((const float4*)&etile[j * EE + k0]);
        *(uint2*)&sh[H_E + j * 72 + k0] = make_uint2(pack2(v.x, v.y), pack2(v.z, v.w));
    }
    // ---- NI cache + zero stats ----
    const float* nip = g_NI + (size_t)((size_t)b * NN + i) * HH;
    smem[F_NI + tid] = __ldg(&nip[tid]);
    smem[F_NI + 256 + tid] = __ldg(&nip[256 + tid]);
    if (tid < 64) { smem[F_SUM + tid] = 0.f; smem[F_SQ + tid] = 0.f; }

    // issue group 0: W1 ch0 -> H_W0, NJ ch0 -> H_NJ0
    {
        #pragma unroll
        for (int t = 0; t < 2; t++) {
            int q = t * 256 + tid;             // 512 segs each
            int n = q >> 3, k8 = (q & 7) * 8;
            cp16(sb + 2 * (H_W0 + n * 72 + k8), g_w1h + n * 64 + k8);
            cp16(sb + 2 * (H_NJ0 + n * 72 + k8), njb + (size_t)n * HH + k8);
        }
        CP_COMMIT();
    }
    __syncthreads();                           // E + NI visible

    // ---- hoist E fragments ----
    uint32_t ef[4][4];
    #pragma unroll
    for (int ks = 0; ks < 4; ks++)
        ldm_x4(ef[ks][0], ef[ks][1], ef[ks][2], ef[ks][3],
               sb + 2 * (H_E + (mt + arow) * 72 + ks * 16 + ak8));

    // ================= GEMM1: he = E@We + NI + NJ ==========================
    float rsum[2] = {0.f, 0.f}, rsq[2] = {0.f, 0.f};
    for (int ch = 0; ch < 8; ch++) {
        CP_WAIT0();
        __syncthreads();                       // group ch visible; prev consume done
        if (ch < 7) {
            const int wb = ((ch + 1) & 1) ? H_W1 : H_W0;
            const int nb = ((ch + 1) & 1) ? H_E : H_NJ0;   // buf1 = dead E tile
            #pragma unroll
            for (int t = 0; t < 2; t++) {
                int q = t * 256 + tid;
                int n = q >> 3, k8 = (q & 7) * 8;
                cp16(sb + 2 * (wb + n * 72 + k8), g_w1h + (ch + 1) * 4096 + n * 64 + k8);
                cp16(sb + 2 * (nb + n * 72 + k8), njb + (size_t)n * HH + (ch + 1) * 64 + k8);
            }
            CP_COMMIT();
        }
        const int bufo = (ch & 1) ? H_W1 : H_W0;
        const int njbf = (ch & 1) ? H_E : H_NJ0;
        float c[4][4];
        #pragma unroll
        for (int nj = 0; nj < 4; nj++)
            #pragma unroll
            for (int x = 0; x < 4; x++) c[nj][x] = 0.f;
        #pragma unroll
        for (int ks = 0; ks < 4; ks++) {
            int k0 = ks * 16;
            uint32_t p0, p1, p2, p3, q0, q1, q2, q3;
            ldm_x4(p0, p1, p2, p3, sb + 2 * (bufo + (ntw + bn) * 72 + k0 + bk8));
            ldm_x4(q0, q1, q2, q3, sb + 2 * (bufo + (ntw + 16 + bn) * 72 + k0 + bk8));
            mma_f16(c[0], ef[ks][0], ef[ks][1], ef[ks][2], ef[ks][3], p0, p1);
            mma_f16(c[1], ef[ks][0], ef[ks][1], ef[ks][2], ef[ks][3], p2, p3);
            mma_f16(c[2], ef[ks][0], ef[ks][1], ef[ks][2], ef[ks][3], q0, q1);
            mma_f16(c[3], ef[ks][0], ef[ks][1], ef[ks][2], ef[ks][3], q2, q3);
        }
        #pragma unroll
        for (int nj = 0; nj < 4; nj++) {
            int cl = ntw + nj * 8 + 2 * tig;
            float2 ni = *(float2*)&smem[F_NI + ch * 64 + cl];
            #pragma unroll
            for (int rr = 0; rr < 2; rr++) {
                int row = mt + g + rr * 8;
                float2 njv = h2f(*(uint32_t*)&sh[njbf + row * 72 + cl]);
                float v0 = c[nj][rr * 2 + 0] + ni.x + njv.x;
                float v1 = c[nj][rr * 2 + 1] + ni.y + njv.y;
                rsum[rr] += v0 + v1;
                rsq[rr]  += v0 * v0 + v1 * v1;
                *(uint32_t*)&sh[H_HE + row * 520 + ch * 64 + cl] = pack2(v0, v1);
            }
        }
    }
    __syncthreads();                           // last consume done

    // issue W2 chunk0 early (overlaps stats + LN pass)
    #pragma unroll
    for (int t = 0; t < 2; t++) {
        int q = t * 256 + tid;
        int n = q >> 3, k8 = (q & 7) * 8;
        cp16(sb + 2 * (H_W0 + n * 72 + k8), g_w2h + n * 64 + k8);
    }
    CP_COMMIT();

    // ---- LN stats reduction ----
    #pragma unroll
    for (int rr = 0; rr < 2; rr++) {
        float s = rsum[rr], q2 = rsq[rr];
        s  += __shfl_xor_sync(0xffffffffu, s, 1);
        s  += __shfl_xor_sync(0xffffffffu, s, 2);
        q2 += __shfl_xor_sync(0xffffffffu, q2, 1);
        q2 += __shfl_xor_sync(0xffffffffu, q2, 2);
        if (tig == 0) {
            atomicAdd(&smem[F_SUM + mt + g + rr * 8], s);
            atomicAdd(&smem[F_SQ  + mt + g + rr * 8], q2);
        }
    }
    __syncthreads();
    if (tid < 64) {
        float mu = smem[F_SUM + tid] * (1.f / HH);
        float var = smem[F_SQ + tid] * (1.f / HH) - mu * mu;
        smem[F_MU + tid] = mu;
        smem[F_RS + tid] = rsqrtf(var + 1e-5f);
    }
    __syncthreads();

    // ---- coalesced in-place LN + relu pass over he ----
    {
        int wr = w * 8;
        #pragma unroll
        for (int pass = 0; pass < 2; pass++) {
            int cb = pass * 256 + lane * 8;
            float4 g0 = __ldg((const float4*)&eg[cb]);
            float4 g1 = __ldg((const float4*)&eg[cb + 4]);
            float4 t0 = __ldg((const float4*)&ebt[cb]);
            float4 t1 = __ldg((const float4*)&ebt[cb + 4]);
            #pragma unroll
            for (int r = 0; r < 8; r++) {
                int row = wr + r;
                float mu = smem[F_MU + row], rs = smem[F_RS + row];
                uint4 u = *(uint4*)&sh[H_HE + row * 520 + cb];
                float2 v;
                v = h2f(u.x);
                u.x = pack2(fmaxf((v.x - mu) * rs * g0.x + t0.x, 0.f),
                            fmaxf((v.y - mu) * rs * g0.y + t0.y, 0.f));
                v = h2f(u.y);
                u.y = pack2(fmaxf((v.x - mu) * rs * g0.z + t0.z, 0.f),
                            fmaxf((v.y - mu) * rs * g0.w + t0.w, 0.f));
                v = h2f(u.z);
                u.z = pack2(fmaxf((v.x - mu) * rs * g1.x + t1.x, 0.f),
                            fmaxf((v.y - mu) * rs * g1.y + t1.y, 0.f));
                v = h2f(u.w);
                u.w = pack2(fmaxf((v.x - mu) * rs * g1.z + t1.z, 0.f),
                            fmaxf((v.y - mu) * rs * g1.w + t1.w, 0.f));
                *(uint4*)&sh[H_HE + row * 520 + cb] = u;
            }
        }
    }

    // ================= GEMM2: out = ln_relu_he @ ew2 =======================
    float c2[4][4];
    #pragma unroll
    for (int nj = 0; nj < 4; nj++)
        #pragma unroll
        for (int x = 0; x < 4; x++) c2[nj][x] = 0.f;

    for (int kc = 0; kc < 8; kc++) {
        CP_WAIT0();
        __syncthreads();
        if (kc < 7) {
            const int wb = ((kc + 1) & 1) ? H_W1 : H_W0;
            #pragma unroll
            for (int t = 0; t < 2; t++) {
                int q = t * 256 + tid;
                int n = q >> 3, k8 = (q & 7) * 8;
                cp16(sb + 2 * (wb + n * 72 + k8), g_w2h + (kc + 1) * 4096 + n * 64 + k8);
            }
            CP_COMMIT();
        }
        const int bufo = (kc & 1) ? H_W1 : H_W0;
        #pragma unroll
        for (int ks = 0; ks < 4; ks++) {
            int k0 = ks * 16;
            uint32_t a0, a1, a2, a3, p0, p1, p2, p3, q0, q1, q2, q3;
            ldm_x4(a0, a1, a2, a3,
                   sb + 2 * (H_HE + (mt + arow) * 520 + kc * 64 + k0 + ak8));
            ldm_x4(p0, p1, p2, p3, sb + 2 * (bufo + (ntw + bn) * 72 + k0 + bk8));
            ldm_x4(q0, q1, q2, q3, sb + 2 * (bufo + (ntw + 16 + bn) * 72 + k0 + bk8));
            mma_f16(c2[0], a0, a1, a2, a3, p0, p1);
            mma_f16(c2[1], a0, a1, a2, a3, p2, p3);
            mma_f16(c2[2], a0, a1, a2, a3, q0, q1);
            mma_f16(c2[3], a0, a1, a2, a3, q2, q3);
        }
    }
    __syncthreads();

    // ---- epilogue: bounce via smem (aliases E/NJ0), coalesced store ----
    #pragma unroll
    for (int nj = 0; nj < 4; nj++) {
        int cl = ntw + nj * 8 + 2 * tig;
        #pragma unroll
        for (int rr = 0; rr < 2; rr++) {
            int row = mt + g + rr * 8;
            *(float2*)&smem[F_OUT + row * 68 + cl] =
                make_float2(c2[nj][rr * 2 + 0], c2[nj][rr * 2 + 1]);
        }
    }
    __syncthreads();
    #pragma unroll
    for (int t = 0; t < 4; t++) {
        int q = t * 256 + tid;
        int r = q >> 4, c4 = (q & 15) * 4;
        float4 m = *(float4*)&smem[F_OUT + r * 68 + c4];
        size_t gbase = ((size_t)((size_t)b * NN + i) * NN + j0 + r) * EE + c4;
        float4 e4 = __ldg((const float4*)&edges[gbase]);
        float4 b4 = __ldg((const float4*)&eb2[c4]);
        float4 o = make_float4(e4.x + m.x + b4.x, e4.y + m.y + b4.y,
                               e4.z + m.z + b4.z, e4.w + m.w + b4.w);
        *(float4*)&out_edges[gbase] = o;
    }
}

// ============================================================
extern "C" void kernel_launch(void* const* d_in, const int* in_sizes, int n_in,
                              void* d_out, int out_size)
{
    const float* nodes = (const float*)d_in[0];
    const float* edges = (const float*)d_in[1];
    const float* adj   = (const float*)d_in[2];
    const float* nw1   = (const float*)d_in[3];
    const float* nb1   = (const float*)d_in[4];
    const float* ng    = (const float*)d_in[5];
    const float* nbt   = (const float*)d_in[6];
    const float* nw2   = (const float*)d_in[7];
    const float* nb2   = (const float*)d_in[8];
    const float* ew1   = (const float*)d_in[9];
    const float* eb1   = (const float*)d_in[10];
    const float* eg    = (const float*)d_in[11];
    const float* ebt   = (const float*)d_in[12];
    const float* ew2   = (const float*)d_in[13];
    const float* eb2   = (const float*)d_in[14];

    float* out_nodes = (float*)d_out;
    float* out_edges = out_nodes + (size_t)BB * NN * DD;

    cudaFuncSetAttribute(k_edge_mma, cudaFuncAttributeMaxDynamicSharedMemorySize,
                         EDGE_SMEM_BYTES);
    cudaFuncSetAttribute(k_ninj_mma, cudaFuncAttributeMaxDynamicSharedMemorySize,
                         NINJ_SMEM_BYTES);
    cudaFuncSetAttribute(k_node1, cudaFuncAttributeMaxDynamicSharedMemorySize,
                         N1_SMEM_BYTES);
    cudaFuncSetAttribute(k_node2, cudaFuncAttributeMaxDynamicSharedMemorySize,
                         N2_SMEM_BYTES);

    static cudaStream_t s2 = nullptr;
    static cudaEvent_t evFork = nullptr, evJoin = nullptr;
    if (s2 == nullptr) {
        if (cudaStreamCreateWithFlags(&s2, cudaStreamNonBlocking) != cudaSuccess)
            s2 = nullptr;
        if (s2) {
            cudaEventCreateWithFlags(&evFork, cudaEventDisableTiming);
            cudaEventCreateWithFlags(&evJoin, cudaEventDisableTiming);
        }
    }

    if (s2) {
        cudaEventRecord(evFork, 0);
        cudaStreamWaitEvent(s2, evFork, 0);
        k_node1<<<48, 256, N1_SMEM_BYTES, s2>>>(nodes, edges, adj, nw1, nb1, ng, nbt);
        k_node2<<<dim3(6, 24), 256, N2_SMEM_BYTES, s2>>>(nodes, nw2, nb2, out_nodes);
        cudaEventRecord(evJoin, s2);
        k_prep<<<296, 256>>>(ew1, ew2);
        k_ninj_mma<<<dim3(8, 12), 256, NINJ_SMEM_BYTES>>>(nodes, eb1);
        k_edge_mma<<<dim3(NN / JT, NN, BB), 256, EDGE_SMEM_BYTES>>>(edges, eg, ebt, eb2, out_edges);
        cudaStreamWaitEvent(0, evJoin, 0);
    } else {
        k_prep<<<296, 256>>>(ew1, ew2);
        k_ninj_mma<<<dim3(8, 12), 256, NINJ_SMEM_BYTES>>>(nodes, eb1);
        k_node1<<<48, 256, N1_SMEM_BYTES>>>(nodes, edges, adj, nw1, nb1, ng, nbt);
        k_node2<<<dim3(6, 24), 256, N2_SMEM_BYTES>>>(nodes, nw2, nb2, out_nodes);
        k_edge_mma<<<dim3(NN / JT, NN, BB), 256, EDGE_SMEM_BYTES>>>(edges, eg, ebt, eb2, out_edges);
    }
}